// round 7
// baseline (speedup 1.0000x reference)
#include <cuda_runtime.h>
#include <cstdint>

// Problem constants (fixed by the reference)
#define BB    2
#define SEQ   2048
#define HID   2048
#define NHEAD 16
#define DHEAD 128
#define MTOT  (BB * SEQ)      // 4096
#define NQKV  (3 * HID)       // 6144
#define QSCALE 0.088388347648318447f

// ---------------------------------------------------------------------------
// Device scratch (all 16B-aligned for cp.async / vector access)
// ---------------------------------------------------------------------------
__device__ __align__(128) uint16_t g_qh[(size_t)BB * NHEAD * SEQ * DHEAD];
__device__ __align__(128) uint16_t g_ql[(size_t)BB * NHEAD * SEQ * DHEAD];
__device__ __align__(128) uint16_t g_kh[(size_t)BB * NHEAD * SEQ * DHEAD];
__device__ __align__(128) uint16_t g_kl[(size_t)BB * NHEAD * SEQ * DHEAD];
__device__ __align__(128) uint16_t g_vh[(size_t)BB * NHEAD * SEQ * DHEAD];
__device__ __align__(128) uint16_t g_vl[(size_t)BB * NHEAD * SEQ * DHEAD];

__device__ __align__(128) uint16_t g_hidh[(size_t)MTOT * HID];
__device__ __align__(128) uint16_t g_hidl[(size_t)MTOT * HID];
__device__ __align__(128) uint16_t g_wah[(size_t)HID * NQKV];
__device__ __align__(128) uint16_t g_wal[(size_t)HID * NQKV];
__device__ __align__(128) uint16_t g_wph[(size_t)HID * HID];
__device__ __align__(128) uint16_t g_wpl[(size_t)HID * HID];
__device__ __align__(128) uint16_t g_ath[(size_t)MTOT * HID];
__device__ __align__(128) uint16_t g_atl[(size_t)MTOT * HID];

// ---------------------------------------------------------------------------
// Helpers
// ---------------------------------------------------------------------------
__device__ __forceinline__ void split_pack(float x0, float x1,
                                           uint32_t &h, uint32_t &l) {
    asm("cvt.rn.bf16x2.f32 %0, %1, %2;" : "=r"(h) : "f"(x1), "f"(x0));
    float h0 = __uint_as_float(h << 16);
    float h1 = __uint_as_float(h & 0xffff0000u);
    asm("cvt.rn.bf16x2.f32 %0, %1, %2;" : "=r"(l) : "f"(x1 - h1), "f"(x0 - h0));
}

__device__ __forceinline__ uint32_t smem_u32(const void *p) {
    uint32_t a;
    asm("{ .reg .u64 t; cvta.to.shared.u64 t, %1; cvt.u32.u64 %0, t; }"
        : "=r"(a) : "l"(p));
    return a;
}

__device__ __forceinline__ void mma16(float *d,
                                      uint32_t a0, uint32_t a1, uint32_t a2, uint32_t a3,
                                      uint32_t b0, uint32_t b1) {
    asm volatile(
        "mma.sync.aligned.m16n8k16.row.col.f32.bf16.bf16.f32 "
        "{%0,%1,%2,%3}, {%4,%5,%6,%7}, {%8,%9}, {%0,%1,%2,%3};\n"
        : "+f"(d[0]), "+f"(d[1]), "+f"(d[2]), "+f"(d[3])
        : "r"(a0), "r"(a1), "r"(a2), "r"(a3), "r"(b0), "r"(b1));
}

#define LDSM4(r, addr)                                                       \
    asm volatile("ldmatrix.sync.aligned.m8n8.x4.shared.b16 {%0,%1,%2,%3}, [%4];" \
        : "=r"((r)[0]), "=r"((r)[1]), "=r"((r)[2]), "=r"((r)[3]) : "r"(addr))
#define LDSM4T(r, addr)                                                      \
    asm volatile("ldmatrix.sync.aligned.m8n8.x4.trans.shared.b16 {%0,%1,%2,%3}, [%4];" \
        : "=r"((r)[0]), "=r"((r)[1]), "=r"((r)[2]), "=r"((r)[3]) : "r"(addr))

__device__ __forceinline__ void cpa16(uint32_t dst, const void *src) {
    asm volatile("cp.async.cg.shared.global [%0], [%1], 16;"
                 :: "r"(dst), "l"(src) : "memory");
}
#define CP_COMMIT() asm volatile("cp.async.commit_group;" ::: "memory")
#define CP_WAIT2()  asm volatile("cp.async.wait_group 2;" ::: "memory")
#define CP_WAIT0()  asm volatile("cp.async.wait_group 0;" ::: "memory")

// ---------------------------------------------------------------------------
// Split kernel: fp32 -> bf16 hi + bf16 lo (row-major preserved)
// ---------------------------------------------------------------------------
__global__ void __launch_bounds__(256)
split4(const float4 *__restrict__ x, uint2 *__restrict__ hi, uint2 *__restrict__ lo) {
    int i = blockIdx.x * 256 + threadIdx.x;
    float4 v = x[i];
    uint32_t h0, l0, h1, l1;
    split_pack(v.x, v.y, h0, l0);
    split_pack(v.z, v.w, h1, l1);
    hi[i] = make_uint2(h0, h1);
    lo[i] = make_uint2(l0, l1);
}

// ---------------------------------------------------------------------------
// GEMM: C = A @ B + bias, bf16x3, pre-split inputs, 4-stage cp.async,
// CTA 128m x 256n, warp tile 64x64, ldmatrix fragments.
// MMA terms grouped in passes (hh | hl | lh) to break accumulator RAW chains.
// MODE 1: QKV epilogue -> split bf16 q/k/v (Q pre-scaled) | MODE 0: fp32 out.
// ---------------------------------------------------------------------------
#define STG_BYTES 53248
#define OFF_AH 0
#define OFF_AL 10240
#define OFF_BH 20480
#define OFF_BL 36864
#define GEMM_SMEM (4 * STG_BYTES)

template <int MODE>
__global__ void __launch_bounds__(256)
gemm_ldsm(const uint16_t *__restrict__ Ah, const uint16_t *__restrict__ Al,
          const uint16_t *__restrict__ Bh, const uint16_t *__restrict__ Bl,
          const float *__restrict__ bias, float *__restrict__ Cout,
          int M, int N, int K) {
    extern __shared__ char smc[];
    const uint32_t sbase = smem_u32(smc);

    const int tid  = threadIdx.x;
    const int lane = tid & 31;
    const int warp = tid >> 5;
    const int wm   = warp >> 2;
    const int wn   = warp & 3;
    const int m0   = blockIdx.y * 128;
    const int n0   = blockIdx.x * 256;
    const int g    = lane >> 2;
    const int q4   = lane & 3;

    float acc[4][8][4];
#pragma unroll
    for (int i = 0; i < 4; i++)
#pragma unroll
        for (int j = 0; j < 8; j++)
#pragma unroll
            for (int e = 0; e < 4; e++) acc[i][j][e] = 0.f;

    auto issue = [&](int s) {
        const uint32_t sb = sbase + (s & 3) * STG_BYTES;
        const int kb = s << 5;
#pragma unroll
        for (int i = 0; i < 2; i++) {
            int id  = tid + i * 256;
            int row = id >> 2;
            int c   = id & 3;
            size_t gidx = (size_t)(m0 + row) * K + kb + c * 8;
            uint32_t d = (row * 5 + c) << 4;
            cpa16(sb + OFF_AH + d, Ah + gidx);
            cpa16(sb + OFF_AL + d, Al + gidx);
        }
#pragma unroll
        for (int i = 0; i < 4; i++) {
            int id = tid + i * 256;
            int k  = id >> 5;
            int c  = id & 31;
            size_t gidx = (size_t)(kb + k) * N + n0 + c * 8;
            uint32_t d = ((k << 5) + (c ^ (k & 7))) << 4;
            cpa16(sb + OFF_BH + d, Bh + gidx);
            cpa16(sb + OFF_BL + d, Bl + gidx);
        }
    };

    auto compute = [&](int s) {
        const uint32_t sb = sbase + (s & 3) * STG_BYTES;
        const int arow = wm * 64 + (lane & 15);
        const int lt16 = lane >> 4;
        const int cbas = wn * 8 + ((lane >> 3) & 1);
#pragma unroll
        for (int kk = 0; kk < 2; kk++) {
            const int ac   = kk * 2 + lt16;
            const int kloc = kk * 16 + (lt16 << 3) + (lane & 7);
            uint32_t ad[4], bd[4];
#pragma unroll
            for (int mt = 0; mt < 4; mt++)
                ad[mt] = sb + OFF_AH + (((arow + mt * 16) * 5 + ac) << 4);
#pragma unroll
            for (int bt = 0; bt < 4; bt++) {
                int c = cbas + bt * 2;
                bd[bt] = sb + OFF_BH + (((kloc << 5) + (c ^ (kloc & 7))) << 4);
            }

            uint32_t ah[4][4], al[4][4], bh[4][4], bl[4][4];
#pragma unroll
            for (int mt = 0; mt < 4; mt++) LDSM4(ah[mt], ad[mt]);
#pragma unroll
            for (int bt = 0; bt < 4; bt++) LDSM4T(bh[bt], bd[bt]);

            // ---- pass 1: A_hi x B_hi (32 independent MMAs) ----
#pragma unroll
            for (int bt = 0; bt < 4; bt++)
#pragma unroll
                for (int mt = 0; mt < 4; mt++) {
                    mma16(acc[mt][2 * bt],     ah[mt][0], ah[mt][1], ah[mt][2], ah[mt][3],
                          bh[bt][0], bh[bt][2]);
                    mma16(acc[mt][2 * bt + 1], ah[mt][0], ah[mt][1], ah[mt][2], ah[mt][3],
                          bh[bt][1], bh[bt][3]);
                }

#pragma unroll
            for (int bt = 0; bt < 4; bt++)
                LDSM4T(bl[bt], bd[bt] + (OFF_BL - OFF_BH));

            // ---- pass 2: A_hi x B_lo ----
#pragma unroll
            for (int bt = 0; bt < 4; bt++)
#pragma unroll
                for (int mt = 0; mt < 4; mt++) {
                    mma16(acc[mt][2 * bt],     ah[mt][0], ah[mt][1], ah[mt][2], ah[mt][3],
                          bl[bt][0], bl[bt][2]);
                    mma16(acc[mt][2 * bt + 1], ah[mt][0], ah[mt][1], ah[mt][2], ah[mt][3],
                          bl[bt][1], bl[bt][3]);
                }

#pragma unroll
            for (int mt = 0; mt < 4; mt++)
                LDSM4(al[mt], ad[mt] + (OFF_AL - OFF_AH));

            // ---- pass 3: A_lo x B_hi ----
#pragma unroll
            for (int bt = 0; bt < 4; bt++)
#pragma unroll
                for (int mt = 0; mt < 4; mt++) {
                    mma16(acc[mt][2 * bt],     al[mt][0], al[mt][1], al[mt][2], al[mt][3],
                          bh[bt][0], bh[bt][2]);
                    mma16(acc[mt][2 * bt + 1], al[mt][0], al[mt][1], al[mt][2], al[mt][3],
                          bh[bt][1], bh[bt][3]);
                }
        }
    };

    const int S = K >> 5;
    issue(0); CP_COMMIT();
    issue(1); CP_COMMIT();
    issue(2); CP_COMMIT();

    for (int s = 0; s < S; s++) {
        CP_WAIT2();
        __syncthreads();
        compute(s);
        if (s + 3 < S) issue(s + 3);
        CP_COMMIT();
    }

    // ---- epilogue ----
#pragma unroll
    for (int mt = 0; mt < 4; mt++) {
#pragma unroll
        for (int nt = 0; nt < 8; nt++) {
            int row = m0 + wm * 64 + mt * 16 + g;
            int col = n0 + wn * 64 + nt * 8 + (q4 << 1);
            float b0 = bias[col];
            float b1 = bias[col + 1];
            if (MODE == 1) {
                int which = col >> 11;
                int head  = (col >> 7) & 15;
                int dc    = col & 127;
                uint16_t *dh = (which == 0) ? g_qh : ((which == 1) ? g_kh : g_vh);
                uint16_t *dl = (which == 0) ? g_ql : ((which == 1) ? g_kl : g_vl);
                float sc = (which == 0) ? QSCALE : 1.f;
                float v00 = (acc[mt][nt][0] + b0) * sc;
                float v01 = (acc[mt][nt][1] + b1) * sc;
                float v10 = (acc[mt][nt][2] + b0) * sc;
                float v11 = (acc[mt][nt][3] + b1) * sc;
                uint32_t h0, l0, h1, l1;
                split_pack(v00, v01, h0, l0);
                split_pack(v10, v11, h1, l1);
                int bi = row >> 11;
                int si = row & 2047;
                size_t u32i = (((size_t)(bi * NHEAD + head) * SEQ + si) * DHEAD + dc) >> 1;
                ((uint32_t *)dh)[u32i] = h0;
                ((uint32_t *)dl)[u32i] = l0;
                ((uint32_t *)dh)[u32i + 8 * 64] = h1;
                ((uint32_t *)dl)[u32i + 8 * 64] = l1;
            } else {
                float2 v0 = make_float2(acc[mt][nt][0] + b0, acc[mt][nt][1] + b1);
                float2 v1 = make_float2(acc[mt][nt][2] + b0, acc[mt][nt][3] + b1);
                *(float2 *)(Cout + (size_t)row * N + col) = v0;
                *(float2 *)(Cout + (size_t)(row + 8) * N + col) = v1;
            }
        }
    }
}

// ---------------------------------------------------------------------------
// Flash attention (causal), bf16x3, ldmatrix fragments, pure cp.async loads.
// CTA: 128 Q rows, 8 warps x 16 rows. KV tile 64. d = 128.
// smem u32: Qh[128*68] Ql[128*68] | stage st: Kh[64*68] Kl Vh Vl (4352 each).
// MMA terms grouped in passes to break accumulator RAW chains.
// ---------------------------------------------------------------------------
#define FL_QU   (128 * 68)          // u32 per Q array
#define FL_AU   (64 * 68)           // u32 per K/V array (4352)
#define FL_STGU (4 * FL_AU)         // 17408 u32 per stage
#define FLASH_SMEM ((2 * FL_QU + 2 * FL_STGU) * 4)

__global__ void __launch_bounds__(256) flash_causal() {
    extern __shared__ uint32_t smf[];
    const uint32_t sbase = smem_u32(smf);

    const int qt   = (gridDim.x - 1) - blockIdx.x;   // heavy tiles first
    const int h    = blockIdx.y;
    const int b    = blockIdx.z;
    const int tid  = threadIdx.x;
    const int lane = tid & 31;
    const int warp = tid >> 5;
    const int g    = lane >> 2;
    const int q4   = lane & 3;

    const size_t headoff = (size_t)(b * NHEAD + h) * SEQ * DHEAD;
    const uint16_t *Qhg = g_qh + headoff;
    const uint16_t *Qlg = g_ql + headoff;
    const uint16_t *Khg = g_kh + headoff;
    const uint16_t *Klg = g_kl + headoff;
    const uint16_t *Vhg = g_vh + headoff;
    const uint16_t *Vlg = g_vl + headoff;

    const int qr0 = qt * 128;

    // ---- Q tile: 2 arrays x (128 rows x 16 chunks) = 4096 cp.async chunks ----
#pragma unroll
    for (int i = 0; i < 16; i++) {
        int id  = tid + i * 256;       // 0..4095
        int arr = id >> 11;            // 0 = Qh, 1 = Ql
        int rc  = id & 2047;
        int row = rc >> 4;             // 0..127
        int c   = rc & 15;
        const uint16_t *src = (arr == 0 ? Qhg : Qlg) +
                              (size_t)(qr0 + row) * DHEAD + c * 8;
        cpa16(sbase + ((arr * FL_QU + row * 68 + c * 4) << 2), src);
    }

    auto copy_kv = [&](int kv0, int st) {
        const uint32_t stb = sbase + ((2 * FL_QU + st * FL_STGU) << 2);
#pragma unroll
        for (int i = 0; i < 16; i++) {
            int id  = tid + i * 256;
            int arr = id >> 10;                      // 0 Kh, 1 Kl, 2 Vh, 3 Vl
            int rc  = id & 1023;
            int row = rc >> 4;
            int c   = rc & 15;
            const uint16_t *base =
                (arr == 0) ? Khg : (arr == 1) ? Klg : (arr == 2) ? Vhg : Vlg;
            cpa16(stb + ((arr * FL_AU + row * 68 + c * 4) << 2),
                  base + (size_t)(kv0 + row) * DHEAD + c * 8);
        }
    };

    float Oacc[16][4];
#pragma unroll
    for (int i = 0; i < 16; i++)
#pragma unroll
        for (int e = 0; e < 4; e++) Oacc[i][e] = 0.f;
    float m_i[2] = {-1e30f, -1e30f};
    float l_i[2] = {0.f, 0.f};

    const int wr0   = warp * 16;
    const int grow0 = qr0 + wr0;
    const int jmax  = 2 * qt + 1;

    copy_kv(0, 0);
    CP_COMMIT();

    const int lt = lane >> 3;      // tile index within x4 (0..3)
    const int lr = lane & 7;       // row within tile

    for (int j = 0; j <= jmax; j++) {
        const int kv0 = j * 64;
        CP_WAIT0();
        __syncthreads();
        if (j + 1 <= jmax) {
            copy_kv((j + 1) * 64, (j + 1) & 1);
            CP_COMMIT();
        }

        if (kv0 <= grow0 + 15) {
            const uint32_t QH = sbase;
            const uint32_t KH = sbase + ((2 * FL_QU + (j & 1) * FL_STGU) << 2);
            const uint32_t VH = KH + ((2 * FL_AU) << 2);

            // ---- S = Q @ K^T : 16 x 64 per warp ----
            float sacc[8][4];
#pragma unroll
            for (int nt = 0; nt < 8; nt++)
#pragma unroll
                for (int e = 0; e < 4; e++) sacc[nt][e] = 0.f;

#pragma unroll
            for (int kk = 0; kk < 8; kk++) {
                uint32_t qrow = wr0 + ((lt & 1) << 3) + lr;
                uint32_t qc   = (kk << 1) + (lt >> 1);
                uint32_t qa   = QH + ((qrow * 68 + qc * 4) << 2);
                uint32_t ka[4];
#pragma unroll
                for (int i = 0; i < 4; i++) {
                    uint32_t krow = (i << 4) + ((lt >> 1) << 3) + lr;
                    uint32_t kc   = (kk << 1) + (lt & 1);
                    ka[i] = KH + ((krow * 68 + kc * 4) << 2);
                }
                uint32_t ah[4], al[4], bh[4][4], bl[4][4];
                LDSM4(ah, qa);
#pragma unroll
                for (int i = 0; i < 4; i++) LDSM4(bh[i], ka[i]);

                // pass 1: hh (8 independent MMAs)
#pragma unroll
                for (int i = 0; i < 4; i++) {
                    mma16(sacc[2 * i],     ah[0], ah[1], ah[2], ah[3], bh[i][0], bh[i][1]);
                    mma16(sacc[2 * i + 1], ah[0], ah[1], ah[2], ah[3], bh[i][2], bh[i][3]);
                }
#pragma unroll
                for (int i = 0; i < 4; i++) LDSM4(bl[i], ka[i] + (FL_AU << 2));
                // pass 2: hl
#pragma unroll
                for (int i = 0; i < 4; i++) {
                    mma16(sacc[2 * i],     ah[0], ah[1], ah[2], ah[3], bl[i][0], bl[i][1]);
                    mma16(sacc[2 * i + 1], ah[0], ah[1], ah[2], ah[3], bl[i][2], bl[i][3]);
                }
                LDSM4(al, qa + (FL_QU << 2));
                // pass 3: lh
#pragma unroll
                for (int i = 0; i < 4; i++) {
                    mma16(sacc[2 * i],     al[0], al[1], al[2], al[3], bh[i][0], bh[i][1]);
                    mma16(sacc[2 * i + 1], al[0], al[1], al[2], al[3], bh[i][2], bh[i][3]);
                }
            }

            // ---- causal mask (near diagonal only) ----
            if (kv0 + 63 > grow0) {
                const int r0 = grow0 + g;
#pragma unroll
                for (int nt = 0; nt < 8; nt++) {
                    int c0 = kv0 + nt * 8 + (q4 << 1);
                    if (c0 > r0)         sacc[nt][0] = -1e30f;
                    if (c0 + 1 > r0)     sacc[nt][1] = -1e30f;
                    if (c0 > r0 + 8)     sacc[nt][2] = -1e30f;
                    if (c0 + 1 > r0 + 8) sacc[nt][3] = -1e30f;
                }
            }

            // ---- streaming softmax ----
            float rmax0 = -1e30f, rmax1 = -1e30f;
#pragma unroll
            for (int nt = 0; nt < 8; nt++) {
                rmax0 = fmaxf(rmax0, fmaxf(sacc[nt][0], sacc[nt][1]));
                rmax1 = fmaxf(rmax1, fmaxf(sacc[nt][2], sacc[nt][3]));
            }
            rmax0 = fmaxf(rmax0, __shfl_xor_sync(0xffffffffu, rmax0, 1));
            rmax0 = fmaxf(rmax0, __shfl_xor_sync(0xffffffffu, rmax0, 2));
            rmax1 = fmaxf(rmax1, __shfl_xor_sync(0xffffffffu, rmax1, 1));
            rmax1 = fmaxf(rmax1, __shfl_xor_sync(0xffffffffu, rmax1, 2));

            float mn0 = fmaxf(m_i[0], rmax0);
            float mn1 = fmaxf(m_i[1], rmax1);
            float alpha0 = __expf(m_i[0] - mn0);
            float alpha1 = __expf(m_i[1] - mn1);

            float rs0 = 0.f, rs1 = 0.f;
#pragma unroll
            for (int nt = 0; nt < 8; nt++) {
                sacc[nt][0] = __expf(sacc[nt][0] - mn0);
                sacc[nt][1] = __expf(sacc[nt][1] - mn0);
                sacc[nt][2] = __expf(sacc[nt][2] - mn1);
                sacc[nt][3] = __expf(sacc[nt][3] - mn1);
                rs0 += sacc[nt][0] + sacc[nt][1];
                rs1 += sacc[nt][2] + sacc[nt][3];
            }
            rs0 += __shfl_xor_sync(0xffffffffu, rs0, 1);
            rs0 += __shfl_xor_sync(0xffffffffu, rs0, 2);
            rs1 += __shfl_xor_sync(0xffffffffu, rs1, 1);
            rs1 += __shfl_xor_sync(0xffffffffu, rs1, 2);

            l_i[0] = l_i[0] * alpha0 + rs0;
            l_i[1] = l_i[1] * alpha1 + rs1;
            m_i[0] = mn0;
            m_i[1] = mn1;

#pragma unroll
            for (int nt = 0; nt < 16; nt++) {
                Oacc[nt][0] *= alpha0; Oacc[nt][1] *= alpha0;
                Oacc[nt][2] *= alpha1; Oacc[nt][3] *= alpha1;
            }

            // ---- O += P @ V (P in regs; V frags via trans ldmatrix) ----
#pragma unroll
            for (int c = 0; c < 4; c++) {
                uint32_t ph[4], pl[4];
                split_pack(sacc[2 * c][0],     sacc[2 * c][1],     ph[0], pl[0]);
                split_pack(sacc[2 * c][2],     sacc[2 * c][3],     ph[1], pl[1]);
                split_pack(sacc[2 * c + 1][0], sacc[2 * c + 1][1], ph[2], pl[2]);
                split_pack(sacc[2 * c + 1][2], sacc[2 * c + 1][3], ph[3], pl[3]);
                const uint32_t srow = (c << 4) + ((lt & 1) << 3) + lr;
#pragma unroll
                for (int half = 0; half < 2; half++) {
                    uint32_t va[4];
#pragma unroll
                    for (int i = 0; i < 4; i++) {
                        uint32_t dc = ((half * 4 + i) << 1) + (lt >> 1);
                        va[i] = VH + ((srow * 68 + dc * 4) << 2);
                    }
                    uint32_t vh[4][4], vl[4][4];
#pragma unroll
                    for (int i = 0; i < 4; i++) LDSM4T(vh[i], va[i]);
                    // pass 1: hh (8 independent MMAs)
#pragma unroll
                    for (int i = 0; i < 4; i++) {
                        int o = 2 * (half * 4 + i);
                        mma16(Oacc[o],     ph[0], ph[1], ph[2], ph[3], vh[i][0], vh[i][1]);
                        mma16(Oacc[o + 1], ph[0], ph[1], ph[2], ph[3], vh[i][2], vh[i][3]);
                    }
#pragma unroll
                    for (int i = 0; i < 4; i++) LDSM4T(vl[i], va[i] + (FL_AU << 2));
                    // pass 2: hl
#pragma unroll
                    for (int i = 0; i < 4; i++) {
                        int o = 2 * (half * 4 + i);
                        mma16(Oacc[o],     ph[0], ph[1], ph[2], ph[3], vl[i][0], vl[i][1]);
                        mma16(Oacc[o + 1], ph[0], ph[1], ph[2], ph[3], vl[i][2], vl[i][3]);
                    }
                    // pass 3: lh
#pragma unroll
                    for (int i = 0; i < 4; i++) {
                        int o = 2 * (half * 4 + i);
                        mma16(Oacc[o],     pl[0], pl[1], pl[2], pl[3], vh[i][0], vh[i][1]);
                        mma16(Oacc[o + 1], pl[0], pl[1], pl[2], pl[3], vh[i][2], vh[i][3]);
                    }
                }
            }
        }
        __syncthreads();
    }

    // ---- epilogue: normalize, split, write hi/lo attn ----
    const float inv0 = 1.f / l_i[0];
    const float inv1 = 1.f / l_i[1];
    const int   s0   = qr0 + wr0 + g;
    const size_t base0 = ((size_t)(b * SEQ) + s0) * (HID / 2) + h * 64;
#pragma unroll
    for (int nt = 0; nt < 16; nt++) {
        float o00 = Oacc[nt][0] * inv0, o01 = Oacc[nt][1] * inv0;
        float o10 = Oacc[nt][2] * inv1, o11 = Oacc[nt][3] * inv1;
        uint32_t h0, l0, h1, l1;
        split_pack(o00, o01, h0, l0);
        split_pack(o10, o11, h1, l1);
        size_t ci = base0 + nt * 4 + q4;
        ((uint32_t *)g_ath)[ci] = h0;
        ((uint32_t *)g_atl)[ci] = l0;
        ((uint32_t *)g_ath)[ci + 8 * (HID / 2)] = h1;
        ((uint32_t *)g_atl)[ci + 8 * (HID / 2)] = l1;
    }
}

// ---------------------------------------------------------------------------
// kernel_launch
// ---------------------------------------------------------------------------
extern "C" void kernel_launch(void *const *d_in, const int *in_sizes, int n_in,
                              void *d_out, int out_size) {
    (void)in_sizes; (void)n_in; (void)out_size;
    const float *hs     = (const float *)d_in[0];
    const float *w_attn = (const float *)d_in[1];
    const float *b_attn = (const float *)d_in[2];
    const float *w_proj = (const float *)d_in[3];
    const float *b_proj = (const float *)d_in[4];
    float *out = (float *)d_out;

    cudaFuncSetAttribute(gemm_ldsm<1>,
                         cudaFuncAttributeMaxDynamicSharedMemorySize, GEMM_SMEM);
    cudaFuncSetAttribute(gemm_ldsm<0>,
                         cudaFuncAttributeMaxDynamicSharedMemorySize, GEMM_SMEM);
    cudaFuncSetAttribute(flash_causal,
                         cudaFuncAttributeMaxDynamicSharedMemorySize, FLASH_SMEM);

    uint16_t *hidh, *hidl, *wah, *wal, *wph, *wpl, *ath, *atl;
    cudaGetSymbolAddress((void **)&hidh, g_hidh);
    cudaGetSymbolAddress((void **)&hidl, g_hidl);
    cudaGetSymbolAddress((void **)&wah,  g_wah);
    cudaGetSymbolAddress((void **)&wal,  g_wal);
    cudaGetSymbolAddress((void **)&wph,  g_wph);
    cudaGetSymbolAddress((void **)&wpl,  g_wpl);
    cudaGetSymbolAddress((void **)&ath,  g_ath);
    cudaGetSymbolAddress((void **)&atl,  g_atl);

    // 0) pre-split fp32 inputs to bf16 hi/lo
    split4<<<(MTOT * HID) / 1024, 256>>>((const float4 *)hs,
                                         (uint2 *)hidh, (uint2 *)hidl);
    split4<<<(HID * NQKV) / 1024, 256>>>((const float4 *)w_attn,
                                         (uint2 *)wah, (uint2 *)wal);
    split4<<<(HID * HID) / 1024, 256>>>((const float4 *)w_proj,
                                        (uint2 *)wph, (uint2 *)wpl);

    // 1) QKV projection -> split bf16 q/k/v (Q pre-scaled)
    gemm_ldsm<1><<<dim3(NQKV / 256, MTOT / 128), 256, GEMM_SMEM>>>(
        hidh, hidl, wah, wal, b_attn, nullptr, MTOT, NQKV, HID);

    // 2) causal flash attention -> split bf16 attn (g_ath/g_atl)
    flash_causal<<<dim3(SEQ / 128, NHEAD, BB), 256, FLASH_SMEM>>>();

    // 3) output projection -> d_out
    gemm_ldsm<0><<<dim3(HID / 256, MTOT / 128), 256, GEMM_SMEM>>>(
        ath, atl, wph, wpl, b_proj, out, MTOT, HID, HID);
}

// round 8
// speedup vs baseline: 1.0353x; 1.0353x over previous
#include <cuda_runtime.h>
#include <cstdint>

// Problem constants (fixed by the reference)
#define BB    2
#define SEQ   2048
#define HID   2048
#define NHEAD 16
#define DHEAD 128
#define MTOT  (BB * SEQ)      // 4096
#define NQKV  (3 * HID)       // 6144
#define QSCALE 0.088388347648318447f

// ---------------------------------------------------------------------------
// Device scratch (all 16B-aligned for cp.async / vector access)
// ---------------------------------------------------------------------------
__device__ __align__(128) uint16_t g_qh[(size_t)BB * NHEAD * SEQ * DHEAD];
__device__ __align__(128) uint16_t g_ql[(size_t)BB * NHEAD * SEQ * DHEAD];
__device__ __align__(128) uint16_t g_kh[(size_t)BB * NHEAD * SEQ * DHEAD];
__device__ __align__(128) uint16_t g_kl[(size_t)BB * NHEAD * SEQ * DHEAD];
__device__ __align__(128) uint16_t g_vh[(size_t)BB * NHEAD * SEQ * DHEAD];
__device__ __align__(128) uint16_t g_vl[(size_t)BB * NHEAD * SEQ * DHEAD];

__device__ __align__(128) uint16_t g_hidh[(size_t)MTOT * HID];
__device__ __align__(128) uint16_t g_hidl[(size_t)MTOT * HID];
__device__ __align__(128) uint16_t g_wah[(size_t)HID * NQKV];
__device__ __align__(128) uint16_t g_wal[(size_t)HID * NQKV];
__device__ __align__(128) uint16_t g_wph[(size_t)HID * HID];
__device__ __align__(128) uint16_t g_wpl[(size_t)HID * HID];
__device__ __align__(128) uint16_t g_ath[(size_t)MTOT * HID];
__device__ __align__(128) uint16_t g_atl[(size_t)MTOT * HID];

// ---------------------------------------------------------------------------
// Helpers
// ---------------------------------------------------------------------------
__device__ __forceinline__ void split_pack(float x0, float x1,
                                           uint32_t &h, uint32_t &l) {
    asm("cvt.rn.bf16x2.f32 %0, %1, %2;" : "=r"(h) : "f"(x1), "f"(x0));
    float h0 = __uint_as_float(h << 16);
    float h1 = __uint_as_float(h & 0xffff0000u);
    asm("cvt.rn.bf16x2.f32 %0, %1, %2;" : "=r"(l) : "f"(x1 - h1), "f"(x0 - h0));
}

__device__ __forceinline__ uint32_t smem_u32(const void *p) {
    uint32_t a;
    asm("{ .reg .u64 t; cvta.to.shared.u64 t, %1; cvt.u32.u64 %0, t; }"
        : "=r"(a) : "l"(p));
    return a;
}

__device__ __forceinline__ void mma16(float *d,
                                      uint32_t a0, uint32_t a1, uint32_t a2, uint32_t a3,
                                      uint32_t b0, uint32_t b1) {
    asm volatile(
        "mma.sync.aligned.m16n8k16.row.col.f32.bf16.bf16.f32 "
        "{%0,%1,%2,%3}, {%4,%5,%6,%7}, {%8,%9}, {%0,%1,%2,%3};\n"
        : "+f"(d[0]), "+f"(d[1]), "+f"(d[2]), "+f"(d[3])
        : "r"(a0), "r"(a1), "r"(a2), "r"(a3), "r"(b0), "r"(b1));
}
__device__ __forceinline__ void mma3(float *d, const uint32_t *ah, const uint32_t *al,
                                     uint32_t bh0, uint32_t bh1,
                                     uint32_t bl0, uint32_t bl1) {
    mma16(d, ah[0], ah[1], ah[2], ah[3], bh0, bh1);
    mma16(d, ah[0], ah[1], ah[2], ah[3], bl0, bl1);
    mma16(d, al[0], al[1], al[2], al[3], bh0, bh1);
}

#define LDSM4(r, addr)                                                       \
    asm volatile("ldmatrix.sync.aligned.m8n8.x4.shared.b16 {%0,%1,%2,%3}, [%4];" \
        : "=r"((r)[0]), "=r"((r)[1]), "=r"((r)[2]), "=r"((r)[3]) : "r"(addr))
#define LDSM4T(r, addr)                                                      \
    asm volatile("ldmatrix.sync.aligned.m8n8.x4.trans.shared.b16 {%0,%1,%2,%3}, [%4];" \
        : "=r"((r)[0]), "=r"((r)[1]), "=r"((r)[2]), "=r"((r)[3]) : "r"(addr))

__device__ __forceinline__ void cpa16(uint32_t dst, const void *src) {
    asm volatile("cp.async.cg.shared.global [%0], [%1], 16;"
                 :: "r"(dst), "l"(src) : "memory");
}
#define CP_COMMIT() asm volatile("cp.async.commit_group;" ::: "memory")
#define CP_WAIT2()  asm volatile("cp.async.wait_group 2;" ::: "memory")
#define CP_WAIT0()  asm volatile("cp.async.wait_group 0;" ::: "memory")

// ---------------------------------------------------------------------------
// Split kernel: fp32 -> bf16 hi + bf16 lo (row-major preserved)
// ---------------------------------------------------------------------------
__global__ void __launch_bounds__(256)
split4(const float4 *__restrict__ x, uint2 *__restrict__ hi, uint2 *__restrict__ lo) {
    int i = blockIdx.x * 256 + threadIdx.x;
    float4 v = x[i];
    uint32_t h0, l0, h1, l1;
    split_pack(v.x, v.y, h0, l0);
    split_pack(v.z, v.w, h1, l1);
    hi[i] = make_uint2(h0, h1);
    lo[i] = make_uint2(l0, l1);
}

// ---------------------------------------------------------------------------
// GEMM: C = A @ B + bias, bf16x3, pre-split inputs, 4-stage cp.async.
// CTA tile 128m x 256n, 512 threads = 16 warps (2 wm x 8 wn), warp tile 64x32.
// Grouped MMA passes (hh | hl | lh) minimize fragment liveness (fits 128 regs
// at 512 thr -> 16 warps resident = 4 warps/SMSP latency hiding).
// MODE 1: QKV epilogue -> split bf16 q/k/v (Q pre-scaled) | MODE 0: fp32 out.
// ---------------------------------------------------------------------------
#define STG_BYTES 53248
#define OFF_AH 0
#define OFF_AL 10240
#define OFF_BH 20480
#define OFF_BL 36864
#define GEMM_SMEM (4 * STG_BYTES)

template <int MODE>
__global__ void __launch_bounds__(512)
gemm_ldsm(const uint16_t *__restrict__ Ah, const uint16_t *__restrict__ Al,
          const uint16_t *__restrict__ Bh, const uint16_t *__restrict__ Bl,
          const float *__restrict__ bias, float *__restrict__ Cout,
          int M, int N, int K) {
    extern __shared__ char smc[];
    const uint32_t sbase = smem_u32(smc);

    const int tid  = threadIdx.x;
    const int lane = tid & 31;
    const int warp = tid >> 5;
    const int wm   = warp >> 3;      // 0..1
    const int wn   = warp & 7;       // 0..7
    const int m0   = blockIdx.y * 128;
    const int n0   = blockIdx.x * 256;
    const int g    = lane >> 2;
    const int q4   = lane & 3;

    float acc[4][4][4];
#pragma unroll
    for (int i = 0; i < 4; i++)
#pragma unroll
        for (int j = 0; j < 4; j++)
#pragma unroll
            for (int e = 0; e < 4; e++) acc[i][j][e] = 0.f;

    auto issue = [&](int s) {
        const uint32_t sb = sbase + (s & 3) * STG_BYTES;
        const int kb = s << 5;
        // A: 128 rows x 4 chunks = 512 ids (hi+lo per id)
        {
            int row = tid >> 2;
            int c   = tid & 3;
            size_t gidx = (size_t)(m0 + row) * K + kb + c * 8;
            uint32_t d = (row * 5 + c) << 4;
            cpa16(sb + OFF_AH + d, Ah + gidx);
            cpa16(sb + OFF_AL + d, Al + gidx);
        }
        // B: 32 k x 32 chunks = 1024 ids (hi+lo per id)
#pragma unroll
        for (int i = 0; i < 2; i++) {
            int id = tid + i * 512;
            int k  = id >> 5;
            int c  = id & 31;
            size_t gidx = (size_t)(kb + k) * N + n0 + c * 8;
            uint32_t d = ((k << 5) + (c ^ (k & 7))) << 4;
            cpa16(sb + OFF_BH + d, Bh + gidx);
            cpa16(sb + OFF_BL + d, Bl + gidx);
        }
    };

    auto compute = [&](int s) {
        const uint32_t sb = sbase + (s & 3) * STG_BYTES;
        const int arow = wm * 64 + (lane & 15);
        const int lt16 = lane >> 4;
        const int cbas = wn * 4 + ((lane >> 3) & 1);
#pragma unroll
        for (int kk = 0; kk < 2; kk++) {
            const int ac   = kk * 2 + lt16;
            const int kloc = kk * 16 + (lt16 << 3) + (lane & 7);
            uint32_t ad[4], bd[2];
#pragma unroll
            for (int mt = 0; mt < 4; mt++)
                ad[mt] = sb + OFF_AH + (((arow + mt * 16) * 5 + ac) << 4);
#pragma unroll
            for (int bt = 0; bt < 2; bt++) {
                int c = cbas + bt * 2;
                bd[bt] = sb + OFF_BH + (((kloc << 5) + (c ^ (kloc & 7))) << 4);
            }

            uint32_t ah[4][4], al[4][4], bh[2][4], bl[2][4];
#pragma unroll
            for (int mt = 0; mt < 4; mt++) LDSM4(ah[mt], ad[mt]);
#pragma unroll
            for (int bt = 0; bt < 2; bt++) LDSM4T(bh[bt], bd[bt]);

            // ---- pass 1: A_hi x B_hi (16 independent MMAs) ----
#pragma unroll
            for (int bt = 0; bt < 2; bt++)
#pragma unroll
                for (int mt = 0; mt < 4; mt++) {
                    mma16(acc[mt][2 * bt],     ah[mt][0], ah[mt][1], ah[mt][2], ah[mt][3],
                          bh[bt][0], bh[bt][2]);
                    mma16(acc[mt][2 * bt + 1], ah[mt][0], ah[mt][1], ah[mt][2], ah[mt][3],
                          bh[bt][1], bh[bt][3]);
                }

#pragma unroll
            for (int bt = 0; bt < 2; bt++)
                LDSM4T(bl[bt], bd[bt] + (OFF_BL - OFF_BH));

            // ---- pass 2: A_hi x B_lo ----
#pragma unroll
            for (int bt = 0; bt < 2; bt++)
#pragma unroll
                for (int mt = 0; mt < 4; mt++) {
                    mma16(acc[mt][2 * bt],     ah[mt][0], ah[mt][1], ah[mt][2], ah[mt][3],
                          bl[bt][0], bl[bt][2]);
                    mma16(acc[mt][2 * bt + 1], ah[mt][0], ah[mt][1], ah[mt][2], ah[mt][3],
                          bl[bt][1], bl[bt][3]);
                }

#pragma unroll
            for (int mt = 0; mt < 4; mt++)
                LDSM4(al[mt], ad[mt] + (OFF_AL - OFF_AH));

            // ---- pass 3: A_lo x B_hi ----
#pragma unroll
            for (int bt = 0; bt < 2; bt++)
#pragma unroll
                for (int mt = 0; mt < 4; mt++) {
                    mma16(acc[mt][2 * bt],     al[mt][0], al[mt][1], al[mt][2], al[mt][3],
                          bh[bt][0], bh[bt][2]);
                    mma16(acc[mt][2 * bt + 1], al[mt][0], al[mt][1], al[mt][2], al[mt][3],
                          bh[bt][1], bh[bt][3]);
                }
        }
    };

    const int S = K >> 5;
    issue(0); CP_COMMIT();
    issue(1); CP_COMMIT();
    issue(2); CP_COMMIT();

    for (int s = 0; s < S; s++) {
        CP_WAIT2();
        __syncthreads();
        compute(s);
        if (s + 3 < S) issue(s + 3);
        CP_COMMIT();
    }

    // ---- epilogue ----
#pragma unroll
    for (int mt = 0; mt < 4; mt++) {
#pragma unroll
        for (int nt = 0; nt < 4; nt++) {
            int row = m0 + wm * 64 + mt * 16 + g;
            int col = n0 + wn * 32 + nt * 8 + (q4 << 1);
            float b0 = bias[col];
            float b1 = bias[col + 1];
            if (MODE == 1) {
                int which = col >> 11;
                int head  = (col >> 7) & 15;
                int dc    = col & 127;
                uint16_t *dh = (which == 0) ? g_qh : ((which == 1) ? g_kh : g_vh);
                uint16_t *dl = (which == 0) ? g_ql : ((which == 1) ? g_kl : g_vl);
                float sc = (which == 0) ? QSCALE : 1.f;
                float v00 = (acc[mt][nt][0] + b0) * sc;
                float v01 = (acc[mt][nt][1] + b1) * sc;
                float v10 = (acc[mt][nt][2] + b0) * sc;
                float v11 = (acc[mt][nt][3] + b1) * sc;
                uint32_t h0, l0, h1, l1;
                split_pack(v00, v01, h0, l0);
                split_pack(v10, v11, h1, l1);
                int bi = row >> 11;
                int si = row & 2047;
                size_t u32i = (((size_t)(bi * NHEAD + head) * SEQ + si) * DHEAD + dc) >> 1;
                ((uint32_t *)dh)[u32i] = h0;
                ((uint32_t *)dl)[u32i] = l0;
                ((uint32_t *)dh)[u32i + 8 * 64] = h1;
                ((uint32_t *)dl)[u32i + 8 * 64] = l1;
            } else {
                float2 v0 = make_float2(acc[mt][nt][0] + b0, acc[mt][nt][1] + b1);
                float2 v1 = make_float2(acc[mt][nt][2] + b0, acc[mt][nt][3] + b1);
                *(float2 *)(Cout + (size_t)row * N + col) = v0;
                *(float2 *)(Cout + (size_t)(row + 8) * N + col) = v1;
            }
        }
    }
}

// ---------------------------------------------------------------------------
// Flash attention (causal), bf16x3, ldmatrix fragments, pure cp.async loads.
// (round-6 version, best measured)
// ---------------------------------------------------------------------------
#define FL_QU   (128 * 68)          // u32 per Q array
#define FL_AU   (64 * 68)           // u32 per K/V array (4352)
#define FL_STGU (4 * FL_AU)         // 17408 u32 per stage
#define FLASH_SMEM ((2 * FL_QU + 2 * FL_STGU) * 4)

__global__ void __launch_bounds__(256) flash_causal() {
    extern __shared__ uint32_t smf[];
    const uint32_t sbase = smem_u32(smf);

    const int qt   = (gridDim.x - 1) - blockIdx.x;   // heavy tiles first
    const int h    = blockIdx.y;
    const int b    = blockIdx.z;
    const int tid  = threadIdx.x;
    const int lane = tid & 31;
    const int warp = tid >> 5;
    const int g    = lane >> 2;
    const int q4   = lane & 3;

    const size_t headoff = (size_t)(b * NHEAD + h) * SEQ * DHEAD;
    const uint16_t *Qhg = g_qh + headoff;
    const uint16_t *Qlg = g_ql + headoff;
    const uint16_t *Khg = g_kh + headoff;
    const uint16_t *Klg = g_kl + headoff;
    const uint16_t *Vhg = g_vh + headoff;
    const uint16_t *Vlg = g_vl + headoff;

    const int qr0 = qt * 128;

    // ---- Q tile: 2 arrays x (128 rows x 16 chunks) = 4096 cp.async chunks ----
#pragma unroll
    for (int i = 0; i < 16; i++) {
        int id  = tid + i * 256;       // 0..4095
        int arr = id >> 11;            // 0 = Qh, 1 = Ql
        int rc  = id & 2047;
        int row = rc >> 4;             // 0..127
        int c   = rc & 15;
        const uint16_t *src = (arr == 0 ? Qhg : Qlg) +
                              (size_t)(qr0 + row) * DHEAD + c * 8;
        cpa16(sbase + ((arr * FL_QU + row * 68 + c * 4) << 2), src);
    }

    auto copy_kv = [&](int kv0, int st) {
        const uint32_t stb = sbase + ((2 * FL_QU + st * FL_STGU) << 2);
#pragma unroll
        for (int i = 0; i < 16; i++) {
            int id  = tid + i * 256;
            int arr = id >> 10;                      // 0 Kh, 1 Kl, 2 Vh, 3 Vl
            int rc  = id & 1023;
            int row = rc >> 4;
            int c   = rc & 15;
            const uint16_t *base =
                (arr == 0) ? Khg : (arr == 1) ? Klg : (arr == 2) ? Vhg : Vlg;
            cpa16(stb + ((arr * FL_AU + row * 68 + c * 4) << 2),
                  base + (size_t)(kv0 + row) * DHEAD + c * 8);
        }
    };

    float Oacc[16][4];
#pragma unroll
    for (int i = 0; i < 16; i++)
#pragma unroll
        for (int e = 0; e < 4; e++) Oacc[i][e] = 0.f;
    float m_i[2] = {-1e30f, -1e30f};
    float l_i[2] = {0.f, 0.f};

    const int wr0   = warp * 16;
    const int grow0 = qr0 + wr0;
    const int jmax  = 2 * qt + 1;

    copy_kv(0, 0);
    CP_COMMIT();

    const int lt = lane >> 3;      // tile index within x4 (0..3)
    const int lr = lane & 7;       // row within tile

    for (int j = 0; j <= jmax; j++) {
        const int kv0 = j * 64;
        CP_WAIT0();
        __syncthreads();
        if (j + 1 <= jmax) {
            copy_kv((j + 1) * 64, (j + 1) & 1);
            CP_COMMIT();
        }

        if (kv0 <= grow0 + 15) {
            const uint32_t QH = sbase;
            const uint32_t KH = sbase + ((2 * FL_QU + (j & 1) * FL_STGU) << 2);
            const uint32_t VH = KH + ((2 * FL_AU) << 2);

            // ---- S = Q @ K^T : 16 x 64 per warp ----
            float sacc[8][4];
#pragma unroll
            for (int nt = 0; nt < 8; nt++)
#pragma unroll
                for (int e = 0; e < 4; e++) sacc[nt][e] = 0.f;

#pragma unroll
            for (int kk = 0; kk < 8; kk++) {
                uint32_t ah[4], al[4];
                {
                    uint32_t qrow = wr0 + ((lt & 1) << 3) + lr;
                    uint32_t qc   = (kk << 1) + (lt >> 1);
                    uint32_t qa   = QH + ((qrow * 68 + qc * 4) << 2);
                    LDSM4(ah, qa);
                    LDSM4(al, qa + (FL_QU << 2));
                }
#pragma unroll
                for (int i = 0; i < 4; i++) {
                    uint32_t krow = (i << 4) + ((lt >> 1) << 3) + lr;
                    uint32_t kc   = (kk << 1) + (lt & 1);
                    uint32_t ka   = KH + ((krow * 68 + kc * 4) << 2);
                    uint32_t bh[4], bl[4];
                    LDSM4(bh, ka);
                    LDSM4(bl, ka + (FL_AU << 2));
                    mma3(sacc[2 * i],     ah, al, bh[0], bh[1], bl[0], bl[1]);
                    mma3(sacc[2 * i + 1], ah, al, bh[2], bh[3], bl[2], bl[3]);
                }
            }

            // ---- causal mask (near diagonal only) ----
            if (kv0 + 63 > grow0) {
                const int r0 = grow0 + g;
#pragma unroll
                for (int nt = 0; nt < 8; nt++) {
                    int c0 = kv0 + nt * 8 + (q4 << 1);
                    if (c0 > r0)         sacc[nt][0] = -1e30f;
                    if (c0 + 1 > r0)     sacc[nt][1] = -1e30f;
                    if (c0 > r0 + 8)     sacc[nt][2] = -1e30f;
                    if (c0 + 1 > r0 + 8) sacc[nt][3] = -1e30f;
                }
            }

            // ---- streaming softmax ----
            float rmax0 = -1e30f, rmax1 = -1e30f;
#pragma unroll
            for (int nt = 0; nt < 8; nt++) {
                rmax0 = fmaxf(rmax0, fmaxf(sacc[nt][0], sacc[nt][1]));
                rmax1 = fmaxf(rmax1, fmaxf(sacc[nt][2], sacc[nt][3]));
            }
            rmax0 = fmaxf(rmax0, __shfl_xor_sync(0xffffffffu, rmax0, 1));
            rmax0 = fmaxf(rmax0, __shfl_xor_sync(0xffffffffu, rmax0, 2));
            rmax1 = fmaxf(rmax1, __shfl_xor_sync(0xffffffffu, rmax1, 1));
            rmax1 = fmaxf(rmax1, __shfl_xor_sync(0xffffffffu, rmax1, 2));

            float mn0 = fmaxf(m_i[0], rmax0);
            float mn1 = fmaxf(m_i[1], rmax1);
            float alpha0 = __expf(m_i[0] - mn0);
            float alpha1 = __expf(m_i[1] - mn1);

            float rs0 = 0.f, rs1 = 0.f;
#pragma unroll
            for (int nt = 0; nt < 8; nt++) {
                sacc[nt][0] = __expf(sacc[nt][0] - mn0);
                sacc[nt][1] = __expf(sacc[nt][1] - mn0);
                sacc[nt][2] = __expf(sacc[nt][2] - mn1);
                sacc[nt][3] = __expf(sacc[nt][3] - mn1);
                rs0 += sacc[nt][0] + sacc[nt][1];
                rs1 += sacc[nt][2] + sacc[nt][3];
            }
            rs0 += __shfl_xor_sync(0xffffffffu, rs0, 1);
            rs0 += __shfl_xor_sync(0xffffffffu, rs0, 2);
            rs1 += __shfl_xor_sync(0xffffffffu, rs1, 1);
            rs1 += __shfl_xor_sync(0xffffffffu, rs1, 2);

            l_i[0] = l_i[0] * alpha0 + rs0;
            l_i[1] = l_i[1] * alpha1 + rs1;
            m_i[0] = mn0;
            m_i[1] = mn1;

#pragma unroll
            for (int nt = 0; nt < 16; nt++) {
                Oacc[nt][0] *= alpha0; Oacc[nt][1] *= alpha0;
                Oacc[nt][2] *= alpha1; Oacc[nt][3] *= alpha1;
            }

            // ---- O += P @ V (P in regs; V frags via trans ldmatrix) ----
#pragma unroll
            for (int c = 0; c < 4; c++) {
                uint32_t ph[4], pl[4];
                split_pack(sacc[2 * c][0],     sacc[2 * c][1],     ph[0], pl[0]);
                split_pack(sacc[2 * c][2],     sacc[2 * c][3],     ph[1], pl[1]);
                split_pack(sacc[2 * c + 1][0], sacc[2 * c + 1][1], ph[2], pl[2]);
                split_pack(sacc[2 * c + 1][2], sacc[2 * c + 1][3], ph[3], pl[3]);
#pragma unroll
                for (int i = 0; i < 8; i++) {
                    uint32_t srow = (c << 4) + ((lt & 1) << 3) + lr;
                    uint32_t dc   = (i << 1) + (lt >> 1);
                    uint32_t va   = VH + ((srow * 68 + dc * 4) << 2);
                    uint32_t vh[4], vl[4];
                    LDSM4T(vh, va);
                    LDSM4T(vl, va + (FL_AU << 2));
                    mma3(Oacc[2 * i],     ph, pl, vh[0], vh[1], vl[0], vl[1]);
                    mma3(Oacc[2 * i + 1], ph, pl, vh[2], vh[3], vl[2], vl[3]);
                }
            }
        }
        __syncthreads();
    }

    // ---- epilogue: normalize, split, write hi/lo attn ----
    const float inv0 = 1.f / l_i[0];
    const float inv1 = 1.f / l_i[1];
    const int   s0   = qr0 + wr0 + g;
    const size_t base0 = ((size_t)(b * SEQ) + s0) * (HID / 2) + h * 64;
#pragma unroll
    for (int nt = 0; nt < 16; nt++) {
        float o00 = Oacc[nt][0] * inv0, o01 = Oacc[nt][1] * inv0;
        float o10 = Oacc[nt][2] * inv1, o11 = Oacc[nt][3] * inv1;
        uint32_t h0, l0, h1, l1;
        split_pack(o00, o01, h0, l0);
        split_pack(o10, o11, h1, l1);
        size_t ci = base0 + nt * 4 + q4;
        ((uint32_t *)g_ath)[ci] = h0;
        ((uint32_t *)g_atl)[ci] = l0;
        ((uint32_t *)g_ath)[ci + 8 * (HID / 2)] = h1;
        ((uint32_t *)g_atl)[ci + 8 * (HID / 2)] = l1;
    }
}

// ---------------------------------------------------------------------------
// kernel_launch
// ---------------------------------------------------------------------------
extern "C" void kernel_launch(void *const *d_in, const int *in_sizes, int n_in,
                              void *d_out, int out_size) {
    (void)in_sizes; (void)n_in; (void)out_size;
    const float *hs     = (const float *)d_in[0];
    const float *w_attn = (const float *)d_in[1];
    const float *b_attn = (const float *)d_in[2];
    const float *w_proj = (const float *)d_in[3];
    const float *b_proj = (const float *)d_in[4];
    float *out = (float *)d_out;

    cudaFuncSetAttribute(gemm_ldsm<1>,
                         cudaFuncAttributeMaxDynamicSharedMemorySize, GEMM_SMEM);
    cudaFuncSetAttribute(gemm_ldsm<0>,
                         cudaFuncAttributeMaxDynamicSharedMemorySize, GEMM_SMEM);
    cudaFuncSetAttribute(flash_causal,
                         cudaFuncAttributeMaxDynamicSharedMemorySize, FLASH_SMEM);

    uint16_t *hidh, *hidl, *wah, *wal, *wph, *wpl, *ath, *atl;
    cudaGetSymbolAddress((void **)&hidh, g_hidh);
    cudaGetSymbolAddress((void **)&hidl, g_hidl);
    cudaGetSymbolAddress((void **)&wah,  g_wah);
    cudaGetSymbolAddress((void **)&wal,  g_wal);
    cudaGetSymbolAddress((void **)&wph,  g_wph);
    cudaGetSymbolAddress((void **)&wpl,  g_wpl);
    cudaGetSymbolAddress((void **)&ath,  g_ath);
    cudaGetSymbolAddress((void **)&atl,  g_atl);

    // 0) pre-split fp32 inputs to bf16 hi/lo
    split4<<<(MTOT * HID) / 1024, 256>>>((const float4 *)hs,
                                         (uint2 *)hidh, (uint2 *)hidl);
    split4<<<(HID * NQKV) / 1024, 256>>>((const float4 *)w_attn,
                                         (uint2 *)wah, (uint2 *)wal);
    split4<<<(HID * HID) / 1024, 256>>>((const float4 *)w_proj,
                                        (uint2 *)wph, (uint2 *)wpl);

    // 1) QKV projection -> split bf16 q/k/v (Q pre-scaled)
    gemm_ldsm<1><<<dim3(NQKV / 256, MTOT / 128), 512, GEMM_SMEM>>>(
        hidh, hidl, wah, wal, b_attn, nullptr, MTOT, NQKV, HID);

    // 2) causal flash attention -> split bf16 attn (g_ath/g_atl)
    flash_causal<<<dim3(SEQ / 128, NHEAD, BB), 256, FLASH_SMEM>>>();

    // 3) output projection -> d_out
    gemm_ldsm<0><<<dim3(HID / 256, MTOT / 128), 512, GEMM_SMEM>>>(
        ath, atl, wph, wpl, b_proj, out, MTOT, HID, HID);
}

// round 9
// speedup vs baseline: 1.2959x; 1.2517x over previous
#include <cuda_runtime.h>
#include <cstdint>

// Problem constants (fixed by the reference)
#define BB    2
#define SEQ   2048
#define HID   2048
#define NHEAD 16
#define DHEAD 128
#define MTOT  (BB * SEQ)      // 4096
#define NQKV  (3 * HID)       // 6144
#define QSCALE 0.088388347648318447f

// ---------------------------------------------------------------------------
// Device scratch (all 16B-aligned for cp.async / vector access)
// ---------------------------------------------------------------------------
__device__ __align__(128) uint16_t g_qh[(size_t)BB * NHEAD * SEQ * DHEAD];   // bf16
__device__ __align__(128) uint16_t g_ql[(size_t)BB * NHEAD * SEQ * DHEAD];
__device__ __align__(128) uint16_t g_kh[(size_t)BB * NHEAD * SEQ * DHEAD];
__device__ __align__(128) uint16_t g_kl[(size_t)BB * NHEAD * SEQ * DHEAD];
__device__ __align__(128) uint16_t g_vh[(size_t)BB * NHEAD * SEQ * DHEAD];
__device__ __align__(128) uint16_t g_vl[(size_t)BB * NHEAD * SEQ * DHEAD];

__device__ __align__(128) uint16_t g_hidh[(size_t)MTOT * HID];   // fp16 split hi
__device__ __align__(128) uint16_t g_hidl[(size_t)MTOT * HID];   // fp16 split lo
__device__ __align__(128) uint16_t g_wah[(size_t)HID * NQKV];    // fp16 rounded
__device__ __align__(128) uint16_t g_wph[(size_t)HID * HID];     // fp16 rounded
__device__ __align__(128) uint16_t g_ath[(size_t)MTOT * HID];    // fp16 split hi
__device__ __align__(128) uint16_t g_atl[(size_t)MTOT * HID];    // fp16 split lo

// ---------------------------------------------------------------------------
// Helpers
// ---------------------------------------------------------------------------
// bf16 split (used by flash + QKV epilogue)
__device__ __forceinline__ void split_pack(float x0, float x1,
                                           uint32_t &h, uint32_t &l) {
    asm("cvt.rn.bf16x2.f32 %0, %1, %2;" : "=r"(h) : "f"(x1), "f"(x0));
    float h0 = __uint_as_float(h << 16);
    float h1 = __uint_as_float(h & 0xffff0000u);
    asm("cvt.rn.bf16x2.f32 %0, %1, %2;" : "=r"(l) : "f"(x1 - h1), "f"(x0 - h0));
}

// fp16 split: h = {fp16(x0) lo16, fp16(x1) hi16}, l = residuals in fp16
__device__ __forceinline__ void split_pack_h(float x0, float x1,
                                             uint32_t &h, uint32_t &l) {
    asm("cvt.rn.f16x2.f32 %0, %1, %2;" : "=r"(h) : "f"(x1), "f"(x0));
    float h0f, h1f;
    asm("{ .reg .b16 a, b;\n\t"
        "  mov.b32 {a, b}, %2;\n\t"
        "  cvt.f32.f16 %0, a;\n\t"
        "  cvt.f32.f16 %1, b; }"
        : "=f"(h0f), "=f"(h1f) : "r"(h));
    asm("cvt.rn.f16x2.f32 %0, %1, %2;" : "=r"(l) : "f"(x1 - h1f), "f"(x0 - h0f));
}
__device__ __forceinline__ uint32_t round_pack_h(float x0, float x1) {
    uint32_t h;
    asm("cvt.rn.f16x2.f32 %0, %1, %2;" : "=r"(h) : "f"(x1), "f"(x0));
    return h;
}

__device__ __forceinline__ uint32_t smem_u32(const void *p) {
    uint32_t a;
    asm("{ .reg .u64 t; cvta.to.shared.u64 t, %1; cvt.u32.u64 %0, t; }"
        : "=r"(a) : "l"(p));
    return a;
}

// bf16 mma (flash)
__device__ __forceinline__ void mma16(float *d,
                                      uint32_t a0, uint32_t a1, uint32_t a2, uint32_t a3,
                                      uint32_t b0, uint32_t b1) {
    asm volatile(
        "mma.sync.aligned.m16n8k16.row.col.f32.bf16.bf16.f32 "
        "{%0,%1,%2,%3}, {%4,%5,%6,%7}, {%8,%9}, {%0,%1,%2,%3};\n"
        : "+f"(d[0]), "+f"(d[1]), "+f"(d[2]), "+f"(d[3])
        : "r"(a0), "r"(a1), "r"(a2), "r"(a3), "r"(b0), "r"(b1));
}
__device__ __forceinline__ void mma3(float *d, const uint32_t *ah, const uint32_t *al,
                                     uint32_t bh0, uint32_t bh1,
                                     uint32_t bl0, uint32_t bl1) {
    mma16(d, ah[0], ah[1], ah[2], ah[3], bh0, bh1);
    mma16(d, ah[0], ah[1], ah[2], ah[3], bl0, bl1);
    mma16(d, al[0], al[1], al[2], al[3], bh0, bh1);
}

// fp16 mma (dense GEMMs)
__device__ __forceinline__ void mma16h(float *d,
                                       uint32_t a0, uint32_t a1, uint32_t a2, uint32_t a3,
                                       uint32_t b0, uint32_t b1) {
    asm volatile(
        "mma.sync.aligned.m16n8k16.row.col.f32.f16.f16.f32 "
        "{%0,%1,%2,%3}, {%4,%5,%6,%7}, {%8,%9}, {%0,%1,%2,%3};\n"
        : "+f"(d[0]), "+f"(d[1]), "+f"(d[2]), "+f"(d[3])
        : "r"(a0), "r"(a1), "r"(a2), "r"(a3), "r"(b0), "r"(b1));
}

#define LDSM4(r, addr)                                                       \
    asm volatile("ldmatrix.sync.aligned.m8n8.x4.shared.b16 {%0,%1,%2,%3}, [%4];" \
        : "=r"((r)[0]), "=r"((r)[1]), "=r"((r)[2]), "=r"((r)[3]) : "r"(addr))
#define LDSM4T(r, addr)                                                      \
    asm volatile("ldmatrix.sync.aligned.m8n8.x4.trans.shared.b16 {%0,%1,%2,%3}, [%4];" \
        : "=r"((r)[0]), "=r"((r)[1]), "=r"((r)[2]), "=r"((r)[3]) : "r"(addr))

__device__ __forceinline__ void cpa16(uint32_t dst, const void *src) {
    asm volatile("cp.async.cg.shared.global [%0], [%1], 16;"
                 :: "r"(dst), "l"(src) : "memory");
}
#define CP_COMMIT() asm volatile("cp.async.commit_group;" ::: "memory")
#define CP_WAIT2()  asm volatile("cp.async.wait_group 2;" ::: "memory")
#define CP_WAIT0()  asm volatile("cp.async.wait_group 0;" ::: "memory")

// ---------------------------------------------------------------------------
// Split kernels
// ---------------------------------------------------------------------------
__global__ void __launch_bounds__(256)
split4h(const float4 *__restrict__ x, uint2 *__restrict__ hi, uint2 *__restrict__ lo) {
    int i = blockIdx.x * 256 + threadIdx.x;
    float4 v = x[i];
    uint32_t h0, l0, h1, l1;
    split_pack_h(v.x, v.y, h0, l0);
    split_pack_h(v.z, v.w, h1, l1);
    hi[i] = make_uint2(h0, h1);
    lo[i] = make_uint2(l0, l1);
}
__global__ void __launch_bounds__(256)
round4h(const float4 *__restrict__ x, uint2 *__restrict__ hi) {
    int i = blockIdx.x * 256 + threadIdx.x;
    float4 v = x[i];
    hi[i] = make_uint2(round_pack_h(v.x, v.y), round_pack_h(v.z, v.w));
}

// ---------------------------------------------------------------------------
// GEMM: C = A @ B + bias, fp16 split-A x2 (A = ah + al exact, B fp16-rounded).
// CTA tile 128m x 256n, 512 threads = 16 warps (2 wm x 8 wn), warp tile 64x32.
// 4-stage cp.async; stage = AH 10240 | AL 10240 | BH 16384 = 36864 B.
// MODE 1: QKV epilogue -> split bf16 q/k/v (Q pre-scaled) | MODE 0: fp32 out.
// ---------------------------------------------------------------------------
#define STG_BYTES 36864
#define OFF_AH 0
#define OFF_AL 10240
#define OFF_BH 20480
#define GEMM_SMEM (4 * STG_BYTES)

template <int MODE>
__global__ void __launch_bounds__(512)
gemm_ldsm(const uint16_t *__restrict__ Ah, const uint16_t *__restrict__ Al,
          const uint16_t *__restrict__ Bh,
          const float *__restrict__ bias, float *__restrict__ Cout,
          int M, int N, int K) {
    extern __shared__ char smc[];
    const uint32_t sbase = smem_u32(smc);

    const int tid  = threadIdx.x;
    const int lane = tid & 31;
    const int warp = tid >> 5;
    const int wm   = warp >> 3;      // 0..1
    const int wn   = warp & 7;       // 0..7
    const int m0   = blockIdx.y * 128;
    const int n0   = blockIdx.x * 256;
    const int g    = lane >> 2;
    const int q4   = lane & 3;

    float acc[4][4][4];
#pragma unroll
    for (int i = 0; i < 4; i++)
#pragma unroll
        for (int j = 0; j < 4; j++)
#pragma unroll
            for (int e = 0; e < 4; e++) acc[i][j][e] = 0.f;

    auto issue = [&](int s) {
        const uint32_t sb = sbase + (s & 3) * STG_BYTES;
        const int kb = s << 5;
        // A: 128 rows x 4 chunks = 512 ids (hi+lo per id)
        {
            int row = tid >> 2;
            int c   = tid & 3;
            size_t gidx = (size_t)(m0 + row) * K + kb + c * 8;
            uint32_t d = (row * 5 + c) << 4;
            cpa16(sb + OFF_AH + d, Ah + gidx);
            cpa16(sb + OFF_AL + d, Al + gidx);
        }
        // B: 32 k x 32 chunks = 1024 ids (hi only)
#pragma unroll
        for (int i = 0; i < 2; i++) {
            int id = tid + i * 512;
            int k  = id >> 5;
            int c  = id & 31;
            size_t gidx = (size_t)(kb + k) * N + n0 + c * 8;
            uint32_t d = ((k << 5) + (c ^ (k & 7))) << 4;
            cpa16(sb + OFF_BH + d, Bh + gidx);
        }
    };

    auto compute = [&](int s) {
        const uint32_t sb = sbase + (s & 3) * STG_BYTES;
        const int arow = wm * 64 + (lane & 15);
        const int lt16 = lane >> 4;
        const int cbas = wn * 4 + ((lane >> 3) & 1);
#pragma unroll
        for (int kk = 0; kk < 2; kk++) {
            const int ac   = kk * 2 + lt16;
            const int kloc = kk * 16 + (lt16 << 3) + (lane & 7);
            uint32_t ad[4], bd[2];
#pragma unroll
            for (int mt = 0; mt < 4; mt++)
                ad[mt] = sb + OFF_AH + (((arow + mt * 16) * 5 + ac) << 4);
#pragma unroll
            for (int bt = 0; bt < 2; bt++) {
                int c = cbas + bt * 2;
                bd[bt] = sb + OFF_BH + (((kloc << 5) + (c ^ (kloc & 7))) << 4);
            }

            uint32_t ah[4][4], al[4][4], bh[2][4];
#pragma unroll
            for (int mt = 0; mt < 4; mt++) LDSM4(ah[mt], ad[mt]);
#pragma unroll
            for (int bt = 0; bt < 2; bt++) LDSM4T(bh[bt], bd[bt]);

            // ---- pass 1: A_hi x B (16 independent MMAs) ----
#pragma unroll
            for (int bt = 0; bt < 2; bt++)
#pragma unroll
                for (int mt = 0; mt < 4; mt++) {
                    mma16h(acc[mt][2 * bt],     ah[mt][0], ah[mt][1], ah[mt][2], ah[mt][3],
                           bh[bt][0], bh[bt][2]);
                    mma16h(acc[mt][2 * bt + 1], ah[mt][0], ah[mt][1], ah[mt][2], ah[mt][3],
                           bh[bt][1], bh[bt][3]);
                }

#pragma unroll
            for (int mt = 0; mt < 4; mt++)
                LDSM4(al[mt], ad[mt] + (OFF_AL - OFF_AH));

            // ---- pass 2: A_lo x B ----
#pragma unroll
            for (int bt = 0; bt < 2; bt++)
#pragma unroll
                for (int mt = 0; mt < 4; mt++) {
                    mma16h(acc[mt][2 * bt],     al[mt][0], al[mt][1], al[mt][2], al[mt][3],
                           bh[bt][0], bh[bt][2]);
                    mma16h(acc[mt][2 * bt + 1], al[mt][0], al[mt][1], al[mt][2], al[mt][3],
                           bh[bt][1], bh[bt][3]);
                }
        }
    };

    const int S = K >> 5;
    issue(0); CP_COMMIT();
    issue(1); CP_COMMIT();
    issue(2); CP_COMMIT();

    for (int s = 0; s < S; s++) {
        CP_WAIT2();
        __syncthreads();
        compute(s);
        if (s + 3 < S) issue(s + 3);
        CP_COMMIT();
    }

    // ---- epilogue ----
#pragma unroll
    for (int mt = 0; mt < 4; mt++) {
#pragma unroll
        for (int nt = 0; nt < 4; nt++) {
            int row = m0 + wm * 64 + mt * 16 + g;
            int col = n0 + wn * 32 + nt * 8 + (q4 << 1);
            float b0 = bias[col];
            float b1 = bias[col + 1];
            if (MODE == 1) {
                int which = col >> 11;
                int head  = (col >> 7) & 15;
                int dc    = col & 127;
                uint16_t *dh = (which == 0) ? g_qh : ((which == 1) ? g_kh : g_vh);
                uint16_t *dl = (which == 0) ? g_ql : ((which == 1) ? g_kl : g_vl);
                float sc = (which == 0) ? QSCALE : 1.f;
                float v00 = (acc[mt][nt][0] + b0) * sc;
                float v01 = (acc[mt][nt][1] + b1) * sc;
                float v10 = (acc[mt][nt][2] + b0) * sc;
                float v11 = (acc[mt][nt][3] + b1) * sc;
                uint32_t h0, l0, h1, l1;
                split_pack(v00, v01, h0, l0);
                split_pack(v10, v11, h1, l1);
                int bi = row >> 11;
                int si = row & 2047;
                size_t u32i = (((size_t)(bi * NHEAD + head) * SEQ + si) * DHEAD + dc) >> 1;
                ((uint32_t *)dh)[u32i] = h0;
                ((uint32_t *)dl)[u32i] = l0;
                ((uint32_t *)dh)[u32i + 8 * 64] = h1;
                ((uint32_t *)dl)[u32i + 8 * 64] = l1;
            } else {
                float2 v0 = make_float2(acc[mt][nt][0] + b0, acc[mt][nt][1] + b1);
                float2 v1 = make_float2(acc[mt][nt][2] + b0, acc[mt][nt][3] + b1);
                *(float2 *)(Cout + (size_t)row * N + col) = v0;
                *(float2 *)(Cout + (size_t)(row + 8) * N + col) = v1;
            }
        }
    }
}

// ---------------------------------------------------------------------------
// Flash attention (causal), bf16x3, ldmatrix fragments, pure cp.async loads.
// (round-6 compute path; epilogue now emits fp16 splits for the proj GEMM)
// ---------------------------------------------------------------------------
#define FL_QU   (128 * 68)          // u32 per Q array
#define FL_AU   (64 * 68)           // u32 per K/V array (4352)
#define FL_STGU (4 * FL_AU)         // 17408 u32 per stage
#define FLASH_SMEM ((2 * FL_QU + 2 * FL_STGU) * 4)

__global__ void __launch_bounds__(256) flash_causal() {
    extern __shared__ uint32_t smf[];
    const uint32_t sbase = smem_u32(smf);

    const int qt   = (gridDim.x - 1) - blockIdx.x;   // heavy tiles first
    const int h    = blockIdx.y;
    const int b    = blockIdx.z;
    const int tid  = threadIdx.x;
    const int lane = tid & 31;
    const int warp = tid >> 5;
    const int g    = lane >> 2;
    const int q4   = lane & 3;

    const size_t headoff = (size_t)(b * NHEAD + h) * SEQ * DHEAD;
    const uint16_t *Qhg = g_qh + headoff;
    const uint16_t *Qlg = g_ql + headoff;
    const uint16_t *Khg = g_kh + headoff;
    const uint16_t *Klg = g_kl + headoff;
    const uint16_t *Vhg = g_vh + headoff;
    const uint16_t *Vlg = g_vl + headoff;

    const int qr0 = qt * 128;

    // ---- Q tile: 2 arrays x (128 rows x 16 chunks) = 4096 cp.async chunks ----
#pragma unroll
    for (int i = 0; i < 16; i++) {
        int id  = tid + i * 256;       // 0..4095
        int arr = id >> 11;            // 0 = Qh, 1 = Ql
        int rc  = id & 2047;
        int row = rc >> 4;             // 0..127
        int c   = rc & 15;
        const uint16_t *src = (arr == 0 ? Qhg : Qlg) +
                              (size_t)(qr0 + row) * DHEAD + c * 8;
        cpa16(sbase + ((arr * FL_QU + row * 68 + c * 4) << 2), src);
    }

    auto copy_kv = [&](int kv0, int st) {
        const uint32_t stb = sbase + ((2 * FL_QU + st * FL_STGU) << 2);
#pragma unroll
        for (int i = 0; i < 16; i++) {
            int id  = tid + i * 256;
            int arr = id >> 10;                      // 0 Kh, 1 Kl, 2 Vh, 3 Vl
            int rc  = id & 1023;
            int row = rc >> 4;
            int c   = rc & 15;
            const uint16_t *base =
                (arr == 0) ? Khg : (arr == 1) ? Klg : (arr == 2) ? Vhg : Vlg;
            cpa16(stb + ((arr * FL_AU + row * 68 + c * 4) << 2),
                  base + (size_t)(kv0 + row) * DHEAD + c * 8);
        }
    };

    float Oacc[16][4];
#pragma unroll
    for (int i = 0; i < 16; i++)
#pragma unroll
        for (int e = 0; e < 4; e++) Oacc[i][e] = 0.f;
    float m_i[2] = {-1e30f, -1e30f};
    float l_i[2] = {0.f, 0.f};

    const int wr0   = warp * 16;
    const int grow0 = qr0 + wr0;
    const int jmax  = 2 * qt + 1;

    copy_kv(0, 0);
    CP_COMMIT();

    const int lt = lane >> 3;      // tile index within x4 (0..3)
    const int lr = lane & 7;       // row within tile

    for (int j = 0; j <= jmax; j++) {
        const int kv0 = j * 64;
        CP_WAIT0();
        __syncthreads();
        if (j + 1 <= jmax) {
            copy_kv((j + 1) * 64, (j + 1) & 1);
            CP_COMMIT();
        }

        if (kv0 <= grow0 + 15) {
            const uint32_t QH = sbase;
            const uint32_t KH = sbase + ((2 * FL_QU + (j & 1) * FL_STGU) << 2);
            const uint32_t VH = KH + ((2 * FL_AU) << 2);

            // ---- S = Q @ K^T : 16 x 64 per warp ----
            float sacc[8][4];
#pragma unroll
            for (int nt = 0; nt < 8; nt++)
#pragma unroll
                for (int e = 0; e < 4; e++) sacc[nt][e] = 0.f;

#pragma unroll
            for (int kk = 0; kk < 8; kk++) {
                uint32_t ah[4], al[4];
                {
                    uint32_t qrow = wr0 + ((lt & 1) << 3) + lr;
                    uint32_t qc   = (kk << 1) + (lt >> 1);
                    uint32_t qa   = QH + ((qrow * 68 + qc * 4) << 2);
                    LDSM4(ah, qa);
                    LDSM4(al, qa + (FL_QU << 2));
                }
#pragma unroll
                for (int i = 0; i < 4; i++) {
                    uint32_t krow = (i << 4) + ((lt >> 1) << 3) + lr;
                    uint32_t kc   = (kk << 1) + (lt & 1);
                    uint32_t ka   = KH + ((krow * 68 + kc * 4) << 2);
                    uint32_t bh[4], bl[4];
                    LDSM4(bh, ka);
                    LDSM4(bl, ka + (FL_AU << 2));
                    mma3(sacc[2 * i],     ah, al, bh[0], bh[1], bl[0], bl[1]);
                    mma3(sacc[2 * i + 1], ah, al, bh[2], bh[3], bl[2], bl[3]);
                }
            }

            // ---- causal mask (near diagonal only) ----
            if (kv0 + 63 > grow0) {
                const int r0 = grow0 + g;
#pragma unroll
                for (int nt = 0; nt < 8; nt++) {
                    int c0 = kv0 + nt * 8 + (q4 << 1);
                    if (c0 > r0)         sacc[nt][0] = -1e30f;
                    if (c0 + 1 > r0)     sacc[nt][1] = -1e30f;
                    if (c0 > r0 + 8)     sacc[nt][2] = -1e30f;
                    if (c0 + 1 > r0 + 8) sacc[nt][3] = -1e30f;
                }
            }

            // ---- streaming softmax ----
            float rmax0 = -1e30f, rmax1 = -1e30f;
#pragma unroll
            for (int nt = 0; nt < 8; nt++) {
                rmax0 = fmaxf(rmax0, fmaxf(sacc[nt][0], sacc[nt][1]));
                rmax1 = fmaxf(rmax1, fmaxf(sacc[nt][2], sacc[nt][3]));
            }
            rmax0 = fmaxf(rmax0, __shfl_xor_sync(0xffffffffu, rmax0, 1));
            rmax0 = fmaxf(rmax0, __shfl_xor_sync(0xffffffffu, rmax0, 2));
            rmax1 = fmaxf(rmax1, __shfl_xor_sync(0xffffffffu, rmax1, 1));
            rmax1 = fmaxf(rmax1, __shfl_xor_sync(0xffffffffu, rmax1, 2));

            float mn0 = fmaxf(m_i[0], rmax0);
            float mn1 = fmaxf(m_i[1], rmax1);
            float alpha0 = __expf(m_i[0] - mn0);
            float alpha1 = __expf(m_i[1] - mn1);

            float rs0 = 0.f, rs1 = 0.f;
#pragma unroll
            for (int nt = 0; nt < 8; nt++) {
                sacc[nt][0] = __expf(sacc[nt][0] - mn0);
                sacc[nt][1] = __expf(sacc[nt][1] - mn0);
                sacc[nt][2] = __expf(sacc[nt][2] - mn1);
                sacc[nt][3] = __expf(sacc[nt][3] - mn1);
                rs0 += sacc[nt][0] + sacc[nt][1];
                rs1 += sacc[nt][2] + sacc[nt][3];
            }
            rs0 += __shfl_xor_sync(0xffffffffu, rs0, 1);
            rs0 += __shfl_xor_sync(0xffffffffu, rs0, 2);
            rs1 += __shfl_xor_sync(0xffffffffu, rs1, 1);
            rs1 += __shfl_xor_sync(0xffffffffu, rs1, 2);

            l_i[0] = l_i[0] * alpha0 + rs0;
            l_i[1] = l_i[1] * alpha1 + rs1;
            m_i[0] = mn0;
            m_i[1] = mn1;

#pragma unroll
            for (int nt = 0; nt < 16; nt++) {
                Oacc[nt][0] *= alpha0; Oacc[nt][1] *= alpha0;
                Oacc[nt][2] *= alpha1; Oacc[nt][3] *= alpha1;
            }

            // ---- O += P @ V (P in regs; V frags via trans ldmatrix) ----
#pragma unroll
            for (int c = 0; c < 4; c++) {
                uint32_t ph[4], pl[4];
                split_pack(sacc[2 * c][0],     sacc[2 * c][1],     ph[0], pl[0]);
                split_pack(sacc[2 * c][2],     sacc[2 * c][3],     ph[1], pl[1]);
                split_pack(sacc[2 * c + 1][0], sacc[2 * c + 1][1], ph[2], pl[2]);
                split_pack(sacc[2 * c + 1][2], sacc[2 * c + 1][3], ph[3], pl[3]);
#pragma unroll
                for (int i = 0; i < 8; i++) {
                    uint32_t srow = (c << 4) + ((lt & 1) << 3) + lr;
                    uint32_t dc   = (i << 1) + (lt >> 1);
                    uint32_t va   = VH + ((srow * 68 + dc * 4) << 2);
                    uint32_t vh[4], vl[4];
                    LDSM4T(vh, va);
                    LDSM4T(vl, va + (FL_AU << 2));
                    mma3(Oacc[2 * i],     ph, pl, vh[0], vh[1], vl[0], vl[1]);
                    mma3(Oacc[2 * i + 1], ph, pl, vh[2], vh[3], vl[2], vl[3]);
                }
            }
        }
        __syncthreads();
    }

    // ---- epilogue: normalize, fp16-split, write hi/lo attn (for fp16 proj) ----
    const float inv0 = 1.f / l_i[0];
    const float inv1 = 1.f / l_i[1];
    const int   s0   = qr0 + wr0 + g;
    const size_t base0 = ((size_t)(b * SEQ) + s0) * (HID / 2) + h * 64;
#pragma unroll
    for (int nt = 0; nt < 16; nt++) {
        float o00 = Oacc[nt][0] * inv0, o01 = Oacc[nt][1] * inv0;
        float o10 = Oacc[nt][2] * inv1, o11 = Oacc[nt][3] * inv1;
        uint32_t h0, l0, h1, l1;
        split_pack_h(o00, o01, h0, l0);
        split_pack_h(o10, o11, h1, l1);
        size_t ci = base0 + nt * 4 + q4;
        ((uint32_t *)g_ath)[ci] = h0;
        ((uint32_t *)g_atl)[ci] = l0;
        ((uint32_t *)g_ath)[ci + 8 * (HID / 2)] = h1;
        ((uint32_t *)g_atl)[ci + 8 * (HID / 2)] = l1;
    }
}

// ---------------------------------------------------------------------------
// kernel_launch
// ---------------------------------------------------------------------------
extern "C" void kernel_launch(void *const *d_in, const int *in_sizes, int n_in,
                              void *d_out, int out_size) {
    (void)in_sizes; (void)n_in; (void)out_size;
    const float *hs     = (const float *)d_in[0];
    const float *w_attn = (const float *)d_in[1];
    const float *b_attn = (const float *)d_in[2];
    const float *w_proj = (const float *)d_in[3];
    const float *b_proj = (const float *)d_in[4];
    float *out = (float *)d_out;

    cudaFuncSetAttribute(gemm_ldsm<1>,
                         cudaFuncAttributeMaxDynamicSharedMemorySize, GEMM_SMEM);
    cudaFuncSetAttribute(gemm_ldsm<0>,
                         cudaFuncAttributeMaxDynamicSharedMemorySize, GEMM_SMEM);
    cudaFuncSetAttribute(flash_causal,
                         cudaFuncAttributeMaxDynamicSharedMemorySize, FLASH_SMEM);

    uint16_t *hidh, *hidl, *wah, *wph, *ath, *atl;
    cudaGetSymbolAddress((void **)&hidh, g_hidh);
    cudaGetSymbolAddress((void **)&hidl, g_hidl);
    cudaGetSymbolAddress((void **)&wah,  g_wah);
    cudaGetSymbolAddress((void **)&wph,  g_wph);
    cudaGetSymbolAddress((void **)&ath,  g_ath);
    cudaGetSymbolAddress((void **)&atl,  g_atl);

    // 0) pre-convert inputs: hidden -> fp16 split; weights -> fp16 rounded
    split4h<<<(MTOT * HID) / 1024, 256>>>((const float4 *)hs,
                                          (uint2 *)hidh, (uint2 *)hidl);
    round4h<<<(HID * NQKV) / 1024, 256>>>((const float4 *)w_attn, (uint2 *)wah);
    round4h<<<(HID * HID) / 1024, 256>>>((const float4 *)w_proj, (uint2 *)wph);

    // 1) QKV projection -> split bf16 q/k/v (Q pre-scaled)
    gemm_ldsm<1><<<dim3(NQKV / 256, MTOT / 128), 512, GEMM_SMEM>>>(
        hidh, hidl, wah, b_attn, nullptr, MTOT, NQKV, HID);

    // 2) causal flash attention -> fp16 split attn (g_ath/g_atl)
    flash_causal<<<dim3(SEQ / 128, NHEAD, BB), 256, FLASH_SMEM>>>();

    // 3) output projection -> d_out
    gemm_ldsm<0><<<dim3(HID / 256, MTOT / 128), 512, GEMM_SMEM>>>(
        ath, atl, wph, b_proj, out, MTOT, HID, HID);
}

// round 10
// speedup vs baseline: 1.4472x; 1.1168x over previous
#include <cuda_runtime.h>
#include <cstdint>

// Problem constants (fixed by the reference)
#define BB    2
#define SEQ   2048
#define HID   2048
#define NHEAD 16
#define DHEAD 128
#define MTOT  (BB * SEQ)      // 4096
#define NQKV  (3 * HID)       // 6144
#define QSCALE 0.088388347648318447f

// ---------------------------------------------------------------------------
// Device scratch (all 16B-aligned for cp.async / vector access)
// ---------------------------------------------------------------------------
__device__ __align__(128) uint16_t g_qh[(size_t)BB * NHEAD * SEQ * DHEAD];  // fp16 hi
__device__ __align__(128) uint16_t g_ql[(size_t)BB * NHEAD * SEQ * DHEAD];  // fp16 lo
__device__ __align__(128) uint16_t g_kh[(size_t)BB * NHEAD * SEQ * DHEAD];  // fp16
__device__ __align__(128) uint16_t g_vh[(size_t)BB * NHEAD * SEQ * DHEAD];  // fp16

__device__ __align__(128) uint16_t g_hidh[(size_t)MTOT * HID];   // fp16 split hi
__device__ __align__(128) uint16_t g_hidl[(size_t)MTOT * HID];   // fp16 split lo
__device__ __align__(128) uint16_t g_wah[(size_t)HID * NQKV];    // fp16 rounded
__device__ __align__(128) uint16_t g_wph[(size_t)HID * HID];     // fp16 rounded
__device__ __align__(128) uint16_t g_ath[(size_t)MTOT * HID];    // fp16 split hi
__device__ __align__(128) uint16_t g_atl[(size_t)MTOT * HID];    // fp16 split lo

// ---------------------------------------------------------------------------
// Helpers
// ---------------------------------------------------------------------------
// fp16 split: h = {fp16(x0) lo16, fp16(x1) hi16}, l = residuals in fp16
__device__ __forceinline__ void split_pack_h(float x0, float x1,
                                             uint32_t &h, uint32_t &l) {
    asm("cvt.rn.f16x2.f32 %0, %1, %2;" : "=r"(h) : "f"(x1), "f"(x0));
    float h0f, h1f;
    asm("{ .reg .b16 a, b;\n\t"
        "  mov.b32 {a, b}, %2;\n\t"
        "  cvt.f32.f16 %0, a;\n\t"
        "  cvt.f32.f16 %1, b; }"
        : "=f"(h0f), "=f"(h1f) : "r"(h));
    asm("cvt.rn.f16x2.f32 %0, %1, %2;" : "=r"(l) : "f"(x1 - h1f), "f"(x0 - h0f));
}
__device__ __forceinline__ uint32_t round_pack_h(float x0, float x1) {
    uint32_t h;
    asm("cvt.rn.f16x2.f32 %0, %1, %2;" : "=r"(h) : "f"(x1), "f"(x0));
    return h;
}

__device__ __forceinline__ uint32_t smem_u32(const void *p) {
    uint32_t a;
    asm("{ .reg .u64 t; cvta.to.shared.u64 t, %1; cvt.u32.u64 %0, t; }"
        : "=r"(a) : "l"(p));
    return a;
}

// fp16 mma
__device__ __forceinline__ void mma16h(float *d,
                                       uint32_t a0, uint32_t a1, uint32_t a2, uint32_t a3,
                                       uint32_t b0, uint32_t b1) {
    asm volatile(
        "mma.sync.aligned.m16n8k16.row.col.f32.f16.f16.f32 "
        "{%0,%1,%2,%3}, {%4,%5,%6,%7}, {%8,%9}, {%0,%1,%2,%3};\n"
        : "+f"(d[0]), "+f"(d[1]), "+f"(d[2]), "+f"(d[3])
        : "r"(a0), "r"(a1), "r"(a2), "r"(a3), "r"(b0), "r"(b1));
}

#define LDSM4(r, addr)                                                       \
    asm volatile("ldmatrix.sync.aligned.m8n8.x4.shared.b16 {%0,%1,%2,%3}, [%4];" \
        : "=r"((r)[0]), "=r"((r)[1]), "=r"((r)[2]), "=r"((r)[3]) : "r"(addr))
#define LDSM4T(r, addr)                                                      \
    asm volatile("ldmatrix.sync.aligned.m8n8.x4.trans.shared.b16 {%0,%1,%2,%3}, [%4];" \
        : "=r"((r)[0]), "=r"((r)[1]), "=r"((r)[2]), "=r"((r)[3]) : "r"(addr))

__device__ __forceinline__ void cpa16(uint32_t dst, const void *src) {
    asm volatile("cp.async.cg.shared.global [%0], [%1], 16;"
                 :: "r"(dst), "l"(src) : "memory");
}
#define CP_COMMIT() asm volatile("cp.async.commit_group;" ::: "memory")
#define CP_WAIT2()  asm volatile("cp.async.wait_group 2;" ::: "memory")
#define CP_WAIT0()  asm volatile("cp.async.wait_group 0;" ::: "memory")

// ---------------------------------------------------------------------------
// Split kernels
// ---------------------------------------------------------------------------
__global__ void __launch_bounds__(256)
split4h(const float4 *__restrict__ x, uint2 *__restrict__ hi, uint2 *__restrict__ lo) {
    int i = blockIdx.x * 256 + threadIdx.x;
    float4 v = x[i];
    uint32_t h0, l0, h1, l1;
    split_pack_h(v.x, v.y, h0, l0);
    split_pack_h(v.z, v.w, h1, l1);
    hi[i] = make_uint2(h0, h1);
    lo[i] = make_uint2(l0, l1);
}
__global__ void __launch_bounds__(256)
round4h(const float4 *__restrict__ x, uint2 *__restrict__ hi) {
    int i = blockIdx.x * 256 + threadIdx.x;
    float4 v = x[i];
    hi[i] = make_uint2(round_pack_h(v.x, v.y), round_pack_h(v.z, v.w));
}

// ---------------------------------------------------------------------------
// GEMM: C = A @ B + bias, fp16 split-A x2 (A = ah + al exact, B fp16-rounded).
// CTA tile 128m x 256n, 512 threads = 16 warps (2 wm x 8 wn), warp tile 64x32.
// 4-stage cp.async; stage = AH 10240 | AL 10240 | BH 16384 = 36864 B.
// MODE 1: QKV epilogue -> fp16-split Q (pre-scaled), fp16 K/V | MODE 0: fp32.
// ---------------------------------------------------------------------------
#define STG_BYTES 36864
#define OFF_AH 0
#define OFF_AL 10240
#define OFF_BH 20480
#define GEMM_SMEM (4 * STG_BYTES)

template <int MODE>
__global__ void __launch_bounds__(512)
gemm_ldsm(const uint16_t *__restrict__ Ah, const uint16_t *__restrict__ Al,
          const uint16_t *__restrict__ Bh,
          const float *__restrict__ bias, float *__restrict__ Cout,
          int M, int N, int K) {
    extern __shared__ char smc[];
    const uint32_t sbase = smem_u32(smc);

    const int tid  = threadIdx.x;
    const int lane = tid & 31;
    const int warp = tid >> 5;
    const int wm   = warp >> 3;      // 0..1
    const int wn   = warp & 7;       // 0..7
    const int m0   = blockIdx.y * 128;
    const int n0   = blockIdx.x * 256;
    const int g    = lane >> 2;
    const int q4   = lane & 3;

    float acc[4][4][4];
#pragma unroll
    for (int i = 0; i < 4; i++)
#pragma unroll
        for (int j = 0; j < 4; j++)
#pragma unroll
            for (int e = 0; e < 4; e++) acc[i][j][e] = 0.f;

    auto issue = [&](int s) {
        const uint32_t sb = sbase + (s & 3) * STG_BYTES;
        const int kb = s << 5;
        {
            int row = tid >> 2;
            int c   = tid & 3;
            size_t gidx = (size_t)(m0 + row) * K + kb + c * 8;
            uint32_t d = (row * 5 + c) << 4;
            cpa16(sb + OFF_AH + d, Ah + gidx);
            cpa16(sb + OFF_AL + d, Al + gidx);
        }
#pragma unroll
        for (int i = 0; i < 2; i++) {
            int id = tid + i * 512;
            int k  = id >> 5;
            int c  = id & 31;
            size_t gidx = (size_t)(kb + k) * N + n0 + c * 8;
            uint32_t d = ((k << 5) + (c ^ (k & 7))) << 4;
            cpa16(sb + OFF_BH + d, Bh + gidx);
        }
    };

    auto compute = [&](int s) {
        const uint32_t sb = sbase + (s & 3) * STG_BYTES;
        const int arow = wm * 64 + (lane & 15);
        const int lt16 = lane >> 4;
        const int cbas = wn * 4 + ((lane >> 3) & 1);
#pragma unroll
        for (int kk = 0; kk < 2; kk++) {
            const int ac   = kk * 2 + lt16;
            const int kloc = kk * 16 + (lt16 << 3) + (lane & 7);
            uint32_t ad[4], bd[2];
#pragma unroll
            for (int mt = 0; mt < 4; mt++)
                ad[mt] = sb + OFF_AH + (((arow + mt * 16) * 5 + ac) << 4);
#pragma unroll
            for (int bt = 0; bt < 2; bt++) {
                int c = cbas + bt * 2;
                bd[bt] = sb + OFF_BH + (((kloc << 5) + (c ^ (kloc & 7))) << 4);
            }

            uint32_t ah[4][4], al[4][4], bh[2][4];
#pragma unroll
            for (int mt = 0; mt < 4; mt++) LDSM4(ah[mt], ad[mt]);
#pragma unroll
            for (int bt = 0; bt < 2; bt++) LDSM4T(bh[bt], bd[bt]);

            // ---- pass 1: A_hi x B ----
#pragma unroll
            for (int bt = 0; bt < 2; bt++)
#pragma unroll
                for (int mt = 0; mt < 4; mt++) {
                    mma16h(acc[mt][2 * bt],     ah[mt][0], ah[mt][1], ah[mt][2], ah[mt][3],
                           bh[bt][0], bh[bt][2]);
                    mma16h(acc[mt][2 * bt + 1], ah[mt][0], ah[mt][1], ah[mt][2], ah[mt][3],
                           bh[bt][1], bh[bt][3]);
                }

#pragma unroll
            for (int mt = 0; mt < 4; mt++)
                LDSM4(al[mt], ad[mt] + (OFF_AL - OFF_AH));

            // ---- pass 2: A_lo x B ----
#pragma unroll
            for (int bt = 0; bt < 2; bt++)
#pragma unroll
                for (int mt = 0; mt < 4; mt++) {
                    mma16h(acc[mt][2 * bt],     al[mt][0], al[mt][1], al[mt][2], al[mt][3],
                           bh[bt][0], bh[bt][2]);
                    mma16h(acc[mt][2 * bt + 1], al[mt][0], al[mt][1], al[mt][2], al[mt][3],
                           bh[bt][1], bh[bt][3]);
                }
        }
    };

    const int S = K >> 5;
    issue(0); CP_COMMIT();
    issue(1); CP_COMMIT();
    issue(2); CP_COMMIT();

    for (int s = 0; s < S; s++) {
        CP_WAIT2();
        __syncthreads();
        compute(s);
        if (s + 3 < S) issue(s + 3);
        CP_COMMIT();
    }

    // ---- epilogue ----
#pragma unroll
    for (int mt = 0; mt < 4; mt++) {
#pragma unroll
        for (int nt = 0; nt < 4; nt++) {
            int row = m0 + wm * 64 + mt * 16 + g;
            int col = n0 + wn * 32 + nt * 8 + (q4 << 1);
            float b0 = bias[col];
            float b1 = bias[col + 1];
            if (MODE == 1) {
                int which = col >> 11;
                int head  = (col >> 7) & 15;
                int dc    = col & 127;
                int bi = row >> 11;
                int si = row & 2047;
                size_t u32i = (((size_t)(bi * NHEAD + head) * SEQ + si) * DHEAD + dc) >> 1;
                if (which == 0) {
                    float v00 = (acc[mt][nt][0] + b0) * QSCALE;
                    float v01 = (acc[mt][nt][1] + b1) * QSCALE;
                    float v10 = (acc[mt][nt][2] + b0) * QSCALE;
                    float v11 = (acc[mt][nt][3] + b1) * QSCALE;
                    uint32_t h0, l0, h1, l1;
                    split_pack_h(v00, v01, h0, l0);
                    split_pack_h(v10, v11, h1, l1);
                    ((uint32_t *)g_qh)[u32i] = h0;
                    ((uint32_t *)g_ql)[u32i] = l0;
                    ((uint32_t *)g_qh)[u32i + 8 * 64] = h1;
                    ((uint32_t *)g_ql)[u32i + 8 * 64] = l1;
                } else {
                    uint16_t *dh = (which == 1) ? g_kh : g_vh;
                    uint32_t h0 = round_pack_h(acc[mt][nt][0] + b0, acc[mt][nt][1] + b1);
                    uint32_t h1 = round_pack_h(acc[mt][nt][2] + b0, acc[mt][nt][3] + b1);
                    ((uint32_t *)dh)[u32i] = h0;
                    ((uint32_t *)dh)[u32i + 8 * 64] = h1;
                }
            } else {
                float2 v0 = make_float2(acc[mt][nt][0] + b0, acc[mt][nt][1] + b1);
                float2 v1 = make_float2(acc[mt][nt][2] + b0, acc[mt][nt][3] + b1);
                *(float2 *)(Cout + (size_t)row * N + col) = v0;
                *(float2 *)(Cout + (size_t)(row + 8) * N + col) = v1;
            }
        }
    }
}

// ---------------------------------------------------------------------------
// Flash attention (causal), fp16 split-A x2 scheme.
// CTA: 128 Q rows, 8 warps x 16 rows. KV tile 64. d = 128.
// smem u32: Qh[128*68] Ql[128*68] | stage st: K[64*68] V[64*68].
// S = qh@K + ql@K (K fp16-rounded). O += ph@V + pl@V (P split fp16 in regs).
// ---------------------------------------------------------------------------
#define FL_QU   (128 * 68)          // u32 per Q array
#define FL_AU   (64 * 68)           // u32 per K/V array (4352)
#define FL_STGU (2 * FL_AU)         // 8704 u32 per stage
#define FLASH_SMEM ((2 * FL_QU + 2 * FL_STGU) * 4)

__global__ void __launch_bounds__(256) flash_causal() {
    extern __shared__ uint32_t smf[];
    const uint32_t sbase = smem_u32(smf);

    const int qt   = (gridDim.x - 1) - blockIdx.x;   // heavy tiles first
    const int h    = blockIdx.y;
    const int b    = blockIdx.z;
    const int tid  = threadIdx.x;
    const int lane = tid & 31;
    const int warp = tid >> 5;
    const int g    = lane >> 2;
    const int q4   = lane & 3;

    const size_t headoff = (size_t)(b * NHEAD + h) * SEQ * DHEAD;
    const uint16_t *Qhg = g_qh + headoff;
    const uint16_t *Qlg = g_ql + headoff;
    const uint16_t *Khg = g_kh + headoff;
    const uint16_t *Vhg = g_vh + headoff;

    const int qr0 = qt * 128;

    // ---- Q tile: 2 arrays x (128 rows x 16 chunks) = 4096 cp.async chunks ----
#pragma unroll
    for (int i = 0; i < 16; i++) {
        int id  = tid + i * 256;       // 0..4095
        int arr = id >> 11;            // 0 = Qh, 1 = Ql
        int rc  = id & 2047;
        int row = rc >> 4;             // 0..127
        int c   = rc & 15;
        const uint16_t *src = (arr == 0 ? Qhg : Qlg) +
                              (size_t)(qr0 + row) * DHEAD + c * 8;
        cpa16(sbase + ((arr * FL_QU + row * 68 + c * 4) << 2), src);
    }

    auto copy_kv = [&](int kv0, int st) {
        const uint32_t stb = sbase + ((2 * FL_QU + st * FL_STGU) << 2);
#pragma unroll
        for (int i = 0; i < 8; i++) {
            int id  = tid + i * 256;                 // 0..2047
            int arr = id >> 10;                      // 0 = K, 1 = V
            int rc  = id & 1023;
            int row = rc >> 4;
            int c   = rc & 15;
            const uint16_t *base = (arr == 0) ? Khg : Vhg;
            cpa16(stb + ((arr * FL_AU + row * 68 + c * 4) << 2),
                  base + (size_t)(kv0 + row) * DHEAD + c * 8);
        }
    };

    float Oacc[16][4];
#pragma unroll
    for (int i = 0; i < 16; i++)
#pragma unroll
        for (int e = 0; e < 4; e++) Oacc[i][e] = 0.f;
    float m_i[2] = {-1e30f, -1e30f};
    float l_i[2] = {0.f, 0.f};

    const int wr0   = warp * 16;
    const int grow0 = qr0 + wr0;
    const int jmax  = 2 * qt + 1;

    copy_kv(0, 0);
    CP_COMMIT();

    const int lt = lane >> 3;      // tile index within x4 (0..3)
    const int lr = lane & 7;       // row within tile

    for (int j = 0; j <= jmax; j++) {
        const int kv0 = j * 64;
        CP_WAIT0();
        __syncthreads();
        if (j + 1 <= jmax) {
            copy_kv((j + 1) * 64, (j + 1) & 1);
            CP_COMMIT();
        }

        if (kv0 <= grow0 + 15) {
            const uint32_t QH = sbase;
            const uint32_t KH = sbase + ((2 * FL_QU + (j & 1) * FL_STGU) << 2);
            const uint32_t VH = KH + (FL_AU << 2);

            // ---- S = Q @ K^T : 16 x 64 per warp ----
            float sacc[8][4];
#pragma unroll
            for (int nt = 0; nt < 8; nt++)
#pragma unroll
                for (int e = 0; e < 4; e++) sacc[nt][e] = 0.f;

#pragma unroll
            for (int kk = 0; kk < 8; kk++) {
                uint32_t ah[4], al[4], bh[4][4];
                uint32_t qrow = wr0 + ((lt & 1) << 3) + lr;
                uint32_t qc   = (kk << 1) + (lt >> 1);
                uint32_t qa   = QH + ((qrow * 68 + qc * 4) << 2);
                LDSM4(ah, qa);
#pragma unroll
                for (int i = 0; i < 4; i++) {
                    uint32_t krow = (i << 4) + ((lt >> 1) << 3) + lr;
                    uint32_t kc   = (kk << 1) + (lt & 1);
                    LDSM4(bh[i], KH + ((krow * 68 + kc * 4) << 2));
                }
                // pass 1: Q_hi x K (8 independent MMAs)
#pragma unroll
                for (int i = 0; i < 4; i++) {
                    mma16h(sacc[2 * i],     ah[0], ah[1], ah[2], ah[3], bh[i][0], bh[i][1]);
                    mma16h(sacc[2 * i + 1], ah[0], ah[1], ah[2], ah[3], bh[i][2], bh[i][3]);
                }
                LDSM4(al, qa + (FL_QU << 2));
                // pass 2: Q_lo x K
#pragma unroll
                for (int i = 0; i < 4; i++) {
                    mma16h(sacc[2 * i],     al[0], al[1], al[2], al[3], bh[i][0], bh[i][1]);
                    mma16h(sacc[2 * i + 1], al[0], al[1], al[2], al[3], bh[i][2], bh[i][3]);
                }
            }

            // ---- causal mask (near diagonal only) ----
            if (kv0 + 63 > grow0) {
                const int r0 = grow0 + g;
#pragma unroll
                for (int nt = 0; nt < 8; nt++) {
                    int c0 = kv0 + nt * 8 + (q4 << 1);
                    if (c0 > r0)         sacc[nt][0] = -1e30f;
                    if (c0 + 1 > r0)     sacc[nt][1] = -1e30f;
                    if (c0 > r0 + 8)     sacc[nt][2] = -1e30f;
                    if (c0 + 1 > r0 + 8) sacc[nt][3] = -1e30f;
                }
            }

            // ---- streaming softmax ----
            float rmax0 = -1e30f, rmax1 = -1e30f;
#pragma unroll
            for (int nt = 0; nt < 8; nt++) {
                rmax0 = fmaxf(rmax0, fmaxf(sacc[nt][0], sacc[nt][1]));
                rmax1 = fmaxf(rmax1, fmaxf(sacc[nt][2], sacc[nt][3]));
            }
            rmax0 = fmaxf(rmax0, __shfl_xor_sync(0xffffffffu, rmax0, 1));
            rmax0 = fmaxf(rmax0, __shfl_xor_sync(0xffffffffu, rmax0, 2));
            rmax1 = fmaxf(rmax1, __shfl_xor_sync(0xffffffffu, rmax1, 1));
            rmax1 = fmaxf(rmax1, __shfl_xor_sync(0xffffffffu, rmax1, 2));

            float mn0 = fmaxf(m_i[0], rmax0);
            float mn1 = fmaxf(m_i[1], rmax1);
            float alpha0 = __expf(m_i[0] - mn0);
            float alpha1 = __expf(m_i[1] - mn1);

            float rs0 = 0.f, rs1 = 0.f;
#pragma unroll
            for (int nt = 0; nt < 8; nt++) {
                sacc[nt][0] = __expf(sacc[nt][0] - mn0);
                sacc[nt][1] = __expf(sacc[nt][1] - mn0);
                sacc[nt][2] = __expf(sacc[nt][2] - mn1);
                sacc[nt][3] = __expf(sacc[nt][3] - mn1);
                rs0 += sacc[nt][0] + sacc[nt][1];
                rs1 += sacc[nt][2] + sacc[nt][3];
            }
            rs0 += __shfl_xor_sync(0xffffffffu, rs0, 1);
            rs0 += __shfl_xor_sync(0xffffffffu, rs0, 2);
            rs1 += __shfl_xor_sync(0xffffffffu, rs1, 1);
            rs1 += __shfl_xor_sync(0xffffffffu, rs1, 2);

            l_i[0] = l_i[0] * alpha0 + rs0;
            l_i[1] = l_i[1] * alpha1 + rs1;
            m_i[0] = mn0;
            m_i[1] = mn1;

#pragma unroll
            for (int nt = 0; nt < 16; nt++) {
                Oacc[nt][0] *= alpha0; Oacc[nt][1] *= alpha0;
                Oacc[nt][2] *= alpha1; Oacc[nt][3] *= alpha1;
            }

            // ---- O += P @ V (P fp16-split in regs; V fp16 via trans ldmatrix) ----
#pragma unroll
            for (int c = 0; c < 4; c++) {
                uint32_t ph[4], pl[4];
                split_pack_h(sacc[2 * c][0],     sacc[2 * c][1],     ph[0], pl[0]);
                split_pack_h(sacc[2 * c][2],     sacc[2 * c][3],     ph[1], pl[1]);
                split_pack_h(sacc[2 * c + 1][0], sacc[2 * c + 1][1], ph[2], pl[2]);
                split_pack_h(sacc[2 * c + 1][2], sacc[2 * c + 1][3], ph[3], pl[3]);
                const uint32_t srow = (c << 4) + ((lt & 1) << 3) + lr;
#pragma unroll
                for (int half = 0; half < 2; half++) {
                    uint32_t vh[4][4];
#pragma unroll
                    for (int i = 0; i < 4; i++) {
                        uint32_t dc = ((half * 4 + i) << 1) + (lt >> 1);
                        LDSM4T(vh[i], VH + ((srow * 68 + dc * 4) << 2));
                    }
                    // pass 1: P_hi x V (8 independent MMAs)
#pragma unroll
                    for (int i = 0; i < 4; i++) {
                        int o = 2 * (half * 4 + i);
                        mma16h(Oacc[o],     ph[0], ph[1], ph[2], ph[3], vh[i][0], vh[i][1]);
                        mma16h(Oacc[o + 1], ph[0], ph[1], ph[2], ph[3], vh[i][2], vh[i][3]);
                    }
                    // pass 2: P_lo x V
#pragma unroll
                    for (int i = 0; i < 4; i++) {
                        int o = 2 * (half * 4 + i);
                        mma16h(Oacc[o],     pl[0], pl[1], pl[2], pl[3], vh[i][0], vh[i][1]);
                        mma16h(Oacc[o + 1], pl[0], pl[1], pl[2], pl[3], vh[i][2], vh[i][3]);
                    }
                }
            }
        }
        __syncthreads();
    }

    // ---- epilogue: normalize, fp16-split, write hi/lo attn (for fp16 proj) ----
    const float inv0 = 1.f / l_i[0];
    const float inv1 = 1.f / l_i[1];
    const int   s0   = qr0 + wr0 + g;
    const size_t base0 = ((size_t)(b * SEQ) + s0) * (HID / 2) + h * 64;
#pragma unroll
    for (int nt = 0; nt < 16; nt++) {
        float o00 = Oacc[nt][0] * inv0, o01 = Oacc[nt][1] * inv0;
        float o10 = Oacc[nt][2] * inv1, o11 = Oacc[nt][3] * inv1;
        uint32_t h0, l0, h1, l1;
        split_pack_h(o00, o01, h0, l0);
        split_pack_h(o10, o11, h1, l1);
        size_t ci = base0 + nt * 4 + q4;
        ((uint32_t *)g_ath)[ci] = h0;
        ((uint32_t *)g_atl)[ci] = l0;
        ((uint32_t *)g_ath)[ci + 8 * (HID / 2)] = h1;
        ((uint32_t *)g_atl)[ci + 8 * (HID / 2)] = l1;
    }
}

// ---------------------------------------------------------------------------
// kernel_launch
// ---------------------------------------------------------------------------
extern "C" void kernel_launch(void *const *d_in, const int *in_sizes, int n_in,
                              void *d_out, int out_size) {
    (void)in_sizes; (void)n_in; (void)out_size;
    const float *hs     = (const float *)d_in[0];
    const float *w_attn = (const float *)d_in[1];
    const float *b_attn = (const float *)d_in[2];
    const float *w_proj = (const float *)d_in[3];
    const float *b_proj = (const float *)d_in[4];
    float *out = (float *)d_out;

    cudaFuncSetAttribute(gemm_ldsm<1>,
                         cudaFuncAttributeMaxDynamicSharedMemorySize, GEMM_SMEM);
    cudaFuncSetAttribute(gemm_ldsm<0>,
                         cudaFuncAttributeMaxDynamicSharedMemorySize, GEMM_SMEM);
    cudaFuncSetAttribute(flash_causal,
                         cudaFuncAttributeMaxDynamicSharedMemorySize, FLASH_SMEM);

    uint16_t *hidh, *hidl, *wah, *wph, *ath, *atl;
    cudaGetSymbolAddress((void **)&hidh, g_hidh);
    cudaGetSymbolAddress((void **)&hidl, g_hidl);
    cudaGetSymbolAddress((void **)&wah,  g_wah);
    cudaGetSymbolAddress((void **)&wph,  g_wph);
    cudaGetSymbolAddress((void **)&ath,  g_ath);
    cudaGetSymbolAddress((void **)&atl,  g_atl);

    // 0) pre-convert inputs: hidden -> fp16 split; weights -> fp16 rounded
    split4h<<<(MTOT * HID) / 1024, 256>>>((const float4 *)hs,
                                          (uint2 *)hidh, (uint2 *)hidl);
    round4h<<<(HID * NQKV) / 1024, 256>>>((const float4 *)w_attn, (uint2 *)wah);
    round4h<<<(HID * HID) / 1024, 256>>>((const float4 *)w_proj, (uint2 *)wph);

    // 1) QKV projection -> fp16-split Q (pre-scaled), fp16 K/V
    gemm_ldsm<1><<<dim3(NQKV / 256, MTOT / 128), 512, GEMM_SMEM>>>(
        hidh, hidl, wah, b_attn, nullptr, MTOT, NQKV, HID);

    // 2) causal flash attention -> fp16 split attn (g_ath/g_atl)
    flash_causal<<<dim3(SEQ / 128, NHEAD, BB), 256, FLASH_SMEM>>>();

    // 3) output projection -> d_out
    gemm_ldsm<0><<<dim3(HID / 256, MTOT / 128), 512, GEMM_SMEM>>>(
        ath, atl, wph, b_proj, out, MTOT, HID, HID);
}

// round 11
// speedup vs baseline: 1.4671x; 1.0138x over previous
#include <cuda_runtime.h>
#include <cstdint>

// Problem constants (fixed by the reference)
#define BB    2
#define SEQ   2048
#define HID   2048
#define NHEAD 16
#define DHEAD 128
#define MTOT  (BB * SEQ)      // 4096
#define NQKV  (3 * HID)       // 6144
#define QSCALE 0.088388347648318447f

// ---------------------------------------------------------------------------
// Device scratch (all 16B-aligned for cp.async / vector access)
// ---------------------------------------------------------------------------
__device__ __align__(128) uint16_t g_qh[(size_t)BB * NHEAD * SEQ * DHEAD];  // fp16 hi
__device__ __align__(128) uint16_t g_ql[(size_t)BB * NHEAD * SEQ * DHEAD];  // fp16 lo
__device__ __align__(128) uint16_t g_kh[(size_t)BB * NHEAD * SEQ * DHEAD];  // fp16
__device__ __align__(128) uint16_t g_vh[(size_t)BB * NHEAD * SEQ * DHEAD];  // fp16

__device__ __align__(128) uint16_t g_hidh[(size_t)MTOT * HID];   // fp16 split hi
__device__ __align__(128) uint16_t g_hidl[(size_t)MTOT * HID];   // fp16 split lo
__device__ __align__(128) uint16_t g_wah[(size_t)HID * NQKV];    // fp16 rounded
__device__ __align__(128) uint16_t g_wph[(size_t)HID * HID];     // fp16 rounded
__device__ __align__(128) uint16_t g_ath[(size_t)MTOT * HID];    // fp16 split hi
__device__ __align__(128) uint16_t g_atl[(size_t)MTOT * HID];    // fp16 split lo

// ---------------------------------------------------------------------------
// Helpers
// ---------------------------------------------------------------------------
// fp16 split: h = {fp16(x0) lo16, fp16(x1) hi16}, l = residuals in fp16
__device__ __forceinline__ void split_pack_h(float x0, float x1,
                                             uint32_t &h, uint32_t &l) {
    asm("cvt.rn.f16x2.f32 %0, %1, %2;" : "=r"(h) : "f"(x1), "f"(x0));
    float h0f, h1f;
    asm("{ .reg .b16 a, b;\n\t"
        "  mov.b32 {a, b}, %2;\n\t"
        "  cvt.f32.f16 %0, a;\n\t"
        "  cvt.f32.f16 %1, b; }"
        : "=f"(h0f), "=f"(h1f) : "r"(h));
    asm("cvt.rn.f16x2.f32 %0, %1, %2;" : "=r"(l) : "f"(x1 - h1f), "f"(x0 - h0f));
}
__device__ __forceinline__ uint32_t round_pack_h(float x0, float x1) {
    uint32_t h;
    asm("cvt.rn.f16x2.f32 %0, %1, %2;" : "=r"(h) : "f"(x1), "f"(x0));
    return h;
}
__device__ __forceinline__ void h2unpack(uint32_t h, float &x0, float &x1) {
    asm("{ .reg .b16 a, b;\n\t"
        "  mov.b32 {a, b}, %2;\n\t"
        "  cvt.f32.f16 %0, a;\n\t"
        "  cvt.f32.f16 %1, b; }"
        : "=f"(x0), "=f"(x1) : "r"(h));
}

__device__ __forceinline__ uint32_t smem_u32(const void *p) {
    uint32_t a;
    asm("{ .reg .u64 t; cvta.to.shared.u64 t, %1; cvt.u32.u64 %0, t; }"
        : "=r"(a) : "l"(p));
    return a;
}

// fp16 mma, fp32 accumulate
__device__ __forceinline__ void mma16h(float *d,
                                       uint32_t a0, uint32_t a1, uint32_t a2, uint32_t a3,
                                       uint32_t b0, uint32_t b1) {
    asm volatile(
        "mma.sync.aligned.m16n8k16.row.col.f32.f16.f16.f32 "
        "{%0,%1,%2,%3}, {%4,%5,%6,%7}, {%8,%9}, {%0,%1,%2,%3};\n"
        : "+f"(d[0]), "+f"(d[1]), "+f"(d[2]), "+f"(d[3])
        : "r"(a0), "r"(a1), "r"(a2), "r"(a3), "r"(b0), "r"(b1));
}
// fp16 mma, fp16 accumulate (half the D writeback)
__device__ __forceinline__ void mma16hh(uint32_t *d,
                                        uint32_t a0, uint32_t a1, uint32_t a2, uint32_t a3,
                                        uint32_t b0, uint32_t b1) {
    asm volatile(
        "mma.sync.aligned.m16n8k16.row.col.f16.f16.f16.f16 "
        "{%0,%1}, {%2,%3,%4,%5}, {%6,%7}, {%0,%1};\n"
        : "+r"(d[0]), "+r"(d[1])
        : "r"(a0), "r"(a1), "r"(a2), "r"(a3), "r"(b0), "r"(b1));
}

#define LDSM4(r, addr)                                                       \
    asm volatile("ldmatrix.sync.aligned.m8n8.x4.shared.b16 {%0,%1,%2,%3}, [%4];" \
        : "=r"((r)[0]), "=r"((r)[1]), "=r"((r)[2]), "=r"((r)[3]) : "r"(addr))
#define LDSM4T(r, addr)                                                      \
    asm volatile("ldmatrix.sync.aligned.m8n8.x4.trans.shared.b16 {%0,%1,%2,%3}, [%4];" \
        : "=r"((r)[0]), "=r"((r)[1]), "=r"((r)[2]), "=r"((r)[3]) : "r"(addr))

__device__ __forceinline__ void cpa16(uint32_t dst, const void *src) {
    asm volatile("cp.async.cg.shared.global [%0], [%1], 16;"
                 :: "r"(dst), "l"(src) : "memory");
}
#define CP_COMMIT() asm volatile("cp.async.commit_group;" ::: "memory")
#define CP_WAIT2()  asm volatile("cp.async.wait_group 2;" ::: "memory")
#define CP_WAIT0()  asm volatile("cp.async.wait_group 0;" ::: "memory")

// ---------------------------------------------------------------------------
// Split kernels
// ---------------------------------------------------------------------------
__global__ void __launch_bounds__(256)
split4h(const float4 *__restrict__ x, uint2 *__restrict__ hi, uint2 *__restrict__ lo) {
    int i = blockIdx.x * 256 + threadIdx.x;
    float4 v = x[i];
    uint32_t h0, l0, h1, l1;
    split_pack_h(v.x, v.y, h0, l0);
    split_pack_h(v.z, v.w, h1, l1);
    hi[i] = make_uint2(h0, h1);
    lo[i] = make_uint2(l0, l1);
}
__global__ void __launch_bounds__(256)
round4h(const float4 *__restrict__ x, uint2 *__restrict__ hi) {
    int i = blockIdx.x * 256 + threadIdx.x;
    float4 v = x[i];
    hi[i] = make_uint2(round_pack_h(v.x, v.y), round_pack_h(v.z, v.w));
}

// ---------------------------------------------------------------------------
// GEMM: C = A @ B + bias, fp16 split-A x2 (A = ah + al exact, B fp16-rounded).
// Pass 1 (A_hi x B): fp32 accumulate. Pass 2 (A_lo x B): fp16 accumulate
// (correction term ~5e-4 relative; fp16 accum error ~1e-7 of output).
// CTA tile 128m x 256n, 512 threads = 16 warps (2 wm x 8 wn), warp tile 64x32.
// 4-stage cp.async; stage = AH 10240 | AL 10240 | BH 16384 = 36864 B.
// MODE 1: QKV epilogue -> fp16-split Q (pre-scaled), fp16 K/V | MODE 0: fp32.
// ---------------------------------------------------------------------------
#define STG_BYTES 36864
#define OFF_AH 0
#define OFF_AL 10240
#define OFF_BH 20480
#define GEMM_SMEM (4 * STG_BYTES)

template <int MODE>
__global__ void __launch_bounds__(512)
gemm_ldsm(const uint16_t *__restrict__ Ah, const uint16_t *__restrict__ Al,
          const uint16_t *__restrict__ Bh,
          const float *__restrict__ bias, float *__restrict__ Cout,
          int M, int N, int K) {
    extern __shared__ char smc[];
    const uint32_t sbase = smem_u32(smc);

    const int tid  = threadIdx.x;
    const int lane = tid & 31;
    const int warp = tid >> 5;
    const int wm   = warp >> 3;      // 0..1
    const int wn   = warp & 7;       // 0..7
    const int m0   = blockIdx.y * 128;
    const int n0   = blockIdx.x * 256;
    const int g    = lane >> 2;
    const int q4   = lane & 3;

    float acc[4][4][4];
    uint32_t acc16[4][4][2];
#pragma unroll
    for (int i = 0; i < 4; i++)
#pragma unroll
        for (int j = 0; j < 4; j++) {
#pragma unroll
            for (int e = 0; e < 4; e++) acc[i][j][e] = 0.f;
            acc16[i][j][0] = 0u;
            acc16[i][j][1] = 0u;
        }

    auto issue = [&](int s) {
        const uint32_t sb = sbase + (s & 3) * STG_BYTES;
        const int kb = s << 5;
        {
            int row = tid >> 2;
            int c   = tid & 3;
            size_t gidx = (size_t)(m0 + row) * K + kb + c * 8;
            uint32_t d = (row * 5 + c) << 4;
            cpa16(sb + OFF_AH + d, Ah + gidx);
            cpa16(sb + OFF_AL + d, Al + gidx);
        }
#pragma unroll
        for (int i = 0; i < 2; i++) {
            int id = tid + i * 512;
            int k  = id >> 5;
            int c  = id & 31;
            size_t gidx = (size_t)(kb + k) * N + n0 + c * 8;
            uint32_t d = ((k << 5) + (c ^ (k & 7))) << 4;
            cpa16(sb + OFF_BH + d, Bh + gidx);
        }
    };

    auto compute = [&](int s) {
        const uint32_t sb = sbase + (s & 3) * STG_BYTES;
        const int arow = wm * 64 + (lane & 15);
        const int lt16 = lane >> 4;
        const int cbas = wn * 4 + ((lane >> 3) & 1);
#pragma unroll
        for (int kk = 0; kk < 2; kk++) {
            const int ac   = kk * 2 + lt16;
            const int kloc = kk * 16 + (lt16 << 3) + (lane & 7);
            uint32_t ad[4], bd[2];
#pragma unroll
            for (int mt = 0; mt < 4; mt++)
                ad[mt] = sb + OFF_AH + (((arow + mt * 16) * 5 + ac) << 4);
#pragma unroll
            for (int bt = 0; bt < 2; bt++) {
                int c = cbas + bt * 2;
                bd[bt] = sb + OFF_BH + (((kloc << 5) + (c ^ (kloc & 7))) << 4);
            }

            uint32_t ah[4][4], al[4][4], bh[2][4];
#pragma unroll
            for (int mt = 0; mt < 4; mt++) LDSM4(ah[mt], ad[mt]);
#pragma unroll
            for (int bt = 0; bt < 2; bt++) LDSM4T(bh[bt], bd[bt]);

            // ---- pass 1: A_hi x B, fp32 accumulate ----
#pragma unroll
            for (int bt = 0; bt < 2; bt++)
#pragma unroll
                for (int mt = 0; mt < 4; mt++) {
                    mma16h(acc[mt][2 * bt],     ah[mt][0], ah[mt][1], ah[mt][2], ah[mt][3],
                           bh[bt][0], bh[bt][2]);
                    mma16h(acc[mt][2 * bt + 1], ah[mt][0], ah[mt][1], ah[mt][2], ah[mt][3],
                           bh[bt][1], bh[bt][3]);
                }

#pragma unroll
            for (int mt = 0; mt < 4; mt++)
                LDSM4(al[mt], ad[mt] + (OFF_AL - OFF_AH));

            // ---- pass 2: A_lo x B, fp16 accumulate ----
#pragma unroll
            for (int bt = 0; bt < 2; bt++)
#pragma unroll
                for (int mt = 0; mt < 4; mt++) {
                    mma16hh(acc16[mt][2 * bt],     al[mt][0], al[mt][1], al[mt][2], al[mt][3],
                            bh[bt][0], bh[bt][2]);
                    mma16hh(acc16[mt][2 * bt + 1], al[mt][0], al[mt][1], al[mt][2], al[mt][3],
                            bh[bt][1], bh[bt][3]);
                }
        }
    };

    const int S = K >> 5;
    issue(0); CP_COMMIT();
    issue(1); CP_COMMIT();
    issue(2); CP_COMMIT();

    for (int s = 0; s < S; s++) {
        CP_WAIT2();
        __syncthreads();
        compute(s);
        if (s + 3 < S) issue(s + 3);
        CP_COMMIT();
    }

    // ---- epilogue: fold fp16 lo accumulators into fp32, add bias, store ----
#pragma unroll
    for (int mt = 0; mt < 4; mt++) {
#pragma unroll
        for (int nt = 0; nt < 4; nt++) {
            float l0, l1, l2, l3;
            h2unpack(acc16[mt][nt][0], l0, l1);
            h2unpack(acc16[mt][nt][1], l2, l3);
            float c0 = acc[mt][nt][0] + l0;
            float c1 = acc[mt][nt][1] + l1;
            float c2 = acc[mt][nt][2] + l2;
            float c3 = acc[mt][nt][3] + l3;

            int row = m0 + wm * 64 + mt * 16 + g;
            int col = n0 + wn * 32 + nt * 8 + (q4 << 1);
            float b0 = bias[col];
            float b1 = bias[col + 1];
            if (MODE == 1) {
                int which = col >> 11;
                int head  = (col >> 7) & 15;
                int dc    = col & 127;
                int bi = row >> 11;
                int si = row & 2047;
                size_t u32i = (((size_t)(bi * NHEAD + head) * SEQ + si) * DHEAD + dc) >> 1;
                if (which == 0) {
                    float v00 = (c0 + b0) * QSCALE;
                    float v01 = (c1 + b1) * QSCALE;
                    float v10 = (c2 + b0) * QSCALE;
                    float v11 = (c3 + b1) * QSCALE;
                    uint32_t h0, lo0, h1, lo1;
                    split_pack_h(v00, v01, h0, lo0);
                    split_pack_h(v10, v11, h1, lo1);
                    ((uint32_t *)g_qh)[u32i] = h0;
                    ((uint32_t *)g_ql)[u32i] = lo0;
                    ((uint32_t *)g_qh)[u32i + 8 * 64] = h1;
                    ((uint32_t *)g_ql)[u32i + 8 * 64] = lo1;
                } else {
                    uint16_t *dh = (which == 1) ? g_kh : g_vh;
                    uint32_t h0 = round_pack_h(c0 + b0, c1 + b1);
                    uint32_t h1 = round_pack_h(c2 + b0, c3 + b1);
                    ((uint32_t *)dh)[u32i] = h0;
                    ((uint32_t *)dh)[u32i + 8 * 64] = h1;
                }
            } else {
                float2 v0 = make_float2(c0 + b0, c1 + b1);
                float2 v1 = make_float2(c2 + b0, c3 + b1);
                *(float2 *)(Cout + (size_t)row * N + col) = v0;
                *(float2 *)(Cout + (size_t)(row + 8) * N + col) = v1;
            }
        }
    }
}

// ---------------------------------------------------------------------------
// Flash attention (causal), fp16 split-A x2 scheme. (round-10 version)
// CTA: 128 Q rows, 8 warps x 16 rows. KV tile 64. d = 128.
// smem u32: Qh[128*68] Ql[128*68] | stage st: K[64*68] V[64*68].
// S = qh@K + ql@K (K fp16-rounded). O += ph@V + pl@V (P split fp16 in regs).
// ---------------------------------------------------------------------------
#define FL_QU   (128 * 68)          // u32 per Q array
#define FL_AU   (64 * 68)           // u32 per K/V array (4352)
#define FL_STGU (2 * FL_AU)         // 8704 u32 per stage
#define FLASH_SMEM ((2 * FL_QU + 2 * FL_STGU) * 4)

__global__ void __launch_bounds__(256) flash_causal() {
    extern __shared__ uint32_t smf[];
    const uint32_t sbase = smem_u32(smf);

    const int qt   = (gridDim.x - 1) - blockIdx.x;   // heavy tiles first
    const int h    = blockIdx.y;
    const int b    = blockIdx.z;
    const int tid  = threadIdx.x;
    const int lane = tid & 31;
    const int warp = tid >> 5;
    const int g    = lane >> 2;
    const int q4   = lane & 3;

    const size_t headoff = (size_t)(b * NHEAD + h) * SEQ * DHEAD;
    const uint16_t *Qhg = g_qh + headoff;
    const uint16_t *Qlg = g_ql + headoff;
    const uint16_t *Khg = g_kh + headoff;
    const uint16_t *Vhg = g_vh + headoff;

    const int qr0 = qt * 128;

    // ---- Q tile: 2 arrays x (128 rows x 16 chunks) = 4096 cp.async chunks ----
#pragma unroll
    for (int i = 0; i < 16; i++) {
        int id  = tid + i * 256;       // 0..4095
        int arr = id >> 11;            // 0 = Qh, 1 = Ql
        int rc  = id & 2047;
        int row = rc >> 4;             // 0..127
        int c   = rc & 15;
        const uint16_t *src = (arr == 0 ? Qhg : Qlg) +
                              (size_t)(qr0 + row) * DHEAD + c * 8;
        cpa16(sbase + ((arr * FL_QU + row * 68 + c * 4) << 2), src);
    }

    auto copy_kv = [&](int kv0, int st) {
        const uint32_t stb = sbase + ((2 * FL_QU + st * FL_STGU) << 2);
#pragma unroll
        for (int i = 0; i < 8; i++) {
            int id  = tid + i * 256;                 // 0..2047
            int arr = id >> 10;                      // 0 = K, 1 = V
            int rc  = id & 1023;
            int row = rc >> 4;
            int c   = rc & 15;
            const uint16_t *base = (arr == 0) ? Khg : Vhg;
            cpa16(stb + ((arr * FL_AU + row * 68 + c * 4) << 2),
                  base + (size_t)(kv0 + row) * DHEAD + c * 8);
        }
    };

    float Oacc[16][4];
#pragma unroll
    for (int i = 0; i < 16; i++)
#pragma unroll
        for (int e = 0; e < 4; e++) Oacc[i][e] = 0.f;
    float m_i[2] = {-1e30f, -1e30f};
    float l_i[2] = {0.f, 0.f};

    const int wr0   = warp * 16;
    const int grow0 = qr0 + wr0;
    const int jmax  = 2 * qt + 1;

    copy_kv(0, 0);
    CP_COMMIT();

    const int lt = lane >> 3;      // tile index within x4 (0..3)
    const int lr = lane & 7;       // row within tile

    for (int j = 0; j <= jmax; j++) {
        const int kv0 = j * 64;
        CP_WAIT0();
        __syncthreads();
        if (j + 1 <= jmax) {
            copy_kv((j + 1) * 64, (j + 1) & 1);
            CP_COMMIT();
        }

        if (kv0 <= grow0 + 15) {
            const uint32_t QH = sbase;
            const uint32_t KH = sbase + ((2 * FL_QU + (j & 1) * FL_STGU) << 2);
            const uint32_t VH = KH + (FL_AU << 2);

            // ---- S = Q @ K^T : 16 x 64 per warp ----
            float sacc[8][4];
#pragma unroll
            for (int nt = 0; nt < 8; nt++)
#pragma unroll
                for (int e = 0; e < 4; e++) sacc[nt][e] = 0.f;

#pragma unroll
            for (int kk = 0; kk < 8; kk++) {
                uint32_t ah[4], al[4], bh[4][4];
                uint32_t qrow = wr0 + ((lt & 1) << 3) + lr;
                uint32_t qc   = (kk << 1) + (lt >> 1);
                uint32_t qa   = QH + ((qrow * 68 + qc * 4) << 2);
                LDSM4(ah, qa);
#pragma unroll
                for (int i = 0; i < 4; i++) {
                    uint32_t krow = (i << 4) + ((lt >> 1) << 3) + lr;
                    uint32_t kc   = (kk << 1) + (lt & 1);
                    LDSM4(bh[i], KH + ((krow * 68 + kc * 4) << 2));
                }
                // pass 1: Q_hi x K
#pragma unroll
                for (int i = 0; i < 4; i++) {
                    mma16h(sacc[2 * i],     ah[0], ah[1], ah[2], ah[3], bh[i][0], bh[i][1]);
                    mma16h(sacc[2 * i + 1], ah[0], ah[1], ah[2], ah[3], bh[i][2], bh[i][3]);
                }
                LDSM4(al, qa + (FL_QU << 2));
                // pass 2: Q_lo x K
#pragma unroll
                for (int i = 0; i < 4; i++) {
                    mma16h(sacc[2 * i],     al[0], al[1], al[2], al[3], bh[i][0], bh[i][1]);
                    mma16h(sacc[2 * i + 1], al[0], al[1], al[2], al[3], bh[i][2], bh[i][3]);
                }
            }

            // ---- causal mask (near diagonal only) ----
            if (kv0 + 63 > grow0) {
                const int r0 = grow0 + g;
#pragma unroll
                for (int nt = 0; nt < 8; nt++) {
                    int c0 = kv0 + nt * 8 + (q4 << 1);
                    if (c0 > r0)         sacc[nt][0] = -1e30f;
                    if (c0 + 1 > r0)     sacc[nt][1] = -1e30f;
                    if (c0 > r0 + 8)     sacc[nt][2] = -1e30f;
                    if (c0 + 1 > r0 + 8) sacc[nt][3] = -1e30f;
                }
            }

            // ---- streaming softmax ----
            float rmax0 = -1e30f, rmax1 = -1e30f;
#pragma unroll
            for (int nt = 0; nt < 8; nt++) {
                rmax0 = fmaxf(rmax0, fmaxf(sacc[nt][0], sacc[nt][1]));
                rmax1 = fmaxf(rmax1, fmaxf(sacc[nt][2], sacc[nt][3]));
            }
            rmax0 = fmaxf(rmax0, __shfl_xor_sync(0xffffffffu, rmax0, 1));
            rmax0 = fmaxf(rmax0, __shfl_xor_sync(0xffffffffu, rmax0, 2));
            rmax1 = fmaxf(rmax1, __shfl_xor_sync(0xffffffffu, rmax1, 1));
            rmax1 = fmaxf(rmax1, __shfl_xor_sync(0xffffffffu, rmax1, 2));

            float mn0 = fmaxf(m_i[0], rmax0);
            float mn1 = fmaxf(m_i[1], rmax1);
            float alpha0 = __expf(m_i[0] - mn0);
            float alpha1 = __expf(m_i[1] - mn1);

            float rs0 = 0.f, rs1 = 0.f;
#pragma unroll
            for (int nt = 0; nt < 8; nt++) {
                sacc[nt][0] = __expf(sacc[nt][0] - mn0);
                sacc[nt][1] = __expf(sacc[nt][1] - mn0);
                sacc[nt][2] = __expf(sacc[nt][2] - mn1);
                sacc[nt][3] = __expf(sacc[nt][3] - mn1);
                rs0 += sacc[nt][0] + sacc[nt][1];
                rs1 += sacc[nt][2] + sacc[nt][3];
            }
            rs0 += __shfl_xor_sync(0xffffffffu, rs0, 1);
            rs0 += __shfl_xor_sync(0xffffffffu, rs0, 2);
            rs1 += __shfl_xor_sync(0xffffffffu, rs1, 1);
            rs1 += __shfl_xor_sync(0xffffffffu, rs1, 2);

            l_i[0] = l_i[0] * alpha0 + rs0;
            l_i[1] = l_i[1] * alpha1 + rs1;
            m_i[0] = mn0;
            m_i[1] = mn1;

#pragma unroll
            for (int nt = 0; nt < 16; nt++) {
                Oacc[nt][0] *= alpha0; Oacc[nt][1] *= alpha0;
                Oacc[nt][2] *= alpha1; Oacc[nt][3] *= alpha1;
            }

            // ---- O += P @ V (P fp16-split in regs; V fp16 via trans ldmatrix) ----
#pragma unroll
            for (int c = 0; c < 4; c++) {
                uint32_t ph[4], pl[4];
                split_pack_h(sacc[2 * c][0],     sacc[2 * c][1],     ph[0], pl[0]);
                split_pack_h(sacc[2 * c][2],     sacc[2 * c][3],     ph[1], pl[1]);
                split_pack_h(sacc[2 * c + 1][0], sacc[2 * c + 1][1], ph[2], pl[2]);
                split_pack_h(sacc[2 * c + 1][2], sacc[2 * c + 1][3], ph[3], pl[3]);
                const uint32_t srow = (c << 4) + ((lt & 1) << 3) + lr;
#pragma unroll
                for (int half = 0; half < 2; half++) {
                    uint32_t vh[4][4];
#pragma unroll
                    for (int i = 0; i < 4; i++) {
                        uint32_t dc = ((half * 4 + i) << 1) + (lt >> 1);
                        LDSM4T(vh[i], VH + ((srow * 68 + dc * 4) << 2));
                    }
                    // pass 1: P_hi x V
#pragma unroll
                    for (int i = 0; i < 4; i++) {
                        int o = 2 * (half * 4 + i);
                        mma16h(Oacc[o],     ph[0], ph[1], ph[2], ph[3], vh[i][0], vh[i][1]);
                        mma16h(Oacc[o + 1], ph[0], ph[1], ph[2], ph[3], vh[i][2], vh[i][3]);
                    }
                    // pass 2: P_lo x V
#pragma unroll
                    for (int i = 0; i < 4; i++) {
                        int o = 2 * (half * 4 + i);
                        mma16h(Oacc[o],     pl[0], pl[1], pl[2], pl[3], vh[i][0], vh[i][1]);
                        mma16h(Oacc[o + 1], pl[0], pl[1], pl[2], pl[3], vh[i][2], vh[i][3]);
                    }
                }
            }
        }
        __syncthreads();
    }

    // ---- epilogue: normalize, fp16-split, write hi/lo attn (for fp16 proj) ----
    const float inv0 = 1.f / l_i[0];
    const float inv1 = 1.f / l_i[1];
    const int   s0   = qr0 + wr0 + g;
    const size_t base0 = ((size_t)(b * SEQ) + s0) * (HID / 2) + h * 64;
#pragma unroll
    for (int nt = 0; nt < 16; nt++) {
        float o00 = Oacc[nt][0] * inv0, o01 = Oacc[nt][1] * inv0;
        float o10 = Oacc[nt][2] * inv1, o11 = Oacc[nt][3] * inv1;
        uint32_t h0, l0, h1, l1;
        split_pack_h(o00, o01, h0, l0);
        split_pack_h(o10, o11, h1, l1);
        size_t ci = base0 + nt * 4 + q4;
        ((uint32_t *)g_ath)[ci] = h0;
        ((uint32_t *)g_atl)[ci] = l0;
        ((uint32_t *)g_ath)[ci + 8 * (HID / 2)] = h1;
        ((uint32_t *)g_atl)[ci + 8 * (HID / 2)] = l1;
    }
}

// ---------------------------------------------------------------------------
// kernel_launch
// ---------------------------------------------------------------------------
extern "C" void kernel_launch(void *const *d_in, const int *in_sizes, int n_in,
                              void *d_out, int out_size) {
    (void)in_sizes; (void)n_in; (void)out_size;
    const float *hs     = (const float *)d_in[0];
    const float *w_attn = (const float *)d_in[1];
    const float *b_attn = (const float *)d_in[2];
    const float *w_proj = (const float *)d_in[3];
    const float *b_proj = (const float *)d_in[4];
    float *out = (float *)d_out;

    cudaFuncSetAttribute(gemm_ldsm<1>,
                         cudaFuncAttributeMaxDynamicSharedMemorySize, GEMM_SMEM);
    cudaFuncSetAttribute(gemm_ldsm<0>,
                         cudaFuncAttributeMaxDynamicSharedMemorySize, GEMM_SMEM);
    cudaFuncSetAttribute(flash_causal,
                         cudaFuncAttributeMaxDynamicSharedMemorySize, FLASH_SMEM);

    uint16_t *hidh, *hidl, *wah, *wph, *ath, *atl;
    cudaGetSymbolAddress((void **)&hidh, g_hidh);
    cudaGetSymbolAddress((void **)&hidl, g_hidl);
    cudaGetSymbolAddress((void **)&wah,  g_wah);
    cudaGetSymbolAddress((void **)&wph,  g_wph);
    cudaGetSymbolAddress((void **)&ath,  g_ath);
    cudaGetSymbolAddress((void **)&atl,  g_atl);

    // 0) pre-convert inputs: hidden -> fp16 split; weights -> fp16 rounded
    split4h<<<(MTOT * HID) / 1024, 256>>>((const float4 *)hs,
                                          (uint2 *)hidh, (uint2 *)hidl);
    round4h<<<(HID * NQKV) / 1024, 256>>>((const float4 *)w_attn, (uint2 *)wah);
    round4h<<<(HID * HID) / 1024, 256>>>((const float4 *)w_proj, (uint2 *)wph);

    // 1) QKV projection -> fp16-split Q (pre-scaled), fp16 K/V
    gemm_ldsm<1><<<dim3(NQKV / 256, MTOT / 128), 512, GEMM_SMEM>>>(
        hidh, hidl, wah, b_attn, nullptr, MTOT, NQKV, HID);

    // 2) causal flash attention -> fp16 split attn (g_ath/g_atl)
    flash_causal<<<dim3(SEQ / 128, NHEAD, BB), 256, FLASH_SMEM>>>();

    // 3) output projection -> d_out
    gemm_ldsm<0><<<dim3(HID / 256, MTOT / 128), 512, GEMM_SMEM>>>(
        ath, atl, wph, b_proj, out, MTOT, HID, HID);
}

// round 12
// speedup vs baseline: 1.7169x; 1.1703x over previous
#include <cuda_runtime.h>
#include <cstdint>

// Problem constants (fixed by the reference)
#define BB    2
#define SEQ   2048
#define HID   2048
#define NHEAD 16
#define DHEAD 128
#define MTOT  (BB * SEQ)      // 4096
#define NQKV  (3 * HID)       // 6144
#define QSCALE 0.088388347648318447f

// ---------------------------------------------------------------------------
// Device scratch (all 16B-aligned for cp.async / vector access)
// ---------------------------------------------------------------------------
__device__ __align__(128) uint16_t g_qh[(size_t)BB * NHEAD * SEQ * DHEAD];  // fp16 hi
__device__ __align__(128) uint16_t g_ql[(size_t)BB * NHEAD * SEQ * DHEAD];  // fp16 lo
__device__ __align__(128) uint16_t g_kh[(size_t)BB * NHEAD * SEQ * DHEAD];  // fp16
__device__ __align__(128) uint16_t g_vh[(size_t)BB * NHEAD * SEQ * DHEAD];  // fp16

__device__ __align__(128) uint16_t g_hidh[(size_t)MTOT * HID];   // fp16 split hi
__device__ __align__(128) uint16_t g_hidl[(size_t)MTOT * HID];   // fp16 split lo
__device__ __align__(128) uint16_t g_wah[(size_t)HID * NQKV];    // fp16 rounded
__device__ __align__(128) uint16_t g_wph[(size_t)HID * HID];     // fp16 rounded
__device__ __align__(128) uint16_t g_ath[(size_t)MTOT * HID];    // fp16 split hi
__device__ __align__(128) uint16_t g_atl[(size_t)MTOT * HID];    // fp16 split lo

// ---------------------------------------------------------------------------
// Helpers
// ---------------------------------------------------------------------------
// fp16 split: h = {fp16(x0) lo16, fp16(x1) hi16}, l = residuals in fp16
__device__ __forceinline__ void split_pack_h(float x0, float x1,
                                             uint32_t &h, uint32_t &l) {
    asm("cvt.rn.f16x2.f32 %0, %1, %2;" : "=r"(h) : "f"(x1), "f"(x0));
    float h0f, h1f;
    asm("{ .reg .b16 a, b;\n\t"
        "  mov.b32 {a, b}, %2;\n\t"
        "  cvt.f32.f16 %0, a;\n\t"
        "  cvt.f32.f16 %1, b; }"
        : "=f"(h0f), "=f"(h1f) : "r"(h));
    asm("cvt.rn.f16x2.f32 %0, %1, %2;" : "=r"(l) : "f"(x1 - h1f), "f"(x0 - h0f));
}
__device__ __forceinline__ uint32_t round_pack_h(float x0, float x1) {
    uint32_t h;
    asm("cvt.rn.f16x2.f32 %0, %1, %2;" : "=r"(h) : "f"(x1), "f"(x0));
    return h;
}
__device__ __forceinline__ void h2unpack(uint32_t h, float &x0, float &x1) {
    asm("{ .reg .b16 a, b;\n\t"
        "  mov.b32 {a, b}, %2;\n\t"
        "  cvt.f32.f16 %0, a;\n\t"
        "  cvt.f32.f16 %1, b; }"
        : "=f"(x0), "=f"(x1) : "r"(h));
}

__device__ __forceinline__ uint32_t smem_u32(const void *p) {
    uint32_t a;
    asm("{ .reg .u64 t; cvta.to.shared.u64 t, %1; cvt.u32.u64 %0, t; }"
        : "=r"(a) : "l"(p));
    return a;
}

// fp16 mma, fp32 accumulate
__device__ __forceinline__ void mma16h(float *d,
                                       uint32_t a0, uint32_t a1, uint32_t a2, uint32_t a3,
                                       uint32_t b0, uint32_t b1) {
    asm volatile(
        "mma.sync.aligned.m16n8k16.row.col.f32.f16.f16.f32 "
        "{%0,%1,%2,%3}, {%4,%5,%6,%7}, {%8,%9}, {%0,%1,%2,%3};\n"
        : "+f"(d[0]), "+f"(d[1]), "+f"(d[2]), "+f"(d[3])
        : "r"(a0), "r"(a1), "r"(a2), "r"(a3), "r"(b0), "r"(b1));
}
// fp16 mma, fp16 accumulate (lo-correction term)
__device__ __forceinline__ void mma16hh(uint32_t *d,
                                        uint32_t a0, uint32_t a1, uint32_t a2, uint32_t a3,
                                        uint32_t b0, uint32_t b1) {
    asm volatile(
        "mma.sync.aligned.m16n8k16.row.col.f16.f16.f16.f16 "
        "{%0,%1}, {%2,%3,%4,%5}, {%6,%7}, {%0,%1};\n"
        : "+r"(d[0]), "+r"(d[1])
        : "r"(a0), "r"(a1), "r"(a2), "r"(a3), "r"(b0), "r"(b1));
}

#define LDSM4(r, addr)                                                       \
    asm volatile("ldmatrix.sync.aligned.m8n8.x4.shared.b16 {%0,%1,%2,%3}, [%4];" \
        : "=r"((r)[0]), "=r"((r)[1]), "=r"((r)[2]), "=r"((r)[3]) : "r"(addr))
#define LDSM4T(r, addr)                                                      \
    asm volatile("ldmatrix.sync.aligned.m8n8.x4.trans.shared.b16 {%0,%1,%2,%3}, [%4];" \
        : "=r"((r)[0]), "=r"((r)[1]), "=r"((r)[2]), "=r"((r)[3]) : "r"(addr))

__device__ __forceinline__ void cpa16(uint32_t dst, const void *src) {
    asm volatile("cp.async.cg.shared.global [%0], [%1], 16;"
                 :: "r"(dst), "l"(src) : "memory");
}
#define CP_COMMIT() asm volatile("cp.async.commit_group;" ::: "memory")
#define CP_WAIT2()  asm volatile("cp.async.wait_group 2;" ::: "memory")
#define CP_WAIT0()  asm volatile("cp.async.wait_group 0;" ::: "memory")

// ---------------------------------------------------------------------------
// Split kernels
// ---------------------------------------------------------------------------
__global__ void __launch_bounds__(256)
split4h(const float4 *__restrict__ x, uint2 *__restrict__ hi, uint2 *__restrict__ lo) {
    int i = blockIdx.x * 256 + threadIdx.x;
    float4 v = x[i];
    uint32_t h0, l0, h1, l1;
    split_pack_h(v.x, v.y, h0, l0);
    split_pack_h(v.z, v.w, h1, l1);
    hi[i] = make_uint2(h0, h1);
    lo[i] = make_uint2(l0, l1);
}
__global__ void __launch_bounds__(256)
round4h(const float4 *__restrict__ x, uint2 *__restrict__ hi) {
    int i = blockIdx.x * 256 + threadIdx.x;
    float4 v = x[i];
    hi[i] = make_uint2(round_pack_h(v.x, v.y), round_pack_h(v.z, v.w));
}

// ---------------------------------------------------------------------------
// GEMM: C = A @ B + bias, fp16 split-A x2 (A = ah + al exact, B fp16-rounded).
// Pass 1 (A_hi x B): fp32 accumulate. Pass 2 (A_lo x B): fp16 accumulate.
// MODE 1 K/V column tiles (n0 >= 2048) SKIP pass 2 entirely: the epilogue
// rounds K/V to a single fp16, which discards the lo-pass correction anyway.
// CTA tile 128m x 256n, 512 threads = 16 warps (2 wm x 8 wn), warp tile 64x32.
// 4-stage cp.async; stage = AH 10240 | AL 10240 | BH 16384 = 36864 B.
// MODE 1: QKV epilogue -> fp16-split Q (pre-scaled), fp16 K/V | MODE 0: fp32.
// ---------------------------------------------------------------------------
#define STG_BYTES 36864
#define OFF_AH 0
#define OFF_AL 10240
#define OFF_BH 20480
#define GEMM_SMEM (4 * STG_BYTES)

template <int MODE>
__global__ void __launch_bounds__(512)
gemm_ldsm(const uint16_t *__restrict__ Ah, const uint16_t *__restrict__ Al,
          const uint16_t *__restrict__ Bh,
          const float *__restrict__ bias, float *__restrict__ Cout,
          int M, int N, int K) {
    extern __shared__ char smc[];
    const uint32_t sbase = smem_u32(smc);

    const int tid  = threadIdx.x;
    const int lane = tid & 31;
    const int warp = tid >> 5;
    const int wm   = warp >> 3;      // 0..1
    const int wn   = warp & 7;       // 0..7
    const int m0   = blockIdx.y * 128;
    const int n0   = blockIdx.x * 256;
    const int g    = lane >> 2;
    const int q4   = lane & 3;

    // K/V outputs are fp16-rounded in the epilogue: skip the lo correction.
    const bool need_lo = (MODE == 0) || (n0 < HID);

    float acc[4][4][4];
    uint32_t acc16[4][4][2];
#pragma unroll
    for (int i = 0; i < 4; i++)
#pragma unroll
        for (int j = 0; j < 4; j++) {
#pragma unroll
            for (int e = 0; e < 4; e++) acc[i][j][e] = 0.f;
            acc16[i][j][0] = 0u;
            acc16[i][j][1] = 0u;
        }

    auto issue = [&](int s) {
        const uint32_t sb = sbase + (s & 3) * STG_BYTES;
        const int kb = s << 5;
        {
            int row = tid >> 2;
            int c   = tid & 3;
            size_t gidx = (size_t)(m0 + row) * K + kb + c * 8;
            uint32_t d = (row * 5 + c) << 4;
            cpa16(sb + OFF_AH + d, Ah + gidx);
            if (need_lo) cpa16(sb + OFF_AL + d, Al + gidx);
        }
#pragma unroll
        for (int i = 0; i < 2; i++) {
            int id = tid + i * 512;
            int k  = id >> 5;
            int c  = id & 31;
            size_t gidx = (size_t)(kb + k) * N + n0 + c * 8;
            uint32_t d = ((k << 5) + (c ^ (k & 7))) << 4;
            cpa16(sb + OFF_BH + d, Bh + gidx);
        }
    };

    auto compute = [&](int s) {
        const uint32_t sb = sbase + (s & 3) * STG_BYTES;
        const int arow = wm * 64 + (lane & 15);
        const int lt16 = lane >> 4;
        const int cbas = wn * 4 + ((lane >> 3) & 1);
#pragma unroll
        for (int kk = 0; kk < 2; kk++) {
            const int ac   = kk * 2 + lt16;
            const int kloc = kk * 16 + (lt16 << 3) + (lane & 7);
            uint32_t ad[4], bd[2];
#pragma unroll
            for (int mt = 0; mt < 4; mt++)
                ad[mt] = sb + OFF_AH + (((arow + mt * 16) * 5 + ac) << 4);
#pragma unroll
            for (int bt = 0; bt < 2; bt++) {
                int c = cbas + bt * 2;
                bd[bt] = sb + OFF_BH + (((kloc << 5) + (c ^ (kloc & 7))) << 4);
            }

            uint32_t ah[4][4], al[4][4], bh[2][4];
#pragma unroll
            for (int mt = 0; mt < 4; mt++) LDSM4(ah[mt], ad[mt]);
#pragma unroll
            for (int bt = 0; bt < 2; bt++) LDSM4T(bh[bt], bd[bt]);

            // ---- pass 1: A_hi x B, fp32 accumulate ----
#pragma unroll
            for (int bt = 0; bt < 2; bt++)
#pragma unroll
                for (int mt = 0; mt < 4; mt++) {
                    mma16h(acc[mt][2 * bt],     ah[mt][0], ah[mt][1], ah[mt][2], ah[mt][3],
                           bh[bt][0], bh[bt][2]);
                    mma16h(acc[mt][2 * bt + 1], ah[mt][0], ah[mt][1], ah[mt][2], ah[mt][3],
                           bh[bt][1], bh[bt][3]);
                }

            if (need_lo) {
#pragma unroll
                for (int mt = 0; mt < 4; mt++)
                    LDSM4(al[mt], ad[mt] + (OFF_AL - OFF_AH));

                // ---- pass 2: A_lo x B, fp16 accumulate ----
#pragma unroll
                for (int bt = 0; bt < 2; bt++)
#pragma unroll
                    for (int mt = 0; mt < 4; mt++) {
                        mma16hh(acc16[mt][2 * bt],     al[mt][0], al[mt][1], al[mt][2], al[mt][3],
                                bh[bt][0], bh[bt][2]);
                        mma16hh(acc16[mt][2 * bt + 1], al[mt][0], al[mt][1], al[mt][2], al[mt][3],
                                bh[bt][1], bh[bt][3]);
                    }
            }
        }
    };

    const int S = K >> 5;
    issue(0); CP_COMMIT();
    issue(1); CP_COMMIT();
    issue(2); CP_COMMIT();

    for (int s = 0; s < S; s++) {
        CP_WAIT2();
        __syncthreads();
        compute(s);
        if (s + 3 < S) issue(s + 3);
        CP_COMMIT();
    }

    // ---- epilogue: fold fp16 lo accumulators into fp32, add bias, store ----
#pragma unroll
    for (int mt = 0; mt < 4; mt++) {
#pragma unroll
        for (int nt = 0; nt < 4; nt++) {
            float l0, l1, l2, l3;
            h2unpack(acc16[mt][nt][0], l0, l1);
            h2unpack(acc16[mt][nt][1], l2, l3);
            float c0 = acc[mt][nt][0] + l0;
            float c1 = acc[mt][nt][1] + l1;
            float c2 = acc[mt][nt][2] + l2;
            float c3 = acc[mt][nt][3] + l3;

            int row = m0 + wm * 64 + mt * 16 + g;
            int col = n0 + wn * 32 + nt * 8 + (q4 << 1);
            float b0 = bias[col];
            float b1 = bias[col + 1];
            if (MODE == 1) {
                int which = col >> 11;
                int head  = (col >> 7) & 15;
                int dc    = col & 127;
                int bi = row >> 11;
                int si = row & 2047;
                size_t u32i = (((size_t)(bi * NHEAD + head) * SEQ + si) * DHEAD + dc) >> 1;
                if (which == 0) {
                    float v00 = (c0 + b0) * QSCALE;
                    float v01 = (c1 + b1) * QSCALE;
                    float v10 = (c2 + b0) * QSCALE;
                    float v11 = (c3 + b1) * QSCALE;
                    uint32_t h0, lo0, h1, lo1;
                    split_pack_h(v00, v01, h0, lo0);
                    split_pack_h(v10, v11, h1, lo1);
                    ((uint32_t *)g_qh)[u32i] = h0;
                    ((uint32_t *)g_ql)[u32i] = lo0;
                    ((uint32_t *)g_qh)[u32i + 8 * 64] = h1;
                    ((uint32_t *)g_ql)[u32i + 8 * 64] = lo1;
                } else {
                    uint16_t *dh = (which == 1) ? g_kh : g_vh;
                    uint32_t h0 = round_pack_h(c0 + b0, c1 + b1);
                    uint32_t h1 = round_pack_h(c2 + b0, c3 + b1);
                    ((uint32_t *)dh)[u32i] = h0;
                    ((uint32_t *)dh)[u32i + 8 * 64] = h1;
                }
            } else {
                float2 v0 = make_float2(c0 + b0, c1 + b1);
                float2 v1 = make_float2(c2 + b0, c3 + b1);
                *(float2 *)(Cout + (size_t)row * N + col) = v0;
                *(float2 *)(Cout + (size_t)(row + 8) * N + col) = v1;
            }
        }
    }
}

// ---------------------------------------------------------------------------
// Flash attention (causal), fp16 split-A x2 scheme. (round-10 version)
// CTA: 128 Q rows, 8 warps x 16 rows. KV tile 64. d = 128.
// smem u32: Qh[128*68] Ql[128*68] | stage st: K[64*68] V[64*68].
// S = qh@K + ql@K (K fp16-rounded). O += ph@V + pl@V (P split fp16 in regs).
// ---------------------------------------------------------------------------
#define FL_QU   (128 * 68)          // u32 per Q array
#define FL_AU   (64 * 68)           // u32 per K/V array (4352)
#define FL_STGU (2 * FL_AU)         // 8704 u32 per stage
#define FLASH_SMEM ((2 * FL_QU + 2 * FL_STGU) * 4)

__global__ void __launch_bounds__(256) flash_causal() {
    extern __shared__ uint32_t smf[];
    const uint32_t sbase = smem_u32(smf);

    const int qt   = (gridDim.x - 1) - blockIdx.x;   // heavy tiles first
    const int h    = blockIdx.y;
    const int b    = blockIdx.z;
    const int tid  = threadIdx.x;
    const int lane = tid & 31;
    const int warp = tid >> 5;
    const int g    = lane >> 2;
    const int q4   = lane & 3;

    const size_t headoff = (size_t)(b * NHEAD + h) * SEQ * DHEAD;
    const uint16_t *Qhg = g_qh + headoff;
    const uint16_t *Qlg = g_ql + headoff;
    const uint16_t *Khg = g_kh + headoff;
    const uint16_t *Vhg = g_vh + headoff;

    const int qr0 = qt * 128;

    // ---- Q tile: 2 arrays x (128 rows x 16 chunks) = 4096 cp.async chunks ----
#pragma unroll
    for (int i = 0; i < 16; i++) {
        int id  = tid + i * 256;       // 0..4095
        int arr = id >> 11;            // 0 = Qh, 1 = Ql
        int rc  = id & 2047;
        int row = rc >> 4;             // 0..127
        int c   = rc & 15;
        const uint16_t *src = (arr == 0 ? Qhg : Qlg) +
                              (size_t)(qr0 + row) * DHEAD + c * 8;
        cpa16(sbase + ((arr * FL_QU + row * 68 + c * 4) << 2), src);
    }

    auto copy_kv = [&](int kv0, int st) {
        const uint32_t stb = sbase + ((2 * FL_QU + st * FL_STGU) << 2);
#pragma unroll
        for (int i = 0; i < 8; i++) {
            int id  = tid + i * 256;                 // 0..2047
            int arr = id >> 10;                      // 0 = K, 1 = V
            int rc  = id & 1023;
            int row = rc >> 4;
            int c   = rc & 15;
            const uint16_t *base = (arr == 0) ? Khg : Vhg;
            cpa16(stb + ((arr * FL_AU + row * 68 + c * 4) << 2),
                  base + (size_t)(kv0 + row) * DHEAD + c * 8);
        }
    };

    float Oacc[16][4];
#pragma unroll
    for (int i = 0; i < 16; i++)
#pragma unroll
        for (int e = 0; e < 4; e++) Oacc[i][e] = 0.f;
    float m_i[2] = {-1e30f, -1e30f};
    float l_i[2] = {0.f, 0.f};

    const int wr0   = warp * 16;
    const int grow0 = qr0 + wr0;
    const int jmax  = 2 * qt + 1;

    copy_kv(0, 0);
    CP_COMMIT();

    const int lt = lane >> 3;      // tile index within x4 (0..3)
    const int lr = lane & 7;       // row within tile

    for (int j = 0; j <= jmax; j++) {
        const int kv0 = j * 64;
        CP_WAIT0();
        __syncthreads();
        if (j + 1 <= jmax) {
            copy_kv((j + 1) * 64, (j + 1) & 1);
            CP_COMMIT();
        }

        if (kv0 <= grow0 + 15) {
            const uint32_t QH = sbase;
            const uint32_t KH = sbase + ((2 * FL_QU + (j & 1) * FL_STGU) << 2);
            const uint32_t VH = KH + (FL_AU << 2);

            // ---- S = Q @ K^T : 16 x 64 per warp ----
            float sacc[8][4];
#pragma unroll
            for (int nt = 0; nt < 8; nt++)
#pragma unroll
                for (int e = 0; e < 4; e++) sacc[nt][e] = 0.f;

#pragma unroll
            for (int kk = 0; kk < 8; kk++) {
                uint32_t ah[4], al[4], bh[4][4];
                uint32_t qrow = wr0 + ((lt & 1) << 3) + lr;
                uint32_t qc   = (kk << 1) + (lt >> 1);
                uint32_t qa   = QH + ((qrow * 68 + qc * 4) << 2);
                LDSM4(ah, qa);
#pragma unroll
                for (int i = 0; i < 4; i++) {
                    uint32_t krow = (i << 4) + ((lt >> 1) << 3) + lr;
                    uint32_t kc   = (kk << 1) + (lt & 1);
                    LDSM4(bh[i], KH + ((krow * 68 + kc * 4) << 2));
                }
                // pass 1: Q_hi x K
#pragma unroll
                for (int i = 0; i < 4; i++) {
                    mma16h(sacc[2 * i],     ah[0], ah[1], ah[2], ah[3], bh[i][0], bh[i][1]);
                    mma16h(sacc[2 * i + 1], ah[0], ah[1], ah[2], ah[3], bh[i][2], bh[i][3]);
                }
                LDSM4(al, qa + (FL_QU << 2));
                // pass 2: Q_lo x K
#pragma unroll
                for (int i = 0; i < 4; i++) {
                    mma16h(sacc[2 * i],     al[0], al[1], al[2], al[3], bh[i][0], bh[i][1]);
                    mma16h(sacc[2 * i + 1], al[0], al[1], al[2], al[3], bh[i][2], bh[i][3]);
                }
            }

            // ---- causal mask (near diagonal only) ----
            if (kv0 + 63 > grow0) {
                const int r0 = grow0 + g;
#pragma unroll
                for (int nt = 0; nt < 8; nt++) {
                    int c0 = kv0 + nt * 8 + (q4 << 1);
                    if (c0 > r0)         sacc[nt][0] = -1e30f;
                    if (c0 + 1 > r0)     sacc[nt][1] = -1e30f;
                    if (c0 > r0 + 8)     sacc[nt][2] = -1e30f;
                    if (c0 + 1 > r0 + 8) sacc[nt][3] = -1e30f;
                }
            }

            // ---- streaming softmax ----
            float rmax0 = -1e30f, rmax1 = -1e30f;
#pragma unroll
            for (int nt = 0; nt < 8; nt++) {
                rmax0 = fmaxf(rmax0, fmaxf(sacc[nt][0], sacc[nt][1]));
                rmax1 = fmaxf(rmax1, fmaxf(sacc[nt][2], sacc[nt][3]));
            }
            rmax0 = fmaxf(rmax0, __shfl_xor_sync(0xffffffffu, rmax0, 1));
            rmax0 = fmaxf(rmax0, __shfl_xor_sync(0xffffffffu, rmax0, 2));
            rmax1 = fmaxf(rmax1, __shfl_xor_sync(0xffffffffu, rmax1, 1));
            rmax1 = fmaxf(rmax1, __shfl_xor_sync(0xffffffffu, rmax1, 2));

            float mn0 = fmaxf(m_i[0], rmax0);
            float mn1 = fmaxf(m_i[1], rmax1);
            float alpha0 = __expf(m_i[0] - mn0);
            float alpha1 = __expf(m_i[1] - mn1);

            float rs0 = 0.f, rs1 = 0.f;
#pragma unroll
            for (int nt = 0; nt < 8; nt++) {
                sacc[nt][0] = __expf(sacc[nt][0] - mn0);
                sacc[nt][1] = __expf(sacc[nt][1] - mn0);
                sacc[nt][2] = __expf(sacc[nt][2] - mn1);
                sacc[nt][3] = __expf(sacc[nt][3] - mn1);
                rs0 += sacc[nt][0] + sacc[nt][1];
                rs1 += sacc[nt][2] + sacc[nt][3];
            }
            rs0 += __shfl_xor_sync(0xffffffffu, rs0, 1);
            rs0 += __shfl_xor_sync(0xffffffffu, rs0, 2);
            rs1 += __shfl_xor_sync(0xffffffffu, rs1, 1);
            rs1 += __shfl_xor_sync(0xffffffffu, rs1, 2);

            l_i[0] = l_i[0] * alpha0 + rs0;
            l_i[1] = l_i[1] * alpha1 + rs1;
            m_i[0] = mn0;
            m_i[1] = mn1;

#pragma unroll
            for (int nt = 0; nt < 16; nt++) {
                Oacc[nt][0] *= alpha0; Oacc[nt][1] *= alpha0;
                Oacc[nt][2] *= alpha1; Oacc[nt][3] *= alpha1;
            }

            // ---- O += P @ V (P fp16-split in regs; V fp16 via trans ldmatrix) ----
#pragma unroll
            for (int c = 0; c < 4; c++) {
                uint32_t ph[4], pl[4];
                split_pack_h(sacc[2 * c][0],     sacc[2 * c][1],     ph[0], pl[0]);
                split_pack_h(sacc[2 * c][2],     sacc[2 * c][3],     ph[1], pl[1]);
                split_pack_h(sacc[2 * c + 1][0], sacc[2 * c + 1][1], ph[2], pl[2]);
                split_pack_h(sacc[2 * c + 1][2], sacc[2 * c + 1][3], ph[3], pl[3]);
                const uint32_t srow = (c << 4) + ((lt & 1) << 3) + lr;
#pragma unroll
                for (int half = 0; half < 2; half++) {
                    uint32_t vh[4][4];
#pragma unroll
                    for (int i = 0; i < 4; i++) {
                        uint32_t dc = ((half * 4 + i) << 1) + (lt >> 1);
                        LDSM4T(vh[i], VH + ((srow * 68 + dc * 4) << 2));
                    }
                    // pass 1: P_hi x V
#pragma unroll
                    for (int i = 0; i < 4; i++) {
                        int o = 2 * (half * 4 + i);
                        mma16h(Oacc[o],     ph[0], ph[1], ph[2], ph[3], vh[i][0], vh[i][1]);
                        mma16h(Oacc[o + 1], ph[0], ph[1], ph[2], ph[3], vh[i][2], vh[i][3]);
                    }
                    // pass 2: P_lo x V
#pragma unroll
                    for (int i = 0; i < 4; i++) {
                        int o = 2 * (half * 4 + i);
                        mma16h(Oacc[o],     pl[0], pl[1], pl[2], pl[3], vh[i][0], vh[i][1]);
                        mma16h(Oacc[o + 1], pl[0], pl[1], pl[2], pl[3], vh[i][2], vh[i][3]);
                    }
                }
            }
        }
        __syncthreads();
    }

    // ---- epilogue: normalize, fp16-split, write hi/lo attn (for fp16 proj) ----
    const float inv0 = 1.f / l_i[0];
    const float inv1 = 1.f / l_i[1];
    const int   s0   = qr0 + wr0 + g;
    const size_t base0 = ((size_t)(b * SEQ) + s0) * (HID / 2) + h * 64;
#pragma unroll
    for (int nt = 0; nt < 16; nt++) {
        float o00 = Oacc[nt][0] * inv0, o01 = Oacc[nt][1] * inv0;
        float o10 = Oacc[nt][2] * inv1, o11 = Oacc[nt][3] * inv1;
        uint32_t h0, l0, h1, l1;
        split_pack_h(o00, o01, h0, l0);
        split_pack_h(o10, o11, h1, l1);
        size_t ci = base0 + nt * 4 + q4;
        ((uint32_t *)g_ath)[ci] = h0;
        ((uint32_t *)g_atl)[ci] = l0;
        ((uint32_t *)g_ath)[ci + 8 * (HID / 2)] = h1;
        ((uint32_t *)g_atl)[ci + 8 * (HID / 2)] = l1;
    }
}

// ---------------------------------------------------------------------------
// kernel_launch
// ---------------------------------------------------------------------------
extern "C" void kernel_launch(void *const *d_in, const int *in_sizes, int n_in,
                              void *d_out, int out_size) {
    (void)in_sizes; (void)n_in; (void)out_size;
    const float *hs     = (const float *)d_in[0];
    const float *w_attn = (const float *)d_in[1];
    const float *b_attn = (const float *)d_in[2];
    const float *w_proj = (const float *)d_in[3];
    const float *b_proj = (const float *)d_in[4];
    float *out = (float *)d_out;

    cudaFuncSetAttribute(gemm_ldsm<1>,
                         cudaFuncAttributeMaxDynamicSharedMemorySize, GEMM_SMEM);
    cudaFuncSetAttribute(gemm_ldsm<0>,
                         cudaFuncAttributeMaxDynamicSharedMemorySize, GEMM_SMEM);
    cudaFuncSetAttribute(flash_causal,
                         cudaFuncAttributeMaxDynamicSharedMemorySize, FLASH_SMEM);

    uint16_t *hidh, *hidl, *wah, *wph, *ath, *atl;
    cudaGetSymbolAddress((void **)&hidh, g_hidh);
    cudaGetSymbolAddress((void **)&hidl, g_hidl);
    cudaGetSymbolAddress((void **)&wah,  g_wah);
    cudaGetSymbolAddress((void **)&wph,  g_wph);
    cudaGetSymbolAddress((void **)&ath,  g_ath);
    cudaGetSymbolAddress((void **)&atl,  g_atl);

    // 0) pre-convert inputs: hidden -> fp16 split; weights -> fp16 rounded
    split4h<<<(MTOT * HID) / 1024, 256>>>((const float4 *)hs,
                                          (uint2 *)hidh, (uint2 *)hidl);
    round4h<<<(HID * NQKV) / 1024, 256>>>((const float4 *)w_attn, (uint2 *)wah);
    round4h<<<(HID * HID) / 1024, 256>>>((const float4 *)w_proj, (uint2 *)wph);

    // 1) QKV projection -> fp16-split Q (pre-scaled), fp16 K/V
    gemm_ldsm<1><<<dim3(NQKV / 256, MTOT / 128), 512, GEMM_SMEM>>>(
        hidh, hidl, wah, b_attn, nullptr, MTOT, NQKV, HID);

    // 2) causal flash attention -> fp16 split attn (g_ath/g_atl)
    flash_causal<<<dim3(SEQ / 128, NHEAD, BB), 256, FLASH_SMEM>>>();

    // 3) output projection -> d_out
    gemm_ldsm<0><<<dim3(HID / 256, MTOT / 128), 512, GEMM_SMEM>>>(
        ath, atl, wph, b_proj, out, MTOT, HID, HID);
}

// round 13
// speedup vs baseline: 2.1482x; 1.2512x over previous
#include <cuda_runtime.h>
#include <cstdint>

// Problem constants (fixed by the reference)
#define BB    2
#define SEQ   2048
#define HID   2048
#define NHEAD 16
#define DHEAD 128
#define MTOT  (BB * SEQ)      // 4096
#define NQKV  (3 * HID)       // 6144
#define QSCALE 0.088388347648318447f

// ---------------------------------------------------------------------------
// Device scratch (all 16B-aligned for cp.async / vector access)
// ---------------------------------------------------------------------------
__device__ __align__(128) uint16_t g_qh[(size_t)BB * NHEAD * SEQ * DHEAD];  // fp16
__device__ __align__(128) uint16_t g_kh[(size_t)BB * NHEAD * SEQ * DHEAD];  // fp16
__device__ __align__(128) uint16_t g_vh[(size_t)BB * NHEAD * SEQ * DHEAD];  // fp16

__device__ __align__(128) uint16_t g_hidh[(size_t)MTOT * HID];   // fp16 rounded
__device__ __align__(128) uint16_t g_wah[(size_t)HID * NQKV];    // fp16 rounded
__device__ __align__(128) uint16_t g_wph[(size_t)HID * HID];     // fp16 rounded
__device__ __align__(128) uint16_t g_ath[(size_t)MTOT * HID];    // fp16 split hi
__device__ __align__(128) uint16_t g_atl[(size_t)MTOT * HID];    // fp16 split lo

// ---------------------------------------------------------------------------
// Helpers
// ---------------------------------------------------------------------------
// fp16 split: h = {fp16(x0) lo16, fp16(x1) hi16}, l = residuals in fp16
__device__ __forceinline__ void split_pack_h(float x0, float x1,
                                             uint32_t &h, uint32_t &l) {
    asm("cvt.rn.f16x2.f32 %0, %1, %2;" : "=r"(h) : "f"(x1), "f"(x0));
    float h0f, h1f;
    asm("{ .reg .b16 a, b;\n\t"
        "  mov.b32 {a, b}, %2;\n\t"
        "  cvt.f32.f16 %0, a;\n\t"
        "  cvt.f32.f16 %1, b; }"
        : "=f"(h0f), "=f"(h1f) : "r"(h));
    asm("cvt.rn.f16x2.f32 %0, %1, %2;" : "=r"(l) : "f"(x1 - h1f), "f"(x0 - h0f));
}
__device__ __forceinline__ uint32_t round_pack_h(float x0, float x1) {
    uint32_t h;
    asm("cvt.rn.f16x2.f32 %0, %1, %2;" : "=r"(h) : "f"(x1), "f"(x0));
    return h;
}
__device__ __forceinline__ void h2unpack(uint32_t h, float &x0, float &x1) {
    asm("{ .reg .b16 a, b;\n\t"
        "  mov.b32 {a, b}, %2;\n\t"
        "  cvt.f32.f16 %0, a;\n\t"
        "  cvt.f32.f16 %1, b; }"
        : "=f"(x0), "=f"(x1) : "r"(h));
}

__device__ __forceinline__ uint32_t smem_u32(const void *p) {
    uint32_t a;
    asm("{ .reg .u64 t; cvta.to.shared.u64 t, %1; cvt.u32.u64 %0, t; }"
        : "=r"(a) : "l"(p));
    return a;
}

// fp16 mma, fp32 accumulate
__device__ __forceinline__ void mma16h(float *d,
                                       uint32_t a0, uint32_t a1, uint32_t a2, uint32_t a3,
                                       uint32_t b0, uint32_t b1) {
    asm volatile(
        "mma.sync.aligned.m16n8k16.row.col.f32.f16.f16.f32 "
        "{%0,%1,%2,%3}, {%4,%5,%6,%7}, {%8,%9}, {%0,%1,%2,%3};\n"
        : "+f"(d[0]), "+f"(d[1]), "+f"(d[2]), "+f"(d[3])
        : "r"(a0), "r"(a1), "r"(a2), "r"(a3), "r"(b0), "r"(b1));
}
// fp16 mma, fp16 accumulate (lo-correction term in proj)
__device__ __forceinline__ void mma16hh(uint32_t *d,
                                        uint32_t a0, uint32_t a1, uint32_t a2, uint32_t a3,
                                        uint32_t b0, uint32_t b1) {
    asm volatile(
        "mma.sync.aligned.m16n8k16.row.col.f16.f16.f16.f16 "
        "{%0,%1}, {%2,%3,%4,%5}, {%6,%7}, {%0,%1};\n"
        : "+r"(d[0]), "+r"(d[1])
        : "r"(a0), "r"(a1), "r"(a2), "r"(a3), "r"(b0), "r"(b1));
}

#define LDSM4(r, addr)                                                       \
    asm volatile("ldmatrix.sync.aligned.m8n8.x4.shared.b16 {%0,%1,%2,%3}, [%4];" \
        : "=r"((r)[0]), "=r"((r)[1]), "=r"((r)[2]), "=r"((r)[3]) : "r"(addr))
#define LDSM4T(r, addr)                                                      \
    asm volatile("ldmatrix.sync.aligned.m8n8.x4.trans.shared.b16 {%0,%1,%2,%3}, [%4];" \
        : "=r"((r)[0]), "=r"((r)[1]), "=r"((r)[2]), "=r"((r)[3]) : "r"(addr))

__device__ __forceinline__ void cpa16(uint32_t dst, const void *src) {
    asm volatile("cp.async.cg.shared.global [%0], [%1], 16;"
                 :: "r"(dst), "l"(src) : "memory");
}
#define CP_COMMIT() asm volatile("cp.async.commit_group;" ::: "memory")
#define CP_WAIT2()  asm volatile("cp.async.wait_group 2;" ::: "memory")
#define CP_WAIT0()  asm volatile("cp.async.wait_group 0;" ::: "memory")

// ---------------------------------------------------------------------------
// Split kernels
// ---------------------------------------------------------------------------
__global__ void __launch_bounds__(256)
split4h(const float4 *__restrict__ x, uint2 *__restrict__ hi, uint2 *__restrict__ lo) {
    int i = blockIdx.x * 256 + threadIdx.x;
    float4 v = x[i];
    uint32_t h0, l0, h1, l1;
    split_pack_h(v.x, v.y, h0, l0);
    split_pack_h(v.z, v.w, h1, l1);
    hi[i] = make_uint2(h0, h1);
    lo[i] = make_uint2(l0, l1);
}
__global__ void __launch_bounds__(256)
round4h(const float4 *__restrict__ x, uint2 *__restrict__ hi) {
    int i = blockIdx.x * 256 + threadIdx.x;
    float4 v = x[i];
    hi[i] = make_uint2(round_pack_h(v.x, v.y), round_pack_h(v.z, v.w));
}

// ---------------------------------------------------------------------------
// GEMM: C = A @ B + bias, fp16 inputs.
// MODE 1 (QKV): single-pass (A and outputs fp16-rounded; downstream consumes
//               fp16 anyway). Epilogue scatters fp16 Q (pre-scaled), K, V.
// MODE 0 (proj): split-A x2 (A = ah + al exact), pass 2 fp16-accum; fp32 out.
// CTA tile 128m x 256n, 512 threads = 16 warps (2 wm x 8 wn), warp tile 64x32.
// 4-stage cp.async; stage = AH 10240 | AL 10240 | BH 16384 = 36864 B.
// ---------------------------------------------------------------------------
#define STG_BYTES 36864
#define OFF_AH 0
#define OFF_AL 10240
#define OFF_BH 20480
#define GEMM_SMEM (4 * STG_BYTES)

template <int MODE>
__global__ void __launch_bounds__(512)
gemm_ldsm(const uint16_t *__restrict__ Ah, const uint16_t *__restrict__ Al,
          const uint16_t *__restrict__ Bh,
          const float *__restrict__ bias, float *__restrict__ Cout,
          int M, int N, int K) {
    extern __shared__ char smc[];
    const uint32_t sbase = smem_u32(smc);

    const int tid  = threadIdx.x;
    const int lane = tid & 31;
    const int warp = tid >> 5;
    const int wm   = warp >> 3;      // 0..1
    const int wn   = warp & 7;       // 0..7
    const int m0   = blockIdx.y * 128;
    const int n0   = blockIdx.x * 256;
    const int g    = lane >> 2;
    const int q4   = lane & 3;

    float acc[4][4][4];
    uint32_t acc16[4][4][2];
#pragma unroll
    for (int i = 0; i < 4; i++)
#pragma unroll
        for (int j = 0; j < 4; j++) {
#pragma unroll
            for (int e = 0; e < 4; e++) acc[i][j][e] = 0.f;
            acc16[i][j][0] = 0u;
            acc16[i][j][1] = 0u;
        }

    auto issue = [&](int s) {
        const uint32_t sb = sbase + (s & 3) * STG_BYTES;
        const int kb = s << 5;
        {
            int row = tid >> 2;
            int c   = tid & 3;
            size_t gidx = (size_t)(m0 + row) * K + kb + c * 8;
            uint32_t d = (row * 5 + c) << 4;
            cpa16(sb + OFF_AH + d, Ah + gidx);
            if (MODE == 0) cpa16(sb + OFF_AL + d, Al + gidx);
        }
#pragma unroll
        for (int i = 0; i < 2; i++) {
            int id = tid + i * 512;
            int k  = id >> 5;
            int c  = id & 31;
            size_t gidx = (size_t)(kb + k) * N + n0 + c * 8;
            uint32_t d = ((k << 5) + (c ^ (k & 7))) << 4;
            cpa16(sb + OFF_BH + d, Bh + gidx);
        }
    };

    auto compute = [&](int s) {
        const uint32_t sb = sbase + (s & 3) * STG_BYTES;
        const int arow = wm * 64 + (lane & 15);
        const int lt16 = lane >> 4;
        const int cbas = wn * 4 + ((lane >> 3) & 1);
#pragma unroll
        for (int kk = 0; kk < 2; kk++) {
            const int ac   = kk * 2 + lt16;
            const int kloc = kk * 16 + (lt16 << 3) + (lane & 7);
            uint32_t ad[4], bd[2];
#pragma unroll
            for (int mt = 0; mt < 4; mt++)
                ad[mt] = sb + OFF_AH + (((arow + mt * 16) * 5 + ac) << 4);
#pragma unroll
            for (int bt = 0; bt < 2; bt++) {
                int c = cbas + bt * 2;
                bd[bt] = sb + OFF_BH + (((kloc << 5) + (c ^ (kloc & 7))) << 4);
            }

            uint32_t ah[4][4], al[4][4], bh[2][4];
#pragma unroll
            for (int mt = 0; mt < 4; mt++) LDSM4(ah[mt], ad[mt]);
#pragma unroll
            for (int bt = 0; bt < 2; bt++) LDSM4T(bh[bt], bd[bt]);

            // ---- pass 1: A_hi x B, fp32 accumulate ----
#pragma unroll
            for (int bt = 0; bt < 2; bt++)
#pragma unroll
                for (int mt = 0; mt < 4; mt++) {
                    mma16h(acc[mt][2 * bt],     ah[mt][0], ah[mt][1], ah[mt][2], ah[mt][3],
                           bh[bt][0], bh[bt][2]);
                    mma16h(acc[mt][2 * bt + 1], ah[mt][0], ah[mt][1], ah[mt][2], ah[mt][3],
                           bh[bt][1], bh[bt][3]);
                }

            if (MODE == 0) {
#pragma unroll
                for (int mt = 0; mt < 4; mt++)
                    LDSM4(al[mt], ad[mt] + (OFF_AL - OFF_AH));

                // ---- pass 2: A_lo x B, fp16 accumulate ----
#pragma unroll
                for (int bt = 0; bt < 2; bt++)
#pragma unroll
                    for (int mt = 0; mt < 4; mt++) {
                        mma16hh(acc16[mt][2 * bt],     al[mt][0], al[mt][1], al[mt][2], al[mt][3],
                                bh[bt][0], bh[bt][2]);
                        mma16hh(acc16[mt][2 * bt + 1], al[mt][0], al[mt][1], al[mt][2], al[mt][3],
                                bh[bt][1], bh[bt][3]);
                    }
            }
        }
    };

    const int S = K >> 5;
    issue(0); CP_COMMIT();
    issue(1); CP_COMMIT();
    issue(2); CP_COMMIT();

    for (int s = 0; s < S; s++) {
        CP_WAIT2();
        __syncthreads();
        compute(s);
        if (s + 3 < S) issue(s + 3);
        CP_COMMIT();
    }

    // ---- epilogue ----
#pragma unroll
    for (int mt = 0; mt < 4; mt++) {
#pragma unroll
        for (int nt = 0; nt < 4; nt++) {
            float c0 = acc[mt][nt][0];
            float c1 = acc[mt][nt][1];
            float c2 = acc[mt][nt][2];
            float c3 = acc[mt][nt][3];
            if (MODE == 0) {
                float l0, l1, l2, l3;
                h2unpack(acc16[mt][nt][0], l0, l1);
                h2unpack(acc16[mt][nt][1], l2, l3);
                c0 += l0; c1 += l1; c2 += l2; c3 += l3;
            }

            int row = m0 + wm * 64 + mt * 16 + g;
            int col = n0 + wn * 32 + nt * 8 + (q4 << 1);
            float b0 = bias[col];
            float b1 = bias[col + 1];
            if (MODE == 1) {
                int which = col >> 11;
                int head  = (col >> 7) & 15;
                int dc    = col & 127;
                int bi = row >> 11;
                int si = row & 2047;
                size_t u32i = (((size_t)(bi * NHEAD + head) * SEQ + si) * DHEAD + dc) >> 1;
                uint16_t *dh = (which == 0) ? g_qh : ((which == 1) ? g_kh : g_vh);
                float sc = (which == 0) ? QSCALE : 1.f;
                uint32_t h0 = round_pack_h((c0 + b0) * sc, (c1 + b1) * sc);
                uint32_t h1 = round_pack_h((c2 + b0) * sc, (c3 + b1) * sc);
                ((uint32_t *)dh)[u32i] = h0;
                ((uint32_t *)dh)[u32i + 8 * 64] = h1;
            } else {
                float2 v0 = make_float2(c0 + b0, c1 + b1);
                float2 v1 = make_float2(c2 + b0, c3 + b1);
                *(float2 *)(Cout + (size_t)row * N + col) = v0;
                *(float2 *)(Cout + (size_t)(row + 8) * N + col) = v1;
            }
        }
    }
}

// ---------------------------------------------------------------------------
// Flash attention (causal), single-pass fp16 (Q, K, V, P all fp16-rounded;
// accumulation in fp32). CTA: 128 Q rows, 8 warps x 16 rows. KV tile 64.
// smem u32: Q[128*68] | stage st: K[64*68] V[64*68]  -> 102 KB (2 CTAs/SM).
// Output: attn split hi/lo (exact) for the 2-pass proj GEMM.
// ---------------------------------------------------------------------------
#define FL_QU   (128 * 68)          // u32 for Q
#define FL_AU   (64 * 68)           // u32 per K/V array (4352)
#define FL_STGU (2 * FL_AU)         // 8704 u32 per stage
#define FLASH_SMEM ((FL_QU + 2 * FL_STGU) * 4)

__global__ void __launch_bounds__(256) flash_causal() {
    extern __shared__ uint32_t smf[];
    const uint32_t sbase = smem_u32(smf);

    const int qt   = (gridDim.x - 1) - blockIdx.x;   // heavy tiles first
    const int h    = blockIdx.y;
    const int b    = blockIdx.z;
    const int tid  = threadIdx.x;
    const int lane = tid & 31;
    const int warp = tid >> 5;
    const int g    = lane >> 2;
    const int q4   = lane & 3;

    const size_t headoff = (size_t)(b * NHEAD + h) * SEQ * DHEAD;
    const uint16_t *Qhg = g_qh + headoff;
    const uint16_t *Khg = g_kh + headoff;
    const uint16_t *Vhg = g_vh + headoff;

    const int qr0 = qt * 128;

    // ---- Q tile: 128 rows x 16 chunks = 2048 cp.async chunks ----
#pragma unroll
    for (int i = 0; i < 8; i++) {
        int id  = tid + i * 256;       // 0..2047
        int row = id >> 4;             // 0..127
        int c   = id & 15;
        cpa16(sbase + ((row * 68 + c * 4) << 2),
              Qhg + (size_t)(qr0 + row) * DHEAD + c * 8);
    }

    auto copy_kv = [&](int kv0, int st) {
        const uint32_t stb = sbase + ((FL_QU + st * FL_STGU) << 2);
#pragma unroll
        for (int i = 0; i < 8; i++) {
            int id  = tid + i * 256;                 // 0..2047
            int arr = id >> 10;                      // 0 = K, 1 = V
            int rc  = id & 1023;
            int row = rc >> 4;
            int c   = rc & 15;
            const uint16_t *base = (arr == 0) ? Khg : Vhg;
            cpa16(stb + ((arr * FL_AU + row * 68 + c * 4) << 2),
                  base + (size_t)(kv0 + row) * DHEAD + c * 8);
        }
    };

    float Oacc[16][4];
#pragma unroll
    for (int i = 0; i < 16; i++)
#pragma unroll
        for (int e = 0; e < 4; e++) Oacc[i][e] = 0.f;
    float m_i[2] = {-1e30f, -1e30f};
    float l_i[2] = {0.f, 0.f};

    const int wr0   = warp * 16;
    const int grow0 = qr0 + wr0;
    const int jmax  = 2 * qt + 1;

    copy_kv(0, 0);
    CP_COMMIT();

    const int lt = lane >> 3;      // tile index within x4 (0..3)
    const int lr = lane & 7;       // row within tile

    for (int j = 0; j <= jmax; j++) {
        const int kv0 = j * 64;
        CP_WAIT0();
        __syncthreads();
        if (j + 1 <= jmax) {
            copy_kv((j + 1) * 64, (j + 1) & 1);
            CP_COMMIT();
        }

        if (kv0 <= grow0 + 15) {
            const uint32_t QH = sbase;
            const uint32_t KH = sbase + ((FL_QU + (j & 1) * FL_STGU) << 2);
            const uint32_t VH = KH + (FL_AU << 2);

            // ---- S = Q @ K^T : 16 x 64 per warp (single pass) ----
            float sacc[8][4];
#pragma unroll
            for (int nt = 0; nt < 8; nt++)
#pragma unroll
                for (int e = 0; e < 4; e++) sacc[nt][e] = 0.f;

#pragma unroll
            for (int kk = 0; kk < 8; kk++) {
                uint32_t ah[4], bh[4][4];
                uint32_t qrow = wr0 + ((lt & 1) << 3) + lr;
                uint32_t qc   = (kk << 1) + (lt >> 1);
                LDSM4(ah, QH + ((qrow * 68 + qc * 4) << 2));
#pragma unroll
                for (int i = 0; i < 4; i++) {
                    uint32_t krow = (i << 4) + ((lt >> 1) << 3) + lr;
                    uint32_t kc   = (kk << 1) + (lt & 1);
                    LDSM4(bh[i], KH + ((krow * 68 + kc * 4) << 2));
                }
#pragma unroll
                for (int i = 0; i < 4; i++) {
                    mma16h(sacc[2 * i],     ah[0], ah[1], ah[2], ah[3], bh[i][0], bh[i][1]);
                    mma16h(sacc[2 * i + 1], ah[0], ah[1], ah[2], ah[3], bh[i][2], bh[i][3]);
                }
            }

            // ---- causal mask (near diagonal only) ----
            if (kv0 + 63 > grow0) {
                const int r0 = grow0 + g;
#pragma unroll
                for (int nt = 0; nt < 8; nt++) {
                    int c0 = kv0 + nt * 8 + (q4 << 1);
                    if (c0 > r0)         sacc[nt][0] = -1e30f;
                    if (c0 + 1 > r0)     sacc[nt][1] = -1e30f;
                    if (c0 > r0 + 8)     sacc[nt][2] = -1e30f;
                    if (c0 + 1 > r0 + 8) sacc[nt][3] = -1e30f;
                }
            }

            // ---- streaming softmax ----
            float rmax0 = -1e30f, rmax1 = -1e30f;
#pragma unroll
            for (int nt = 0; nt < 8; nt++) {
                rmax0 = fmaxf(rmax0, fmaxf(sacc[nt][0], sacc[nt][1]));
                rmax1 = fmaxf(rmax1, fmaxf(sacc[nt][2], sacc[nt][3]));
            }
            rmax0 = fmaxf(rmax0, __shfl_xor_sync(0xffffffffu, rmax0, 1));
            rmax0 = fmaxf(rmax0, __shfl_xor_sync(0xffffffffu, rmax0, 2));
            rmax1 = fmaxf(rmax1, __shfl_xor_sync(0xffffffffu, rmax1, 1));
            rmax1 = fmaxf(rmax1, __shfl_xor_sync(0xffffffffu, rmax1, 2));

            float mn0 = fmaxf(m_i[0], rmax0);
            float mn1 = fmaxf(m_i[1], rmax1);
            float alpha0 = __expf(m_i[0] - mn0);
            float alpha1 = __expf(m_i[1] - mn1);

            float rs0 = 0.f, rs1 = 0.f;
#pragma unroll
            for (int nt = 0; nt < 8; nt++) {
                sacc[nt][0] = __expf(sacc[nt][0] - mn0);
                sacc[nt][1] = __expf(sacc[nt][1] - mn0);
                sacc[nt][2] = __expf(sacc[nt][2] - mn1);
                sacc[nt][3] = __expf(sacc[nt][3] - mn1);
                rs0 += sacc[nt][0] + sacc[nt][1];
                rs1 += sacc[nt][2] + sacc[nt][3];
            }
            rs0 += __shfl_xor_sync(0xffffffffu, rs0, 1);
            rs0 += __shfl_xor_sync(0xffffffffu, rs0, 2);
            rs1 += __shfl_xor_sync(0xffffffffu, rs1, 1);
            rs1 += __shfl_xor_sync(0xffffffffu, rs1, 2);

            l_i[0] = l_i[0] * alpha0 + rs0;
            l_i[1] = l_i[1] * alpha1 + rs1;
            m_i[0] = mn0;
            m_i[1] = mn1;

#pragma unroll
            for (int nt = 0; nt < 16; nt++) {
                Oacc[nt][0] *= alpha0; Oacc[nt][1] *= alpha0;
                Oacc[nt][2] *= alpha1; Oacc[nt][3] *= alpha1;
            }

            // ---- O += P @ V (P fp16-rounded in regs; single pass) ----
#pragma unroll
            for (int c = 0; c < 4; c++) {
                uint32_t ph[4];
                ph[0] = round_pack_h(sacc[2 * c][0],     sacc[2 * c][1]);
                ph[1] = round_pack_h(sacc[2 * c][2],     sacc[2 * c][3]);
                ph[2] = round_pack_h(sacc[2 * c + 1][0], sacc[2 * c + 1][1]);
                ph[3] = round_pack_h(sacc[2 * c + 1][2], sacc[2 * c + 1][3]);
                const uint32_t srow = (c << 4) + ((lt & 1) << 3) + lr;
#pragma unroll
                for (int i = 0; i < 8; i++) {
                    uint32_t dc = (i << 1) + (lt >> 1);
                    uint32_t vh[4];
                    LDSM4T(vh, VH + ((srow * 68 + dc * 4) << 2));
                    mma16h(Oacc[2 * i],     ph[0], ph[1], ph[2], ph[3], vh[0], vh[1]);
                    mma16h(Oacc[2 * i + 1], ph[0], ph[1], ph[2], ph[3], vh[2], vh[3]);
                }
            }
        }
        __syncthreads();
    }

    // ---- epilogue: normalize, fp16-split, write hi/lo attn (for fp16 proj) ----
    const float inv0 = 1.f / l_i[0];
    const float inv1 = 1.f / l_i[1];
    const int   s0   = qr0 + wr0 + g;
    const size_t base0 = ((size_t)(b * SEQ) + s0) * (HID / 2) + h * 64;
#pragma unroll
    for (int nt = 0; nt < 16; nt++) {
        float o00 = Oacc[nt][0] * inv0, o01 = Oacc[nt][1] * inv0;
        float o10 = Oacc[nt][2] * inv1, o11 = Oacc[nt][3] * inv1;
        uint32_t h0, l0, h1, l1;
        split_pack_h(o00, o01, h0, l0);
        split_pack_h(o10, o11, h1, l1);
        size_t ci = base0 + nt * 4 + q4;
        ((uint32_t *)g_ath)[ci] = h0;
        ((uint32_t *)g_atl)[ci] = l0;
        ((uint32_t *)g_ath)[ci + 8 * (HID / 2)] = h1;
        ((uint32_t *)g_atl)[ci + 8 * (HID / 2)] = l1;
    }
}

// ---------------------------------------------------------------------------
// kernel_launch
// ---------------------------------------------------------------------------
extern "C" void kernel_launch(void *const *d_in, const int *in_sizes, int n_in,
                              void *d_out, int out_size) {
    (void)in_sizes; (void)n_in; (void)out_size;
    const float *hs     = (const float *)d_in[0];
    const float *w_attn = (const float *)d_in[1];
    const float *b_attn = (const float *)d_in[2];
    const float *w_proj = (const float *)d_in[3];
    const float *b_proj = (const float *)d_in[4];
    float *out = (float *)d_out;

    cudaFuncSetAttribute(gemm_ldsm<1>,
                         cudaFuncAttributeMaxDynamicSharedMemorySize, GEMM_SMEM);
    cudaFuncSetAttribute(gemm_ldsm<0>,
                         cudaFuncAttributeMaxDynamicSharedMemorySize, GEMM_SMEM);
    cudaFuncSetAttribute(flash_causal,
                         cudaFuncAttributeMaxDynamicSharedMemorySize, FLASH_SMEM);

    uint16_t *hidh, *wah, *wph, *ath, *atl;
    cudaGetSymbolAddress((void **)&hidh, g_hidh);
    cudaGetSymbolAddress((void **)&wah,  g_wah);
    cudaGetSymbolAddress((void **)&wph,  g_wph);
    cudaGetSymbolAddress((void **)&ath,  g_ath);
    cudaGetSymbolAddress((void **)&atl,  g_atl);

    // 0) pre-convert inputs: all fp16 rounded (QKV path is single-pass fp16)
    round4h<<<(MTOT * HID) / 1024, 256>>>((const float4 *)hs, (uint2 *)hidh);
    round4h<<<(HID * NQKV) / 1024, 256>>>((const float4 *)w_attn, (uint2 *)wah);
    round4h<<<(HID * HID) / 1024, 256>>>((const float4 *)w_proj, (uint2 *)wph);

    // 1) QKV projection -> fp16 Q (pre-scaled), K, V (single-pass)
    gemm_ldsm<1><<<dim3(NQKV / 256, MTOT / 128), 512, GEMM_SMEM>>>(
        hidh, nullptr, wah, b_attn, nullptr, MTOT, NQKV, HID);

    // 2) causal flash attention -> fp16 split attn (g_ath/g_atl)
    flash_causal<<<dim3(SEQ / 128, NHEAD, BB), 256, FLASH_SMEM>>>();

    // 3) output projection -> d_out (exact split-A x2)
    gemm_ldsm<0><<<dim3(HID / 256, MTOT / 128), 512, GEMM_SMEM>>>(
        ath, atl, wph, b_proj, out, MTOT, HID, HID);
}

// round 14
// speedup vs baseline: 2.4439x; 1.1377x over previous
#include <cuda_runtime.h>
#include <cstdint>

// Problem constants (fixed by the reference)
#define BB    2
#define SEQ   2048
#define HID   2048
#define NHEAD 16
#define DHEAD 128
#define MTOT  (BB * SEQ)      // 4096
#define NQKV  (3 * HID)       // 6144
#define QSCALE 0.088388347648318447f

// ---------------------------------------------------------------------------
// Device scratch (all 16B-aligned for cp.async / vector access)
// ---------------------------------------------------------------------------
__device__ __align__(128) uint16_t g_qh[(size_t)BB * NHEAD * SEQ * DHEAD];  // fp16
__device__ __align__(128) uint16_t g_kh[(size_t)BB * NHEAD * SEQ * DHEAD];  // fp16
__device__ __align__(128) uint16_t g_vh[(size_t)BB * NHEAD * SEQ * DHEAD];  // fp16

__device__ __align__(128) uint16_t g_hidh[(size_t)MTOT * HID];   // fp16 rounded
__device__ __align__(128) uint16_t g_wah[(size_t)HID * NQKV];    // fp16 rounded
__device__ __align__(128) uint16_t g_wph[(size_t)HID * HID];     // fp16 rounded
__device__ __align__(128) uint16_t g_ath[(size_t)MTOT * HID];    // fp16 rounded attn

// ---------------------------------------------------------------------------
// Helpers
// ---------------------------------------------------------------------------
__device__ __forceinline__ uint32_t round_pack_h(float x0, float x1) {
    uint32_t h;
    asm("cvt.rn.f16x2.f32 %0, %1, %2;" : "=r"(h) : "f"(x1), "f"(x0));
    return h;
}

__device__ __forceinline__ uint32_t smem_u32(const void *p) {
    uint32_t a;
    asm("{ .reg .u64 t; cvta.to.shared.u64 t, %1; cvt.u32.u64 %0, t; }"
        : "=r"(a) : "l"(p));
    return a;
}

// fp16 mma, fp32 accumulate
__device__ __forceinline__ void mma16h(float *d,
                                       uint32_t a0, uint32_t a1, uint32_t a2, uint32_t a3,
                                       uint32_t b0, uint32_t b1) {
    asm volatile(
        "mma.sync.aligned.m16n8k16.row.col.f32.f16.f16.f32 "
        "{%0,%1,%2,%3}, {%4,%5,%6,%7}, {%8,%9}, {%0,%1,%2,%3};\n"
        : "+f"(d[0]), "+f"(d[1]), "+f"(d[2]), "+f"(d[3])
        : "r"(a0), "r"(a1), "r"(a2), "r"(a3), "r"(b0), "r"(b1));
}

#define LDSM4(r, addr)                                                       \
    asm volatile("ldmatrix.sync.aligned.m8n8.x4.shared.b16 {%0,%1,%2,%3}, [%4];" \
        : "=r"((r)[0]), "=r"((r)[1]), "=r"((r)[2]), "=r"((r)[3]) : "r"(addr))
#define LDSM4T(r, addr)                                                      \
    asm volatile("ldmatrix.sync.aligned.m8n8.x4.trans.shared.b16 {%0,%1,%2,%3}, [%4];" \
        : "=r"((r)[0]), "=r"((r)[1]), "=r"((r)[2]), "=r"((r)[3]) : "r"(addr))

__device__ __forceinline__ void cpa16(uint32_t dst, const void *src) {
    asm volatile("cp.async.cg.shared.global [%0], [%1], 16;"
                 :: "r"(dst), "l"(src) : "memory");
}
#define CP_COMMIT() asm volatile("cp.async.commit_group;" ::: "memory")
#define CP_WAIT2()  asm volatile("cp.async.wait_group 2;" ::: "memory")
#define CP_WAIT0()  asm volatile("cp.async.wait_group 0;" ::: "memory")

// ---------------------------------------------------------------------------
// Round kernel: fp32 -> fp16 (row-major preserved)
// ---------------------------------------------------------------------------
__global__ void __launch_bounds__(256)
round4h(const float4 *__restrict__ x, uint2 *__restrict__ hi) {
    int i = blockIdx.x * 256 + threadIdx.x;
    float4 v = x[i];
    hi[i] = make_uint2(round_pack_h(v.x, v.y), round_pack_h(v.z, v.w));
}

// ---------------------------------------------------------------------------
// GEMM: C = A @ B + bias, fp16 inputs, single pass, fp32 accumulate.
// CTA tile 128m x 256n, 512 threads = 16 warps (2 wm x 8 wn), warp tile 64x32.
// 4-stage cp.async; stage = A 10240 | B 16384 = 26624 B.
// MODE 1: QKV epilogue scatters fp16 Q (pre-scaled), K, V | MODE 0: fp32 out.
// ---------------------------------------------------------------------------
#define STG_BYTES 26624
#define OFF_A 0
#define OFF_B 10240
#define GEMM_SMEM (4 * STG_BYTES)

template <int MODE>
__global__ void __launch_bounds__(512)
gemm_ldsm(const uint16_t *__restrict__ Ah, const uint16_t *__restrict__ Bh,
          const float *__restrict__ bias, float *__restrict__ Cout,
          int M, int N, int K) {
    extern __shared__ char smc[];
    const uint32_t sbase = smem_u32(smc);

    const int tid  = threadIdx.x;
    const int lane = tid & 31;
    const int warp = tid >> 5;
    const int wm   = warp >> 3;      // 0..1
    const int wn   = warp & 7;       // 0..7
    const int m0   = blockIdx.y * 128;
    const int n0   = blockIdx.x * 256;
    const int g    = lane >> 2;
    const int q4   = lane & 3;

    float acc[4][4][4];
#pragma unroll
    for (int i = 0; i < 4; i++)
#pragma unroll
        for (int j = 0; j < 4; j++)
#pragma unroll
            for (int e = 0; e < 4; e++) acc[i][j][e] = 0.f;

    auto issue = [&](int s) {
        const uint32_t sb = sbase + (s & 3) * STG_BYTES;
        const int kb = s << 5;
        {
            int row = tid >> 2;
            int c   = tid & 3;
            cpa16(sb + OFF_A + ((row * 5 + c) << 4),
                  Ah + (size_t)(m0 + row) * K + kb + c * 8);
        }
#pragma unroll
        for (int i = 0; i < 2; i++) {
            int id = tid + i * 512;
            int k  = id >> 5;
            int c  = id & 31;
            cpa16(sb + OFF_B + (((k << 5) + (c ^ (k & 7))) << 4),
                  Bh + (size_t)(kb + k) * N + n0 + c * 8);
        }
    };

    auto compute = [&](int s) {
        const uint32_t sb = sbase + (s & 3) * STG_BYTES;
        const int arow = wm * 64 + (lane & 15);
        const int lt16 = lane >> 4;
        const int cbas = wn * 4 + ((lane >> 3) & 1);
#pragma unroll
        for (int kk = 0; kk < 2; kk++) {
            const int ac   = kk * 2 + lt16;
            const int kloc = kk * 16 + (lt16 << 3) + (lane & 7);

            uint32_t ah[4][4], bh[2][4];
#pragma unroll
            for (int mt = 0; mt < 4; mt++)
                LDSM4(ah[mt], sb + OFF_A + (((arow + mt * 16) * 5 + ac) << 4));
#pragma unroll
            for (int bt = 0; bt < 2; bt++) {
                int c = cbas + bt * 2;
                LDSM4T(bh[bt], sb + OFF_B + (((kloc << 5) + (c ^ (kloc & 7))) << 4));
            }

#pragma unroll
            for (int bt = 0; bt < 2; bt++)
#pragma unroll
                for (int mt = 0; mt < 4; mt++) {
                    mma16h(acc[mt][2 * bt],     ah[mt][0], ah[mt][1], ah[mt][2], ah[mt][3],
                           bh[bt][0], bh[bt][2]);
                    mma16h(acc[mt][2 * bt + 1], ah[mt][0], ah[mt][1], ah[mt][2], ah[mt][3],
                           bh[bt][1], bh[bt][3]);
                }
        }
    };

    const int S = K >> 5;
    issue(0); CP_COMMIT();
    issue(1); CP_COMMIT();
    issue(2); CP_COMMIT();

    for (int s = 0; s < S; s++) {
        CP_WAIT2();
        __syncthreads();
        compute(s);
        if (s + 3 < S) issue(s + 3);
        CP_COMMIT();
    }

    // ---- epilogue ----
#pragma unroll
    for (int mt = 0; mt < 4; mt++) {
#pragma unroll
        for (int nt = 0; nt < 4; nt++) {
            float c0 = acc[mt][nt][0];
            float c1 = acc[mt][nt][1];
            float c2 = acc[mt][nt][2];
            float c3 = acc[mt][nt][3];

            int row = m0 + wm * 64 + mt * 16 + g;
            int col = n0 + wn * 32 + nt * 8 + (q4 << 1);
            float b0 = bias[col];
            float b1 = bias[col + 1];
            if (MODE == 1) {
                int which = col >> 11;
                int head  = (col >> 7) & 15;
                int dc    = col & 127;
                int bi = row >> 11;
                int si = row & 2047;
                size_t u32i = (((size_t)(bi * NHEAD + head) * SEQ + si) * DHEAD + dc) >> 1;
                uint16_t *dh = (which == 0) ? g_qh : ((which == 1) ? g_kh : g_vh);
                float sc = (which == 0) ? QSCALE : 1.f;
                ((uint32_t *)dh)[u32i] =
                    round_pack_h((c0 + b0) * sc, (c1 + b1) * sc);
                ((uint32_t *)dh)[u32i + 8 * 64] =
                    round_pack_h((c2 + b0) * sc, (c3 + b1) * sc);
            } else {
                float2 v0 = make_float2(c0 + b0, c1 + b1);
                float2 v1 = make_float2(c2 + b0, c3 + b1);
                *(float2 *)(Cout + (size_t)row * N + col) = v0;
                *(float2 *)(Cout + (size_t)(row + 8) * N + col) = v1;
            }
        }
    }
}

// ---------------------------------------------------------------------------
// Flash attention (causal), single-pass fp16 (Q, K, V, P all fp16-rounded;
// accumulation in fp32). CTA: 128 Q rows, 8 warps x 16 rows. KV tile 64.
// smem u32: Q[128*68] | stage st: K[64*68] V[64*68]  -> 102 KB (2 CTAs/SM).
// Output: single fp16 attn (g_ath) for the single-pass proj GEMM.
// ---------------------------------------------------------------------------
#define FL_QU   (128 * 68)          // u32 for Q
#define FL_AU   (64 * 68)           // u32 per K/V array (4352)
#define FL_STGU (2 * FL_AU)         // 8704 u32 per stage
#define FLASH_SMEM ((FL_QU + 2 * FL_STGU) * 4)

__global__ void __launch_bounds__(256) flash_causal() {
    extern __shared__ uint32_t smf[];
    const uint32_t sbase = smem_u32(smf);

    const int qt   = (gridDim.x - 1) - blockIdx.x;   // heavy tiles first
    const int h    = blockIdx.y;
    const int b    = blockIdx.z;
    const int tid  = threadIdx.x;
    const int lane = tid & 31;
    const int warp = tid >> 5;
    const int g    = lane >> 2;
    const int q4   = lane & 3;

    const size_t headoff = (size_t)(b * NHEAD + h) * SEQ * DHEAD;
    const uint16_t *Qhg = g_qh + headoff;
    const uint16_t *Khg = g_kh + headoff;
    const uint16_t *Vhg = g_vh + headoff;

    const int qr0 = qt * 128;

    // ---- Q tile: 128 rows x 16 chunks = 2048 cp.async chunks ----
#pragma unroll
    for (int i = 0; i < 8; i++) {
        int id  = tid + i * 256;       // 0..2047
        int row = id >> 4;             // 0..127
        int c   = id & 15;
        cpa16(sbase + ((row * 68 + c * 4) << 2),
              Qhg + (size_t)(qr0 + row) * DHEAD + c * 8);
    }

    auto copy_kv = [&](int kv0, int st) {
        const uint32_t stb = sbase + ((FL_QU + st * FL_STGU) << 2);
#pragma unroll
        for (int i = 0; i < 8; i++) {
            int id  = tid + i * 256;                 // 0..2047
            int arr = id >> 10;                      // 0 = K, 1 = V
            int rc  = id & 1023;
            int row = rc >> 4;
            int c   = rc & 15;
            const uint16_t *base = (arr == 0) ? Khg : Vhg;
            cpa16(stb + ((arr * FL_AU + row * 68 + c * 4) << 2),
                  base + (size_t)(kv0 + row) * DHEAD + c * 8);
        }
    };

    float Oacc[16][4];
#pragma unroll
    for (int i = 0; i < 16; i++)
#pragma unroll
        for (int e = 0; e < 4; e++) Oacc[i][e] = 0.f;
    float m_i[2] = {-1e30f, -1e30f};
    float l_i[2] = {0.f, 0.f};

    const int wr0   = warp * 16;
    const int grow0 = qr0 + wr0;
    const int jmax  = 2 * qt + 1;

    copy_kv(0, 0);
    CP_COMMIT();

    const int lt = lane >> 3;      // tile index within x4 (0..3)
    const int lr = lane & 7;       // row within tile

    for (int j = 0; j <= jmax; j++) {
        const int kv0 = j * 64;
        CP_WAIT0();
        __syncthreads();
        if (j + 1 <= jmax) {
            copy_kv((j + 1) * 64, (j + 1) & 1);
            CP_COMMIT();
        }

        if (kv0 <= grow0 + 15) {
            const uint32_t QH = sbase;
            const uint32_t KH = sbase + ((FL_QU + (j & 1) * FL_STGU) << 2);
            const uint32_t VH = KH + (FL_AU << 2);

            // ---- S = Q @ K^T : 16 x 64 per warp (single pass) ----
            float sacc[8][4];
#pragma unroll
            for (int nt = 0; nt < 8; nt++)
#pragma unroll
                for (int e = 0; e < 4; e++) sacc[nt][e] = 0.f;

#pragma unroll
            for (int kk = 0; kk < 8; kk++) {
                uint32_t ah[4], bh[4][4];
                uint32_t qrow = wr0 + ((lt & 1) << 3) + lr;
                uint32_t qc   = (kk << 1) + (lt >> 1);
                LDSM4(ah, QH + ((qrow * 68 + qc * 4) << 2));
#pragma unroll
                for (int i = 0; i < 4; i++) {
                    uint32_t krow = (i << 4) + ((lt >> 1) << 3) + lr;
                    uint32_t kc   = (kk << 1) + (lt & 1);
                    LDSM4(bh[i], KH + ((krow * 68 + kc * 4) << 2));
                }
#pragma unroll
                for (int i = 0; i < 4; i++) {
                    mma16h(sacc[2 * i],     ah[0], ah[1], ah[2], ah[3], bh[i][0], bh[i][1]);
                    mma16h(sacc[2 * i + 1], ah[0], ah[1], ah[2], ah[3], bh[i][2], bh[i][3]);
                }
            }

            // ---- causal mask (near diagonal only) ----
            if (kv0 + 63 > grow0) {
                const int r0 = grow0 + g;
#pragma unroll
                for (int nt = 0; nt < 8; nt++) {
                    int c0 = kv0 + nt * 8 + (q4 << 1);
                    if (c0 > r0)         sacc[nt][0] = -1e30f;
                    if (c0 + 1 > r0)     sacc[nt][1] = -1e30f;
                    if (c0 > r0 + 8)     sacc[nt][2] = -1e30f;
                    if (c0 + 1 > r0 + 8) sacc[nt][3] = -1e30f;
                }
            }

            // ---- streaming softmax ----
            float rmax0 = -1e30f, rmax1 = -1e30f;
#pragma unroll
            for (int nt = 0; nt < 8; nt++) {
                rmax0 = fmaxf(rmax0, fmaxf(sacc[nt][0], sacc[nt][1]));
                rmax1 = fmaxf(rmax1, fmaxf(sacc[nt][2], sacc[nt][3]));
            }
            rmax0 = fmaxf(rmax0, __shfl_xor_sync(0xffffffffu, rmax0, 1));
            rmax0 = fmaxf(rmax0, __shfl_xor_sync(0xffffffffu, rmax0, 2));
            rmax1 = fmaxf(rmax1, __shfl_xor_sync(0xffffffffu, rmax1, 1));
            rmax1 = fmaxf(rmax1, __shfl_xor_sync(0xffffffffu, rmax1, 2));

            float mn0 = fmaxf(m_i[0], rmax0);
            float mn1 = fmaxf(m_i[1], rmax1);
            float alpha0 = __expf(m_i[0] - mn0);
            float alpha1 = __expf(m_i[1] - mn1);

            float rs0 = 0.f, rs1 = 0.f;
#pragma unroll
            for (int nt = 0; nt < 8; nt++) {
                sacc[nt][0] = __expf(sacc[nt][0] - mn0);
                sacc[nt][1] = __expf(sacc[nt][1] - mn0);
                sacc[nt][2] = __expf(sacc[nt][2] - mn1);
                sacc[nt][3] = __expf(sacc[nt][3] - mn1);
                rs0 += sacc[nt][0] + sacc[nt][1];
                rs1 += sacc[nt][2] + sacc[nt][3];
            }
            rs0 += __shfl_xor_sync(0xffffffffu, rs0, 1);
            rs0 += __shfl_xor_sync(0xffffffffu, rs0, 2);
            rs1 += __shfl_xor_sync(0xffffffffu, rs1, 1);
            rs1 += __shfl_xor_sync(0xffffffffu, rs1, 2);

            l_i[0] = l_i[0] * alpha0 + rs0;
            l_i[1] = l_i[1] * alpha1 + rs1;
            m_i[0] = mn0;
            m_i[1] = mn1;

#pragma unroll
            for (int nt = 0; nt < 16; nt++) {
                Oacc[nt][0] *= alpha0; Oacc[nt][1] *= alpha0;
                Oacc[nt][2] *= alpha1; Oacc[nt][3] *= alpha1;
            }

            // ---- O += P @ V (P fp16-rounded in regs; single pass) ----
#pragma unroll
            for (int c = 0; c < 4; c++) {
                uint32_t ph[4];
                ph[0] = round_pack_h(sacc[2 * c][0],     sacc[2 * c][1]);
                ph[1] = round_pack_h(sacc[2 * c][2],     sacc[2 * c][3]);
                ph[2] = round_pack_h(sacc[2 * c + 1][0], sacc[2 * c + 1][1]);
                ph[3] = round_pack_h(sacc[2 * c + 1][2], sacc[2 * c + 1][3]);
                const uint32_t srow = (c << 4) + ((lt & 1) << 3) + lr;
#pragma unroll
                for (int i = 0; i < 8; i++) {
                    uint32_t dc = (i << 1) + (lt >> 1);
                    uint32_t vh[4];
                    LDSM4T(vh, VH + ((srow * 68 + dc * 4) << 2));
                    mma16h(Oacc[2 * i],     ph[0], ph[1], ph[2], ph[3], vh[0], vh[1]);
                    mma16h(Oacc[2 * i + 1], ph[0], ph[1], ph[2], ph[3], vh[2], vh[3]);
                }
            }
        }
        __syncthreads();
    }

    // ---- epilogue: normalize, round fp16, write attn ----
    const float inv0 = 1.f / l_i[0];
    const float inv1 = 1.f / l_i[1];
    const int   s0   = qr0 + wr0 + g;
    const size_t base0 = ((size_t)(b * SEQ) + s0) * (HID / 2) + h * 64;
#pragma unroll
    for (int nt = 0; nt < 16; nt++) {
        uint32_t h0 = round_pack_h(Oacc[nt][0] * inv0, Oacc[nt][1] * inv0);
        uint32_t h1 = round_pack_h(Oacc[nt][2] * inv1, Oacc[nt][3] * inv1);
        size_t ci = base0 + nt * 4 + q4;
        ((uint32_t *)g_ath)[ci] = h0;
        ((uint32_t *)g_ath)[ci + 8 * (HID / 2)] = h1;
    }
}

// ---------------------------------------------------------------------------
// kernel_launch
// ---------------------------------------------------------------------------
extern "C" void kernel_launch(void *const *d_in, const int *in_sizes, int n_in,
                              void *d_out, int out_size) {
    (void)in_sizes; (void)n_in; (void)out_size;
    const float *hs     = (const float *)d_in[0];
    const float *w_attn = (const float *)d_in[1];
    const float *b_attn = (const float *)d_in[2];
    const float *w_proj = (const float *)d_in[3];
    const float *b_proj = (const float *)d_in[4];
    float *out = (float *)d_out;

    cudaFuncSetAttribute(gemm_ldsm<1>,
                         cudaFuncAttributeMaxDynamicSharedMemorySize, GEMM_SMEM);
    cudaFuncSetAttribute(gemm_ldsm<0>,
                         cudaFuncAttributeMaxDynamicSharedMemorySize, GEMM_SMEM);
    cudaFuncSetAttribute(flash_causal,
                         cudaFuncAttributeMaxDynamicSharedMemorySize, FLASH_SMEM);

    uint16_t *hidh, *wah, *wph, *ath;
    cudaGetSymbolAddress((void **)&hidh, g_hidh);
    cudaGetSymbolAddress((void **)&wah,  g_wah);
    cudaGetSymbolAddress((void **)&wph,  g_wph);
    cudaGetSymbolAddress((void **)&ath,  g_ath);

    // 0) pre-convert inputs: all fp16 rounded
    round4h<<<(MTOT * HID) / 1024, 256>>>((const float4 *)hs, (uint2 *)hidh);
    round4h<<<(HID * NQKV) / 1024, 256>>>((const float4 *)w_attn, (uint2 *)wah);
    round4h<<<(HID * HID) / 1024, 256>>>((const float4 *)w_proj, (uint2 *)wph);

    // 1) QKV projection -> fp16 Q (pre-scaled), K, V (single-pass)
    gemm_ldsm<1><<<dim3(NQKV / 256, MTOT / 128), 512, GEMM_SMEM>>>(
        hidh, wah, b_attn, nullptr, MTOT, NQKV, HID);

    // 2) causal flash attention -> fp16 attn (g_ath)
    flash_causal<<<dim3(SEQ / 128, NHEAD, BB), 256, FLASH_SMEM>>>();

    // 3) output projection -> d_out (single-pass)
    gemm_ldsm<0><<<dim3(HID / 256, MTOT / 128), 512, GEMM_SMEM>>>(
        ath, wph, b_proj, out, MTOT, HID, HID);
}